// round 1
// baseline (speedup 1.0000x reference)
#include <cuda_runtime.h>
#include <math.h>

#define B 2
#define S 2048
#define E 2048
#define H 8
#define KV 4
#define D 256
#define WIN 1024
#define EPS 1e-6f

// ---------------- scratch (device globals; no allocation) ----------------
__device__ float g_q[(size_t)B * S * H * D];   // 32 MB
__device__ float g_k[(size_t)B * S * KV * D];  // 16 MB
__device__ float g_v[(size_t)B * S * KV * D];  // 16 MB
__device__ float g_o[(size_t)B * S * H * D];   // 32 MB

// ---------------- generic fp32 SGEMM: C[M,N] = A[M,K] @ Bm[K,N] ----------
// 128x128 block tile, BK=16, 256 threads, 8x8 register tile per thread.
// Requires M%128==0, N%128==0, K%16==0 (true for all our shapes).
__global__ __launch_bounds__(256) void sgemm128(
    const float* __restrict__ A, const float* __restrict__ Bm,
    float* __restrict__ C, int M, int N, int K) {
  __shared__ float As[16][128];
  __shared__ float Bs[16][128];
  const int tid = threadIdx.x;
  const int bm = blockIdx.y * 128;
  const int bn = blockIdx.x * 128;
  const int arow = tid >> 2;          // 0..63
  const int acol = (tid & 3) << 2;    // 0,4,8,12
  const int brow = tid >> 5;          // 0..7
  const int bcol = (tid & 31) << 2;   // 0..124
  const int tx = tid & 15, ty = tid >> 4;
  float acc[8][8] = {};
  for (int k0 = 0; k0 < K; k0 += 16) {
#pragma unroll
    for (int i = 0; i < 2; i++) {
      int r = arow + i * 64;
      float4 a4 = *(const float4*)&A[(size_t)(bm + r) * K + k0 + acol];
      As[acol + 0][r] = a4.x;
      As[acol + 1][r] = a4.y;
      As[acol + 2][r] = a4.z;
      As[acol + 3][r] = a4.w;
    }
#pragma unroll
    for (int i = 0; i < 2; i++) {
      int rr = brow + i * 8;
      *(float4*)&Bs[rr][bcol] =
          *(const float4*)&Bm[(size_t)(k0 + rr) * N + bn + bcol];
    }
    __syncthreads();
#pragma unroll
    for (int kk = 0; kk < 16; kk++) {
      float a[8], b[8];
      *(float4*)&a[0] = *(float4*)&As[kk][ty * 8];
      *(float4*)&a[4] = *(float4*)&As[kk][ty * 8 + 4];
      *(float4*)&b[0] = *(float4*)&Bs[kk][tx * 8];
      *(float4*)&b[4] = *(float4*)&Bs[kk][tx * 8 + 4];
#pragma unroll
      for (int i = 0; i < 8; i++)
#pragma unroll
        for (int j = 0; j < 8; j++) acc[i][j] = fmaf(a[i], b[j], acc[i][j]);
    }
    __syncthreads();
  }
#pragma unroll
  for (int i = 0; i < 8; i++) {
    size_t row = (size_t)(bm + ty * 8 + i) * N + bn + tx * 8;
    *(float4*)&C[row] = *(float4*)&acc[i][0];
    *(float4*)&C[row + 4] = *(float4*)&acc[i][4];
  }
}

// ---------------- fused RMSNorm (Gemma style: *(1+w)) + RoPE ------------
// grid: (B*S, H+KV), block: D=256 threads. In-place on g_q / g_k.
__global__ __launch_bounds__(256) void norm_rope(
    const float* __restrict__ cosb, const float* __restrict__ sinb,
    const float* __restrict__ qw, const float* __restrict__ kw) {
  const int row = blockIdx.x;  // b*S + s
  const int hh = blockIdx.y;
  const int d = threadIdx.x;
  float* buf;
  const float* w;
  int nh, h;
  if (hh < H) { buf = g_q; w = qw; nh = H; h = hh; }
  else        { buf = g_k; w = kw; nh = KV; h = hh - H; }
  float* x = &buf[((size_t)row * nh + h) * D];
  float v = x[d];
  float ss = v * v;
#pragma unroll
  for (int o = 16; o > 0; o >>= 1) ss += __shfl_xor_sync(0xffffffffu, ss, o);
  __shared__ float red[8];
  __shared__ float xs[D];
  if ((d & 31) == 0) red[d >> 5] = ss;
  __syncthreads();
  float tot = 0.f;
#pragma unroll
  for (int i = 0; i < 8; i++) tot += red[i];
  float inv = rsqrtf(tot * (1.0f / D) + EPS);
  float xn = v * inv * (1.0f + w[d]);
  xs[d] = xn;
  __syncthreads();
  float rot = (d < D / 2) ? -xs[d + D / 2] : xs[d - D / 2];
  x[d] = xn * cosb[(size_t)row * D + d] + rot * sinb[(size_t)row * D + d];
}

// ---------------- sliding-window flash attention (fp32 SIMT) ------------
// grid: (S/32, H, B), block 256. Each block: 32 queries x full D.
// Key blocks of 64 staged in dynamic SMEM; online softmax.
#define SC_LD 65  // padded row stride for score tile (bank-conflict free)

__global__ __launch_bounds__(256) void attn_kernel(const int* __restrict__ am) {
  extern __shared__ float sm[];
  float* Qs = sm;                  // 32*256
  float* Ks = Qs + 32 * 256;       // 64*256
  float* Vs = Ks + 64 * 256;       // 64*256
  float* Sc = Vs + 64 * 256;       // 32*SC_LD
  float* rs = Sc + 32 * SC_LD;     // 32

  const int tid = threadIdx.x;
  const int q0 = blockIdx.x * 32;
  const int h = blockIdx.y;
  const int b = blockIdx.z;
  const int hk = h / (H / KV);
  const float NEG_INF = __int_as_float(0xff800000u);

  // load scaled Q tile
  for (int i = tid; i < 32 * 64; i += 256) {  // i indexes float4
    int r = i >> 6, c4 = (i & 63) << 2;
    float4 q4 = *(const float4*)&g_q[(((size_t)(b * S + q0 + r) * H + h) * D) + c4];
    q4.x *= 0.0625f; q4.y *= 0.0625f; q4.z *= 0.0625f; q4.w *= 0.0625f;
    *(float4*)&Qs[r * 256 + c4] = q4;
  }

  float m = NEG_INF, l = 0.f;
  float acc[32] = {};
  const int r = tid >> 3;
  const int cg = tid & 7;
  const int dbase = cg * 32;
  const int kb_end = q0 + 31;
  int kb0 = q0 - (WIN - 1);
  if (kb0 < 0) kb0 = 0;
  kb0 &= ~63;

  for (int kb = kb0; kb <= kb_end; kb += 64) {
    __syncthreads();  // protect Ks/Vs/Sc from previous iteration readers
    for (int i = tid; i < 64 * 64; i += 256) {
      int rr = i >> 6, c4 = (i & 63) << 2;
      size_t base = ((size_t)(b * S + kb + rr) * KV + hk) * D + c4;
      *(float4*)&Ks[rr * 256 + c4] = *(const float4*)&g_k[base];
      *(float4*)&Vs[rr * 256 + c4] = *(const float4*)&g_v[base];
    }
    __syncthreads();

    // scores: thread -> row r, 8 cols starting cg*8
    float s8[8] = {};
    const float* qp = &Qs[r * 256];
    for (int d4 = 0; d4 < 256; d4 += 4) {
      float4 q4 = *(const float4*)&qp[d4];
#pragma unroll
      for (int j = 0; j < 8; j++) {
        float4 k4 = *(const float4*)&Ks[(cg * 8 + j) * 256 + d4];
        s8[j] = fmaf(q4.x, k4.x, s8[j]);
        s8[j] = fmaf(q4.y, k4.y, s8[j]);
        s8[j] = fmaf(q4.z, k4.z, s8[j]);
        s8[j] = fmaf(q4.w, k4.w, s8[j]);
      }
    }
#pragma unroll
    for (int j = 0; j < 8; j++) Sc[r * SC_LD + cg * 8 + j] = s8[j];
    __syncthreads();

    // online softmax, one thread per query row
    if (tid < 32) {
      const int qi = q0 + tid;
      float mx = m;
      for (int c = 0; c < 64; c++) {
        int kk = kb + c;
        bool ok = (kk <= qi) && (qi - kk < WIN) && (am[b * S + kk] > 0);
        float sv = ok ? Sc[tid * SC_LD + c] : NEG_INF;
        mx = fmaxf(mx, sv);
      }
      float sc_;
      if (mx == NEG_INF) {
        sc_ = 1.0f;
        for (int c = 0; c < 64; c++) Sc[tid * SC_LD + c] = 0.f;
      } else {
        sc_ = __expf(m - mx);  // m == -inf -> 0
        float sum = 0.f;
        for (int c = 0; c < 64; c++) {
          int kk = kb + c;
          bool ok = (kk <= qi) && (qi - kk < WIN) && (am[b * S + kk] > 0);
          float p = ok ? __expf(Sc[tid * SC_LD + c] - mx) : 0.f;
          Sc[tid * SC_LD + c] = p;
          sum += p;
        }
        l = l * sc_ + sum;
        m = mx;
      }
      rs[tid] = sc_;
    }
    __syncthreads();

    // acc update: thread -> row r, 32 d-cols from dbase
    float sc2 = rs[r];
#pragma unroll
    for (int j = 0; j < 32; j++) acc[j] *= sc2;
    for (int c = 0; c < 64; c++) {
      float p = Sc[r * SC_LD + c];
      const float* vp = &Vs[c * 256 + dbase];
#pragma unroll
      for (int j = 0; j < 32; j += 4) {
        float4 v4 = *(const float4*)&vp[j];
        acc[j + 0] = fmaf(p, v4.x, acc[j + 0]);
        acc[j + 1] = fmaf(p, v4.y, acc[j + 1]);
        acc[j + 2] = fmaf(p, v4.z, acc[j + 2]);
        acc[j + 3] = fmaf(p, v4.w, acc[j + 3]);
      }
    }
  }

  __syncthreads();
  if (tid < 32) rs[tid] = 1.0f / l;
  __syncthreads();
  const float il = rs[r];
  float* op = &g_o[(((size_t)(b * S + q0 + r) * H + h) * D) + dbase];
#pragma unroll
  for (int j = 0; j < 32; j += 4) {
    float4 o4;
    o4.x = acc[j + 0] * il;
    o4.y = acc[j + 1] * il;
    o4.z = acc[j + 2] * il;
    o4.w = acc[j + 3] * il;
    *(float4*)&op[j] = o4;
  }
}

// ---------------- launch ----------------
extern "C" void kernel_launch(void* const* d_in, const int* in_sizes, int n_in,
                              void* d_out, int out_size) {
  const float* hs   = (const float*)d_in[0];
  const float* cosb = (const float*)d_in[1];
  const float* sinb = (const float*)d_in[2];
  const int*   am   = (const int*)d_in[3];
  const float* Wq   = (const float*)d_in[4];
  const float* Wk   = (const float*)d_in[5];
  const float* Wv   = (const float*)d_in[6];
  const float* Wo   = (const float*)d_in[7];
  const float* qw   = (const float*)d_in[8];
  const float* kw   = (const float*)d_in[9];
  float* out = (float*)d_out;

  float *qp, *kp, *vp, *op;
  cudaGetSymbolAddress((void**)&qp, g_q);
  cudaGetSymbolAddress((void**)&kp, g_k);
  cudaGetSymbolAddress((void**)&vp, g_v);
  cudaGetSymbolAddress((void**)&op, g_o);

  const int M = B * S;  // 4096

  sgemm128<<<dim3((H * D) / 128, M / 128), 256>>>(hs, Wq, qp, M, H * D, E);
  sgemm128<<<dim3((KV * D) / 128, M / 128), 256>>>(hs, Wk, kp, M, KV * D, E);
  sgemm128<<<dim3((KV * D) / 128, M / 128), 256>>>(hs, Wv, vp, M, KV * D, E);

  norm_rope<<<dim3(M, H + KV), 256>>>(cosb, sinb, qw, kw);

  size_t smem = (size_t)(32 * 256 + 64 * 256 + 64 * 256 + 32 * SC_LD + 32) *
                sizeof(float);
  cudaFuncSetAttribute(attn_kernel, cudaFuncAttributeMaxDynamicSharedMemorySize,
                       (int)smem);
  attn_kernel<<<dim3(S / 32, H, B), 256, smem>>>(am);

  sgemm128<<<dim3(E / 128, M / 128), 256>>>(op, Wo, out, M, E, E);
}

// round 4
// speedup vs baseline: 1.1107x; 1.1107x over previous
#include <cuda_runtime.h>
#include <math.h>
#include <stdint.h>

#define B 2
#define S 2048
#define E 2048
#define H 8
#define KV 4
#define D 256
#define WIN 1024
#define EPS 1e-6f

// ---------------- scratch (device globals; no allocation) ----------------
__device__ float g_q[(size_t)B * S * H * D];   // 32 MB
__device__ float g_k[(size_t)B * S * KV * D];  // 16 MB
__device__ float g_v[(size_t)B * S * KV * D];  // 16 MB
__device__ float g_o[(size_t)B * S * H * D];   // 32 MB

// ======================= helpers =========================================
__device__ __forceinline__ uint32_t f2tf32(float x) {
  uint32_t r;
  asm("cvt.rna.tf32.f32 %0, %1;" : "=r"(r) : "f"(x));
  return r;
}

__device__ __forceinline__ void mma_tf32(float* d, const uint32_t* a,
                                         const uint32_t* b) {
  asm volatile(
      "mma.sync.aligned.m16n8k8.row.col.f32.tf32.tf32.f32 "
      "{%0,%1,%2,%3},{%4,%5,%6,%7},{%8,%9},{%0,%1,%2,%3};"
      : "+f"(d[0]), "+f"(d[1]), "+f"(d[2]), "+f"(d[3])
      : "r"(a[0]), "r"(a[1]), "r"(a[2]), "r"(a[3]), "r"(b[0]), "r"(b[1]));
}

// ================== tf32 mma.sync GEMM: C[M,N] = A[M,K] @ Bw[K,N] ========
// CTA tile 128x128, BK=32. 256 threads = 8 warps (4x2), warp tile 32x64.
// A smem: [128][36] row-major (pad 4). B smem: [32][136] (pad 8).
// Double buffered, register-prefetch pipeline.
#define ALD 36
#define BLD 136
#define ASTG (128 * ALD)
#define BSTG (32 * BLD)
#define GEMM_SMEM ((2 * ASTG + 2 * BSTG) * 4)

__global__ __launch_bounds__(256) void gemm_mma(
    const float* __restrict__ A, const float* __restrict__ Bw,
    float* __restrict__ C, int M, int N, int K) {
  extern __shared__ float sm[];
  float* As = sm;                 // [2][128][ALD]
  float* Bs = sm + 2 * ASTG;      // [2][32][BLD]

  const int tid = threadIdx.x;
  const int lane = tid & 31;
  const int wid = tid >> 5;
  const int bm = blockIdx.y * 128;
  const int bn = blockIdx.x * 128;
  const int wm = (wid & 3) * 32;
  const int wn = (wid >> 2) * 64;

  // global load indices
  // A: idx = tid + 256*i (i<4): row = idx>>3 (0..127), c4 = idx&7 (k group)
  // B: idx = tid + 256*i (i<4): krow = idx>>5 (0..31), c4 = idx&31 (n group)
  int a_row[4], a_c4[4];
  int b_k[4], b_c4[4];
#pragma unroll
  for (int i = 0; i < 4; i++) {
    int idx = tid + 256 * i;
    a_row[i] = idx >> 3;
    a_c4[i] = idx & 7;
    b_k[i] = idx >> 5;
    b_c4[i] = idx & 31;
  }

  const float* Ag = A + (size_t)bm * K;
  const float* Bg = Bw + bn;
  const int NC = K >> 5;

  float4 aR[4], bR[4];
  // prologue: load chunk 0
#pragma unroll
  for (int i = 0; i < 4; i++) {
    aR[i] = *(const float4*)&Ag[(size_t)a_row[i] * K + a_c4[i] * 4];
    bR[i] = *(const float4*)&Bg[(size_t)b_k[i] * N + b_c4[i] * 4];
  }

  // sts chunk 0 -> stage 0
#pragma unroll
  for (int i = 0; i < 4; i++) {
    uint4 ua;
    ua.x = f2tf32(aR[i].x); ua.y = f2tf32(aR[i].y);
    ua.z = f2tf32(aR[i].z); ua.w = f2tf32(aR[i].w);
    *(uint4*)&As[a_row[i] * ALD + a_c4[i] * 4] = ua;
    uint4 ub;
    ub.x = f2tf32(bR[i].x); ub.y = f2tf32(bR[i].y);
    ub.z = f2tf32(bR[i].z); ub.w = f2tf32(bR[i].w);
    *(uint4*)&Bs[b_k[i] * BLD + b_c4[i] * 4] = ub;
  }
  __syncthreads();

  float acc[2][8][4] = {};

  for (int c = 0; c < NC; c++) {
    const int st = c & 1;
    // prefetch next chunk from global
    if (c + 1 < NC) {
      const int kof = (c + 1) * 32;
#pragma unroll
      for (int i = 0; i < 4; i++) {
        aR[i] = *(const float4*)&Ag[(size_t)a_row[i] * K + kof + a_c4[i] * 4];
        bR[i] = *(const float4*)&Bg[(size_t)(kof + b_k[i]) * N + b_c4[i] * 4];
      }
    }

    // compute on stage st
    const float* Ab = As + st * ASTG;
    const float* Bb = Bs + st * BSTG;
#pragma unroll
    for (int ks = 0; ks < 4; ks++) {
      const int k0 = ks * 8 + (lane & 3);
      uint32_t af[2][4], bf[8][2];
#pragma unroll
      for (int mf = 0; mf < 2; mf++) {
        const int m0 = wm + mf * 16 + (lane >> 2);
        af[mf][0] = *(const uint32_t*)&Ab[m0 * ALD + k0];
        af[mf][1] = *(const uint32_t*)&Ab[(m0 + 8) * ALD + k0];
        af[mf][2] = *(const uint32_t*)&Ab[m0 * ALD + k0 + 4];
        af[mf][3] = *(const uint32_t*)&Ab[(m0 + 8) * ALD + k0 + 4];
      }
#pragma unroll
      for (int nf = 0; nf < 8; nf++) {
        const int n0 = wn + nf * 8 + (lane >> 2);
        bf[nf][0] = *(const uint32_t*)&Bb[k0 * BLD + n0];
        bf[nf][1] = *(const uint32_t*)&Bb[(k0 + 4) * BLD + n0];
      }
#pragma unroll
      for (int mf = 0; mf < 2; mf++)
#pragma unroll
        for (int nf = 0; nf < 8; nf++)
          mma_tf32(acc[mf][nf], af[mf], bf[nf]);
    }

    // sts next chunk -> stage st^1
    if (c + 1 < NC) {
      float* An = As + (st ^ 1) * ASTG;
      float* Bn = Bs + (st ^ 1) * BSTG;
#pragma unroll
      for (int i = 0; i < 4; i++) {
        uint4 ua;
        ua.x = f2tf32(aR[i].x); ua.y = f2tf32(aR[i].y);
        ua.z = f2tf32(aR[i].z); ua.w = f2tf32(aR[i].w);
        *(uint4*)&An[a_row[i] * ALD + a_c4[i] * 4] = ua;
        uint4 ub;
        ub.x = f2tf32(bR[i].x); ub.y = f2tf32(bR[i].y);
        ub.z = f2tf32(bR[i].z); ub.w = f2tf32(bR[i].w);
        *(uint4*)&Bn[b_k[i] * BLD + b_c4[i] * 4] = ub;
      }
    }
    __syncthreads();
  }

  // epilogue: write accumulators
#pragma unroll
  for (int mf = 0; mf < 2; mf++) {
    const int r0 = bm + wm + mf * 16 + (lane >> 2);
#pragma unroll
    for (int nf = 0; nf < 8; nf++) {
      const int col = bn + wn + nf * 8 + 2 * (lane & 3);
      float2 v0, v1;
      v0.x = acc[mf][nf][0]; v0.y = acc[mf][nf][1];
      v1.x = acc[mf][nf][2]; v1.y = acc[mf][nf][3];
      *(float2*)&C[(size_t)r0 * N + col] = v0;
      *(float2*)&C[(size_t)(r0 + 8) * N + col] = v1;
    }
  }
}

// ---------------- fused RMSNorm (Gemma style: *(1+w)) + RoPE ------------
__global__ __launch_bounds__(256) void norm_rope(
    const float* __restrict__ cosb, const float* __restrict__ sinb,
    const float* __restrict__ qw, const float* __restrict__ kw) {
  const int row = blockIdx.x;  // b*S + s
  const int hh = blockIdx.y;
  const int d = threadIdx.x;
  float* buf;
  const float* w;
  int nh, h;
  if (hh < H) { buf = g_q; w = qw; nh = H; h = hh; }
  else        { buf = g_k; w = kw; nh = KV; h = hh - H; }
  float* x = &buf[((size_t)row * nh + h) * D];
  float v = x[d];
  float ss = v * v;
#pragma unroll
  for (int o = 16; o > 0; o >>= 1) ss += __shfl_xor_sync(0xffffffffu, ss, o);
  __shared__ float red[8];
  __shared__ float xs[D];
  if ((d & 31) == 0) red[d >> 5] = ss;
  __syncthreads();
  float tot = 0.f;
#pragma unroll
  for (int i = 0; i < 8; i++) tot += red[i];
  float inv = rsqrtf(tot * (1.0f / D) + EPS);
  float xn = v * inv * (1.0f + w[d]);
  xs[d] = xn;
  __syncthreads();
  float rot = (d < D / 2) ? -xs[d + D / 2] : xs[d - D / 2];
  x[d] = xn * cosb[(size_t)row * D + d] + rot * sinb[(size_t)row * D + d];
}

// ---------------- sliding-window flash attention (fp32 SIMT) ------------
#define SC_LD 65

__global__ __launch_bounds__(256) void attn_kernel(const int* __restrict__ am) {
  extern __shared__ float smf[];
  float* Qs = smf;
  float* Ks = Qs + 32 * 256;
  float* Vs = Ks + 64 * 256;
  float* Sc = Vs + 64 * 256;
  float* rs = Sc + 32 * SC_LD;

  const int tid = threadIdx.x;
  const int q0 = blockIdx.x * 32;
  const int h = blockIdx.y;
  const int b = blockIdx.z;
  const int hk = h / (H / KV);
  const float NEG_INF = __int_as_float(0xff800000u);

  for (int i = tid; i < 32 * 64; i += 256) {
    int r = i >> 6, c4 = (i & 63) << 2;
    float4 q4 = *(const float4*)&g_q[(((size_t)(b * S + q0 + r) * H + h) * D) + c4];
    q4.x *= 0.0625f; q4.y *= 0.0625f; q4.z *= 0.0625f; q4.w *= 0.0625f;
    *(float4*)&Qs[r * 256 + c4] = q4;
  }

  float m = NEG_INF, l = 0.f;
  float acc[32] = {};
  const int r = tid >> 3;
  const int cg = tid & 7;
  const int dbase = cg * 32;
  const int kb_end = q0 + 31;
  int kb0 = q0 - (WIN - 1);
  if (kb0 < 0) kb0 = 0;
  kb0 &= ~63;

  for (int kb = kb0; kb <= kb_end; kb += 64) {
    __syncthreads();
    for (int i = tid; i < 64 * 64; i += 256) {
      int rr = i >> 6, c4 = (i & 63) << 2;
      size_t base = ((size_t)(b * S + kb + rr) * KV + hk) * D + c4;
      *(float4*)&Ks[rr * 256 + c4] = *(const float4*)&g_k[base];
      *(float4*)&Vs[rr * 256 + c4] = *(const float4*)&g_v[base];
    }
    __syncthreads();

    float s8[8] = {};
    const float* qp = &Qs[r * 256];
    for (int d4 = 0; d4 < 256; d4 += 4) {
      float4 q4 = *(const float4*)&qp[d4];
#pragma unroll
      for (int j = 0; j < 8; j++) {
        float4 k4 = *(const float4*)&Ks[(cg * 8 + j) * 256 + d4];
        s8[j] = fmaf(q4.x, k4.x, s8[j]);
        s8[j] = fmaf(q4.y, k4.y, s8[j]);
        s8[j] = fmaf(q4.z, k4.z, s8[j]);
        s8[j] = fmaf(q4.w, k4.w, s8[j]);
      }
    }
#pragma unroll
    for (int j = 0; j < 8; j++) Sc[r * SC_LD + cg * 8 + j] = s8[j];
    __syncthreads();

    if (tid < 32) {
      const int qi = q0 + tid;
      float mx = m;
      for (int c = 0; c < 64; c++) {
        int kk = kb + c;
        bool ok = (kk <= qi) && (qi - kk < WIN) && (am[b * S + kk] > 0);
        float sv = ok ? Sc[tid * SC_LD + c] : NEG_INF;
        mx = fmaxf(mx, sv);
      }
      float sc_;
      if (mx == NEG_INF) {
        sc_ = 1.0f;
        for (int c = 0; c < 64; c++) Sc[tid * SC_LD + c] = 0.f;
      } else {
        sc_ = __expf(m - mx);
        float sum = 0.f;
        for (int c = 0; c < 64; c++) {
          int kk = kb + c;
          bool ok = (kk <= qi) && (qi - kk < WIN) && (am[b * S + kk] > 0);
          float p = ok ? __expf(Sc[tid * SC_LD + c] - mx) : 0.f;
          Sc[tid * SC_LD + c] = p;
          sum += p;
        }
        l = l * sc_ + sum;
        m = mx;
      }
      rs[tid] = sc_;
    }
    __syncthreads();

    float sc2 = rs[r];
#pragma unroll
    for (int j = 0; j < 32; j++) acc[j] *= sc2;
    for (int c = 0; c < 64; c++) {
      float p = Sc[r * SC_LD + c];
      const float* vp = &Vs[c * 256 + dbase];
#pragma unroll
      for (int j = 0; j < 32; j += 4) {
        float4 v4 = *(const float4*)&vp[j];
        acc[j + 0] = fmaf(p, v4.x, acc[j + 0]);
        acc[j + 1] = fmaf(p, v4.y, acc[j + 1]);
        acc[j + 2] = fmaf(p, v4.z, acc[j + 2]);
        acc[j + 3] = fmaf(p, v4.w, acc[j + 3]);
      }
    }
  }

  __syncthreads();
  if (tid < 32) rs[tid] = 1.0f / l;
  __syncthreads();
  const float il = rs[r];
  float* op = &g_o[(((size_t)(b * S + q0 + r) * H + h) * D) + dbase];
#pragma unroll
  for (int j = 0; j < 32; j += 4) {
    float4 o4;
    o4.x = acc[j + 0] * il;
    o4.y = acc[j + 1] * il;
    o4.z = acc[j + 2] * il;
    o4.w = acc[j + 3] * il;
    *(float4*)&op[j] = o4;
  }
}

// ---------------- launch ----------------
extern "C" void kernel_launch(void* const* d_in, const int* in_sizes, int n_in,
                              void* d_out, int out_size) {
  const float* hs   = (const float*)d_in[0];
  const float* cosb = (const float*)d_in[1];
  const float* sinb = (const float*)d_in[2];
  const int*   am   = (const int*)d_in[3];
  const float* Wq   = (const float*)d_in[4];
  const float* Wk   = (const float*)d_in[5];
  const float* Wv   = (const float*)d_in[6];
  const float* Wo   = (const float*)d_in[7];
  const float* qw   = (const float*)d_in[8];
  const float* kw   = (const float*)d_in[9];
  float* out = (float*)d_out;

  float *qp, *kp, *vp, *op;
  cudaGetSymbolAddress((void**)&qp, g_q);
  cudaGetSymbolAddress((void**)&kp, g_k);
  cudaGetSymbolAddress((void**)&vp, g_v);
  cudaGetSymbolAddress((void**)&op, g_o);

  const int M = B * S;  // 4096

  cudaFuncSetAttribute(gemm_mma, cudaFuncAttributeMaxDynamicSharedMemorySize,
                       GEMM_SMEM);

  gemm_mma<<<dim3((H * D) / 128, M / 128), 256, GEMM_SMEM>>>(hs, Wq, qp, M, H * D, E);
  gemm_mma<<<dim3((KV * D) / 128, M / 128), 256, GEMM_SMEM>>>(hs, Wk, kp, M, KV * D, E);
  gemm_mma<<<dim3((KV * D) / 128, M / 128), 256, GEMM_SMEM>>>(hs, Wv, vp, M, KV * D, E);

  norm_rope<<<dim3(M, H + KV), 256>>>(cosb, sinb, qw, kw);

  size_t smem = (size_t)(32 * 256 + 64 * 256 + 64 * 256 + 32 * SC_LD + 32) *
                sizeof(float);
  cudaFuncSetAttribute(attn_kernel, cudaFuncAttributeMaxDynamicSharedMemorySize,
                       (int)smem);
  attn_kernel<<<dim3(S / 32, H, B), 256, smem>>>(am);

  gemm_mma<<<dim3(E / 128, M / 128), 256, GEMM_SMEM>>>(op, Wo, out, M, E, E);
}

// round 5
// speedup vs baseline: 11.9740x; 10.7803x over previous
#include <cuda_runtime.h>
#include <math.h>
#include <stdint.h>

#define B 2
#define S 2048
#define E 2048
#define H 8
#define KV 4
#define D 256
#define WIN 1024
#define EPS 1e-6f

// ---------------- scratch (device globals; no allocation) ----------------
__device__ float g_q[(size_t)B * S * H * D];   // 32 MB
__device__ float g_k[(size_t)B * S * KV * D];  // 16 MB
__device__ float g_v[(size_t)B * S * KV * D];  // 16 MB
__device__ float g_o[(size_t)B * S * H * D];   // 32 MB

// ======================= helpers =========================================
__device__ __forceinline__ uint32_t f2tf32(float x) {
  uint32_t r;
  asm("cvt.rna.tf32.f32 %0, %1;" : "=r"(r) : "f"(x));
  return r;
}

__device__ __forceinline__ void mma_tf32(float* d, const uint32_t* a,
                                         const uint32_t* b) {
  asm volatile(
      "mma.sync.aligned.m16n8k8.row.col.f32.tf32.tf32.f32 "
      "{%0,%1,%2,%3},{%4,%5,%6,%7},{%8,%9},{%0,%1,%2,%3};"
      : "+f"(d[0]), "+f"(d[1]), "+f"(d[2]), "+f"(d[3])
      : "r"(a[0]), "r"(a[1]), "r"(a[2]), "r"(a[3]), "r"(b[0]), "r"(b[1]));
}

// ================== tf32 mma.sync GEMM: C[M,N] = A[M,K] @ Bw[K,N] ========
#define ALD 36
#define BLD 136
#define ASTG (128 * ALD)
#define BSTG (32 * BLD)
#define GEMM_SMEM ((2 * ASTG + 2 * BSTG) * 4)

__global__ __launch_bounds__(256) void gemm_mma(
    const float* __restrict__ A, const float* __restrict__ Bw,
    float* __restrict__ C, int M, int N, int K) {
  extern __shared__ float sm[];
  float* As = sm;                 // [2][128][ALD]
  float* Bs = sm + 2 * ASTG;      // [2][32][BLD]

  const int tid = threadIdx.x;
  const int lane = tid & 31;
  const int wid = tid >> 5;
  const int bm = blockIdx.y * 128;
  const int bn = blockIdx.x * 128;
  const int wm = (wid & 3) * 32;
  const int wn = (wid >> 2) * 64;

  int a_row[4], a_c4[4];
  int b_k[4], b_c4[4];
#pragma unroll
  for (int i = 0; i < 4; i++) {
    int idx = tid + 256 * i;
    a_row[i] = idx >> 3;
    a_c4[i] = idx & 7;
    b_k[i] = idx >> 5;
    b_c4[i] = idx & 31;
  }

  const float* Ag = A + (size_t)bm * K;
  const float* Bg = Bw + bn;
  const int NC = K >> 5;

  float4 aR[4], bR[4];
#pragma unroll
  for (int i = 0; i < 4; i++) {
    aR[i] = *(const float4*)&Ag[(size_t)a_row[i] * K + a_c4[i] * 4];
    bR[i] = *(const float4*)&Bg[(size_t)b_k[i] * N + b_c4[i] * 4];
  }

#pragma unroll
  for (int i = 0; i < 4; i++) {
    uint4 ua;
    ua.x = f2tf32(aR[i].x); ua.y = f2tf32(aR[i].y);
    ua.z = f2tf32(aR[i].z); ua.w = f2tf32(aR[i].w);
    *(uint4*)&As[a_row[i] * ALD + a_c4[i] * 4] = ua;
    uint4 ub;
    ub.x = f2tf32(bR[i].x); ub.y = f2tf32(bR[i].y);
    ub.z = f2tf32(bR[i].z); ub.w = f2tf32(bR[i].w);
    *(uint4*)&Bs[b_k[i] * BLD + b_c4[i] * 4] = ub;
  }
  __syncthreads();

  float acc[2][8][4] = {};

  for (int c = 0; c < NC; c++) {
    const int st = c & 1;
    if (c + 1 < NC) {
      const int kof = (c + 1) * 32;
#pragma unroll
      for (int i = 0; i < 4; i++) {
        aR[i] = *(const float4*)&Ag[(size_t)a_row[i] * K + kof + a_c4[i] * 4];
        bR[i] = *(const float4*)&Bg[(size_t)(kof + b_k[i]) * N + b_c4[i] * 4];
      }
    }

    const float* Ab = As + st * ASTG;
    const float* Bb = Bs + st * BSTG;
#pragma unroll
    for (int ks = 0; ks < 4; ks++) {
      const int k0 = ks * 8 + (lane & 3);
      uint32_t af[2][4], bf[8][2];
#pragma unroll
      for (int mf = 0; mf < 2; mf++) {
        const int m0 = wm + mf * 16 + (lane >> 2);
        af[mf][0] = *(const uint32_t*)&Ab[m0 * ALD + k0];
        af[mf][1] = *(const uint32_t*)&Ab[(m0 + 8) * ALD + k0];
        af[mf][2] = *(const uint32_t*)&Ab[m0 * ALD + k0 + 4];
        af[mf][3] = *(const uint32_t*)&Ab[(m0 + 8) * ALD + k0 + 4];
      }
#pragma unroll
      for (int nf = 0; nf < 8; nf++) {
        const int n0 = wn + nf * 8 + (lane >> 2);
        bf[nf][0] = *(const uint32_t*)&Bb[k0 * BLD + n0];
        bf[nf][1] = *(const uint32_t*)&Bb[(k0 + 4) * BLD + n0];
      }
#pragma unroll
      for (int mf = 0; mf < 2; mf++)
#pragma unroll
        for (int nf = 0; nf < 8; nf++)
          mma_tf32(acc[mf][nf], af[mf], bf[nf]);
    }

    if (c + 1 < NC) {
      float* An = As + (st ^ 1) * ASTG;
      float* Bn = Bs + (st ^ 1) * BSTG;
#pragma unroll
      for (int i = 0; i < 4; i++) {
        uint4 ua;
        ua.x = f2tf32(aR[i].x); ua.y = f2tf32(aR[i].y);
        ua.z = f2tf32(aR[i].z); ua.w = f2tf32(aR[i].w);
        *(uint4*)&An[a_row[i] * ALD + a_c4[i] * 4] = ua;
        uint4 ub;
        ub.x = f2tf32(bR[i].x); ub.y = f2tf32(bR[i].y);
        ub.z = f2tf32(bR[i].z); ub.w = f2tf32(bR[i].w);
        *(uint4*)&Bn[b_k[i] * BLD + b_c4[i] * 4] = ub;
      }
    }
    __syncthreads();
  }

#pragma unroll
  for (int mf = 0; mf < 2; mf++) {
    const int r0 = bm + wm + mf * 16 + (lane >> 2);
#pragma unroll
    for (int nf = 0; nf < 8; nf++) {
      const int col = bn + wn + nf * 8 + 2 * (lane & 3);
      float2 v0, v1;
      v0.x = acc[mf][nf][0]; v0.y = acc[mf][nf][1];
      v1.x = acc[mf][nf][2]; v1.y = acc[mf][nf][3];
      *(float2*)&C[(size_t)r0 * N + col] = v0;
      *(float2*)&C[(size_t)(r0 + 8) * N + col] = v1;
    }
  }
}

// ---------------- fused RMSNorm (Gemma style: *(1+w)) + RoPE ------------
__global__ __launch_bounds__(256) void norm_rope(
    const float* __restrict__ cosb, const float* __restrict__ sinb,
    const float* __restrict__ qw, const float* __restrict__ kw) {
  const int row = blockIdx.x;  // b*S + s
  const int hh = blockIdx.y;
  const int d = threadIdx.x;
  float* buf;
  const float* w;
  int nh, h;
  if (hh < H) { buf = g_q; w = qw; nh = H; h = hh; }
  else        { buf = g_k; w = kw; nh = KV; h = hh - H; }
  float* x = &buf[((size_t)row * nh + h) * D];
  float v = x[d];
  float ss = v * v;
#pragma unroll
  for (int o = 16; o > 0; o >>= 1) ss += __shfl_xor_sync(0xffffffffu, ss, o);
  __shared__ float red[8];
  __shared__ float xs[D];
  if ((d & 31) == 0) red[d >> 5] = ss;
  __syncthreads();
  float tot = 0.f;
#pragma unroll
  for (int i = 0; i < 8; i++) tot += red[i];
  float inv = rsqrtf(tot * (1.0f / D) + EPS);
  float xn = v * inv * (1.0f + w[d]);
  xs[d] = xn;
  __syncthreads();
  float rot = (d < D / 2) ? -xs[d + D / 2] : xs[d - D / 2];
  x[d] = xn * cosb[(size_t)row * D + d] + rot * sinb[(size_t)row * D + d];
}

// ============= mma.sync tf32 flash attention (sliding window) ============
// CTA: 64 queries, 256 threads = 8 warps.
// QK: warp w -> m-tile (w&3) [16 q rows], key-half (w>>2) [32 keys].
// PV computed transposed: out^T[d][q] = V^T[d][k] @ P^T[k][q]
//   A-frag from Vs[key][d] (natural layout), B-frag from Ps[q][key].
//   warp w -> d-tiles {2w, 2w+1} (32 d), all 64 q cols.
#define QLD 260  // 260 mod 32 = 4 -> conflict-free frag loads
#define PLD 68
#define ATT_SMEM ((3 * 64 * QLD + 64 * PLD + 3 * 64 + 2 * 128 + 64) * 4)
#define NEGF (-1e30f)

__global__ __launch_bounds__(256) void attn_mma(const int* __restrict__ am) {
  extern __shared__ float smf[];
  float* Qs = smf;                    // [64][QLD]
  float* Ks = Qs + 64 * QLD;          // [64][QLD]
  float* Vs = Ks + 64 * QLD;          // [64][QLD]
  float* Ps = Vs + 64 * QLD;          // [64][PLD]
  float* row_m = Ps + 64 * PLD;       // [64]
  float* row_l = row_m + 64;          // [64]
  float* row_a = row_l + 64;          // [64]
  float* pm = row_a + 64;             // [2][64]
  float* pl = pm + 128;               // [2][64]
  int* ams = (int*)(pl + 128);        // [64]

  const int tid = threadIdx.x;
  const int lane = tid & 31;
  const int w = tid >> 5;
  const int mt = w & 3;      // QK m-tile
  const int half = w >> 2;   // QK key-half
  const int lr = lane >> 2;  // 0..7
  const int lc = lane & 3;   // 0..3

  const int q0 = blockIdx.x * 64;
  const int h = blockIdx.y;
  const int b = blockIdx.z;
  const int hk = h / (H / KV);

  // ---- load Q tile (scaled by D^-1/2, tf32-rounded) ----
  for (int i = tid; i < 64 * 64; i += 256) {
    int r = i >> 6, c4 = (i & 63) << 2;
    float4 q4 = *(const float4*)&g_q[(((size_t)(b * S + q0 + r) * H + h) * D) + c4];
    uint4 u;
    u.x = f2tf32(q4.x * 0.0625f);
    u.y = f2tf32(q4.y * 0.0625f);
    u.z = f2tf32(q4.z * 0.0625f);
    u.w = f2tf32(q4.w * 0.0625f);
    *(uint4*)&Qs[r * QLD + c4] = u;
  }
  if (tid < 64) {
    row_m[tid] = NEGF;
    row_l[tid] = 0.f;
  }

  float oacc[2][8][4] = {};

  int kb0 = q0 - (WIN - 1);
  if (kb0 < 0) kb0 = 0;
  kb0 &= ~63;
  const int kb_end = q0 + 63;

  for (int kb = kb0; kb <= kb_end; kb += 64) {
    __syncthreads();  // (a) previous iter's PV reads done; Q ready (1st iter)
    // ---- load K, V (tf32) ----
    for (int i = tid; i < 64 * 64; i += 256) {
      int r = i >> 6, c4 = (i & 63) << 2;
      size_t base = ((size_t)(b * S + kb + r) * KV + hk) * D + c4;
      float4 k4 = *(const float4*)&g_k[base];
      float4 v4 = *(const float4*)&g_v[base];
      uint4 uk, uv;
      uk.x = f2tf32(k4.x); uk.y = f2tf32(k4.y);
      uk.z = f2tf32(k4.z); uk.w = f2tf32(k4.w);
      uv.x = f2tf32(v4.x); uv.y = f2tf32(v4.y);
      uv.z = f2tf32(v4.z); uv.w = f2tf32(v4.w);
      *(uint4*)&Ks[r * QLD + c4] = uk;
      *(uint4*)&Vs[r * QLD + c4] = uv;
    }
    if (tid < 64) ams[tid] = am[b * S + kb + tid];
    __syncthreads();  // (b)

    // ---- QK^T: 16x32 scores per warp ----
    float sacc[4][4] = {};
    const int arow = mt * 16 + lr;
#pragma unroll
    for (int ks = 0; ks < 32; ks++) {
      const int k0 = ks * 8 + lc;
      uint32_t a[4];
      a[0] = *(const uint32_t*)&Qs[arow * QLD + k0];
      a[1] = *(const uint32_t*)&Qs[(arow + 8) * QLD + k0];
      a[2] = *(const uint32_t*)&Qs[arow * QLD + k0 + 4];
      a[3] = *(const uint32_t*)&Qs[(arow + 8) * QLD + k0 + 4];
#pragma unroll
      for (int nt = 0; nt < 4; nt++) {
        const int n0 = half * 32 + nt * 8 + lr;
        uint32_t bfr[2];
        bfr[0] = *(const uint32_t*)&Ks[n0 * QLD + k0];
        bfr[1] = *(const uint32_t*)&Ks[n0 * QLD + k0 + 4];
        mma_tf32(sacc[nt], a, bfr);
      }
    }

    // ---- mask + partial row max ----
    const int r0 = mt * 16 + lr;
    const int r1 = r0 + 8;
    const int qg0 = q0 + r0;
    const int qg1 = q0 + r1;
    float mx0 = NEGF, mx1 = NEGF;
#pragma unroll
    for (int nt = 0; nt < 4; nt++) {
      const int colb = half * 32 + nt * 8 + 2 * lc;
#pragma unroll
      for (int j = 0; j < 4; j++) {
        const int col = colb + (j & 1);
        const int kg = kb + col;
        const int qg = (j < 2) ? qg0 : qg1;
        bool ok = (kg <= qg) && (qg - kg < WIN) && (ams[col] != 0);
        float v = ok ? sacc[nt][j] : NEGF;
        sacc[nt][j] = v;
        if (j < 2) mx0 = fmaxf(mx0, v);
        else       mx1 = fmaxf(mx1, v);
      }
    }
    mx0 = fmaxf(mx0, __shfl_xor_sync(0xffffffffu, mx0, 1));
    mx0 = fmaxf(mx0, __shfl_xor_sync(0xffffffffu, mx0, 2));
    mx1 = fmaxf(mx1, __shfl_xor_sync(0xffffffffu, mx1, 1));
    mx1 = fmaxf(mx1, __shfl_xor_sync(0xffffffffu, mx1, 2));
    if (lc == 0) {
      pm[half * 64 + r0] = mx0;
      pm[half * 64 + r1] = mx1;
    }
    __syncthreads();  // (c)
    if (tid < 64) {
      float mn = fmaxf(row_m[tid], fmaxf(pm[tid], pm[64 + tid]));
      row_a[tid] = __expf(row_m[tid] - mn);  // NEGF-NEGF -> exp(0)=1 ok
      row_m[tid] = mn;
    }
    __syncthreads();  // (d)

    // ---- P = exp(s - m), partial sums, store Ps (tf32), rescale oacc ----
    const float mn0 = row_m[r0];
    const float mn1 = row_m[r1];
    float s0 = 0.f, s1 = 0.f;
#pragma unroll
    for (int nt = 0; nt < 4; nt++) {
      const int colb = half * 32 + nt * 8 + 2 * lc;
#pragma unroll
      for (int j = 0; j < 4; j++) {
        const float v = sacc[nt][j];
        const float mnj = (j < 2) ? mn0 : mn1;
        float p = (v < -5e29f) ? 0.f : __expf(v - mnj);
        if (j < 2) s0 += p; else s1 += p;
        const int row = (j < 2) ? r0 : r1;
        *(uint32_t*)&Ps[row * PLD + colb + (j & 1)] = f2tf32(p);
      }
    }
    s0 += __shfl_xor_sync(0xffffffffu, s0, 1);
    s0 += __shfl_xor_sync(0xffffffffu, s0, 2);
    s1 += __shfl_xor_sync(0xffffffffu, s1, 1);
    s1 += __shfl_xor_sync(0xffffffffu, s1, 2);
    if (lc == 0) {
      pl[half * 64 + r0] = s0;
      pl[half * 64 + r1] = s1;
    }
    // rescale output accumulators (cols = q)
#pragma unroll
    for (int nt2 = 0; nt2 < 8; nt2++) {
      const int qc = nt2 * 8 + 2 * lc;
      const float a0 = row_a[qc];
      const float a1 = row_a[qc + 1];
#pragma unroll
      for (int mt2 = 0; mt2 < 2; mt2++) {
        oacc[mt2][nt2][0] *= a0;
        oacc[mt2][nt2][1] *= a1;
        oacc[mt2][nt2][2] *= a0;
        oacc[mt2][nt2][3] *= a1;
      }
    }
    __syncthreads();  // (e) Ps complete; pl complete
    if (tid < 64) row_l[tid] = row_l[tid] * row_a[tid] + pl[tid] + pl[64 + tid];

    // ---- PV (transposed): out^T[d][q] += V^T[d][k] P^T[k][q] ----
#pragma unroll
    for (int ks2 = 0; ks2 < 8; ks2++) {
      const int kk = ks2 * 8 + lc;
      uint32_t a2[2][4];
#pragma unroll
      for (int mt2 = 0; mt2 < 2; mt2++) {
        const int d0 = w * 32 + mt2 * 16 + lr;
        a2[mt2][0] = *(const uint32_t*)&Vs[kk * QLD + d0];
        a2[mt2][1] = *(const uint32_t*)&Vs[kk * QLD + d0 + 8];
        a2[mt2][2] = *(const uint32_t*)&Vs[(kk + 4) * QLD + d0];
        a2[mt2][3] = *(const uint32_t*)&Vs[(kk + 4) * QLD + d0 + 8];
      }
#pragma unroll
      for (int nt2 = 0; nt2 < 8; nt2++) {
        const int n0 = nt2 * 8 + lr;
        uint32_t bfr[2];
        bfr[0] = *(const uint32_t*)&Ps[n0 * PLD + kk];
        bfr[1] = *(const uint32_t*)&Ps[n0 * PLD + kk + 4];
        mma_tf32(oacc[0][nt2], a2[0], bfr);
        mma_tf32(oacc[1][nt2], a2[1], bfr);
      }
    }
  }

  // ---- epilogue: normalize, transpose via Qs, coalesced store ----
  __syncthreads();
#pragma unroll
  for (int nt2 = 0; nt2 < 8; nt2++) {
    const int qc = nt2 * 8 + 2 * lc;
    const float il0 = 1.0f / row_l[qc];
    const float il1 = 1.0f / row_l[qc + 1];
#pragma unroll
    for (int mt2 = 0; mt2 < 2; mt2++) {
      const int d0 = w * 32 + mt2 * 16 + lr;
      Qs[qc * QLD + d0] = oacc[mt2][nt2][0] * il0;
      Qs[(qc + 1) * QLD + d0] = oacc[mt2][nt2][1] * il1;
      Qs[qc * QLD + d0 + 8] = oacc[mt2][nt2][2] * il0;
      Qs[(qc + 1) * QLD + d0 + 8] = oacc[mt2][nt2][3] * il1;
    }
  }
  __syncthreads();
  for (int i = tid; i < 64 * 64; i += 256) {
    int r = i >> 6, c4 = (i & 63) << 2;
    float4 o = *(const float4*)&Qs[r * QLD + c4];
    *(float4*)&g_o[(((size_t)(b * S + q0 + r) * H + h) * D) + c4] = o;
  }
}

// ---------------- launch ----------------
extern "C" void kernel_launch(void* const* d_in, const int* in_sizes, int n_in,
                              void* d_out, int out_size) {
  const float* hs   = (const float*)d_in[0];
  const float* cosb = (const float*)d_in[1];
  const float* sinb = (const float*)d_in[2];
  const int*   am   = (const int*)d_in[3];
  const float* Wq   = (const float*)d_in[4];
  const float* Wk   = (const float*)d_in[5];
  const float* Wv   = (const float*)d_in[6];
  const float* Wo   = (const float*)d_in[7];
  const float* qw   = (const float*)d_in[8];
  const float* kw   = (const float*)d_in[9];
  float* out = (float*)d_out;

  float *qp, *kp, *vp, *op;
  cudaGetSymbolAddress((void**)&qp, g_q);
  cudaGetSymbolAddress((void**)&kp, g_k);
  cudaGetSymbolAddress((void**)&vp, g_v);
  cudaGetSymbolAddress((void**)&op, g_o);

  const int M = B * S;  // 4096

  cudaFuncSetAttribute(gemm_mma, cudaFuncAttributeMaxDynamicSharedMemorySize,
                       GEMM_SMEM);
  cudaFuncSetAttribute(attn_mma, cudaFuncAttributeMaxDynamicSharedMemorySize,
                       ATT_SMEM);

  gemm_mma<<<dim3((H * D) / 128, M / 128), 256, GEMM_SMEM>>>(hs, Wq, qp, M, H * D, E);
  gemm_mma<<<dim3((KV * D) / 128, M / 128), 256, GEMM_SMEM>>>(hs, Wk, kp, M, KV * D, E);
  gemm_mma<<<dim3((KV * D) / 128, M / 128), 256, GEMM_SMEM>>>(hs, Wv, vp, M, KV * D, E);

  norm_rope<<<dim3(M, H + KV), 256>>>(cosb, sinb, qw, kw);

  attn_mma<<<dim3(S / 64, H, B), 256, ATT_SMEM>>>(am);

  gemm_mma<<<dim3(E / 128, M / 128), 256, GEMM_SMEM>>>(op, Wo, out, M, E, E);
}

// round 6
// speedup vs baseline: 14.0487x; 1.1733x over previous
#include <cuda_runtime.h>
#include <math.h>
#include <stdint.h>

#define B 2
#define S 2048
#define E 2048
#define H 8
#define KV 4
#define D 256
#define WIN 1024
#define EPS 1e-6f

// ---------------- scratch (device globals; no allocation) ----------------
__device__ float g_q[(size_t)B * S * H * D];   // 32 MB
__device__ float g_k[(size_t)B * S * KV * D];  // 16 MB
__device__ float g_v[(size_t)B * S * KV * D];  // 16 MB
__device__ float g_o[(size_t)B * S * H * D];   // 32 MB
// tf32-rounded copies (so the GEMM hot loop has no cvt)
__device__ float g_hst[(size_t)B * S * E];     // 32 MB
__device__ float g_wqt[(size_t)E * H * D];     // 16 MB
__device__ float g_wkt[(size_t)E * KV * D];    // 8 MB
__device__ float g_wvt[(size_t)E * KV * D];    // 8 MB
__device__ float g_wot[(size_t)H * D * E];     // 16 MB

// ======================= helpers =========================================
__device__ __forceinline__ uint32_t smem_u32(const void* p) {
  uint32_t a;
  asm("{ .reg .u64 t; cvta.to.shared.u64 t, %1; cvt.u32.u64 %0, t; }"
      : "=r"(a) : "l"(p));
  return a;
}
__device__ __forceinline__ uint32_t f2tf32(float x) {
  uint32_t r;
  asm("cvt.rna.tf32.f32 %0, %1;" : "=r"(r) : "f"(x));
  return r;
}
__device__ __forceinline__ void cpasync16(uint32_t dst, const float* src) {
  asm volatile("cp.async.cg.shared.global [%0], [%1], 16;"
               :: "r"(dst), "l"(src));
}
#define CP_COMMIT() asm volatile("cp.async.commit_group;" ::: "memory")
#define CP_WAIT1() asm volatile("cp.async.wait_group 1;" ::: "memory")
#define CP_WAIT0() asm volatile("cp.async.wait_group 0;" ::: "memory")

__device__ __forceinline__ void mma_tf32(float* d, const uint32_t* a,
                                         const uint32_t* b) {
  asm volatile(
      "mma.sync.aligned.m16n8k8.row.col.f32.tf32.tf32.f32 "
      "{%0,%1,%2,%3},{%4,%5,%6,%7},{%8,%9},{%0,%1,%2,%3};"
      : "+f"(d[0]), "+f"(d[1]), "+f"(d[2]), "+f"(d[3])
      : "r"(a[0]), "r"(a[1]), "r"(a[2]), "r"(a[3]), "r"(b[0]), "r"(b[1]));
}

// ---------------- tf32 rounding pass (elementwise) -----------------------
__global__ __launch_bounds__(256) void cvt_tf32(const float4* __restrict__ s,
                                                float4* __restrict__ d,
                                                int n4) {
  int i = blockIdx.x * blockDim.x + threadIdx.x;
  const int stride = gridDim.x * blockDim.x;
  for (; i < n4; i += stride) {
    float4 v = s[i];
    uint4 u;
    u.x = f2tf32(v.x); u.y = f2tf32(v.y);
    u.z = f2tf32(v.z); u.w = f2tf32(v.w);
    ((uint4*)d)[i] = u;
  }
}

// ========= tf32 mma.sync GEMM (cp.async 3-stage): C = A @ Bw =============
// Inputs must already be tf32-rounded fp32. CTA 128x128, BK=32, 256 thr,
// 8 warps (4x2), warp tile 32x64. 2 CTAs/SM.
#define ALD 36
#define BLD 136
#define ASTG (128 * ALD)
#define BSTG (32 * BLD)
#define GEMM_SMEM (3 * (ASTG + BSTG) * 4)

__global__ __launch_bounds__(256, 2) void gemm_mma(
    const float* __restrict__ A, const float* __restrict__ Bw,
    float* __restrict__ C, int M, int N, int K) {
  extern __shared__ float sm[];
  const uint32_t smb = smem_u32(sm);

  const int tid = threadIdx.x;
  const int lane = tid & 31;
  const int wid = tid >> 5;
  const int bm = blockIdx.y * 128;
  const int bn = blockIdx.x * 128;
  const int wm = (wid & 3) * 32;
  const int wn = (wid >> 2) * 64;

  // per-thread cp.async granules (16B each): 4 for A, 4 for B per chunk
  const float* aP[4];
  const float* bP[4];
  uint32_t aS[4], bS[4];
#pragma unroll
  for (int i = 0; i < 4; i++) {
    int idx = tid + 256 * i;
    int ar = idx >> 3, ag = idx & 7;      // A: 128 rows x 8 granules
    int br = idx >> 5, bg = idx & 31;     // B: 32 rows x 32 granules
    aP[i] = A + (size_t)(bm + ar) * K + ag * 4;
    bP[i] = Bw + (size_t)br * N + bn + bg * 4;
    aS[i] = smb + 4 * (ar * ALD + ag * 4);
    bS[i] = smb + 4 * (3 * ASTG + br * BLD + bg * 4);
  }
  const size_t bStep = (size_t)32 * N;
  const int NC = K >> 5;

#define ISSUE(st, c)                                                  \
  do {                                                                \
    const int _ko = (c) * 32;                                         \
    const size_t _bo = (size_t)(c) * bStep;                           \
    _Pragma("unroll") for (int _i = 0; _i < 4; _i++) {                \
      cpasync16(aS[_i] + (st) * (4 * ASTG), aP[_i] + _ko);            \
      cpasync16(bS[_i] + (st) * (4 * BSTG), bP[_i] + _bo);            \
    }                                                                 \
  } while (0)

  ISSUE(0, 0); CP_COMMIT();
  ISSUE(1, 1); CP_COMMIT();

  float acc[2][8][4] = {};

  for (int c = 0; c < NC; c++) {
    if (c + 1 < NC) CP_WAIT1(); else CP_WAIT0();
    __syncthreads();
    if (c + 2 < NC) {
      ISSUE((c + 2) % 3, c + 2);
      CP_COMMIT();
    }

    const float* Ab = sm + (c % 3) * ASTG;
    const float* Bb = sm + 3 * ASTG + (c % 3) * BSTG;
#pragma unroll
    for (int ks = 0; ks < 4; ks++) {
      const int k0 = ks * 8 + (lane & 3);
      uint32_t af[2][4], bf[8][2];
#pragma unroll
      for (int mf = 0; mf < 2; mf++) {
        const int m0 = wm + mf * 16 + (lane >> 2);
        af[mf][0] = *(const uint32_t*)&Ab[m0 * ALD + k0];
        af[mf][1] = *(const uint32_t*)&Ab[(m0 + 8) * ALD + k0];
        af[mf][2] = *(const uint32_t*)&Ab[m0 * ALD + k0 + 4];
        af[mf][3] = *(const uint32_t*)&Ab[(m0 + 8) * ALD + k0 + 4];
      }
#pragma unroll
      for (int nf = 0; nf < 8; nf++) {
        const int n0 = wn + nf * 8 + (lane >> 2);
        bf[nf][0] = *(const uint32_t*)&Bb[k0 * BLD + n0];
        bf[nf][1] = *(const uint32_t*)&Bb[(k0 + 4) * BLD + n0];
      }
#pragma unroll
      for (int mf = 0; mf < 2; mf++)
#pragma unroll
        for (int nf = 0; nf < 8; nf++)
          mma_tf32(acc[mf][nf], af[mf], bf[nf]);
    }
  }

#pragma unroll
  for (int mf = 0; mf < 2; mf++) {
    const int r0 = bm + wm + mf * 16 + (lane >> 2);
#pragma unroll
    for (int nf = 0; nf < 8; nf++) {
      const int col = bn + wn + nf * 8 + 2 * (lane & 3);
      float2 v0, v1;
      v0.x = acc[mf][nf][0]; v0.y = acc[mf][nf][1];
      v1.x = acc[mf][nf][2]; v1.y = acc[mf][nf][3];
      *(float2*)&C[(size_t)r0 * N + col] = v0;
      *(float2*)&C[(size_t)(r0 + 8) * N + col] = v1;
    }
  }
}

// ---------------- fused RMSNorm (Gemma style: *(1+w)) + RoPE ------------
__global__ __launch_bounds__(256) void norm_rope(
    const float* __restrict__ cosb, const float* __restrict__ sinb,
    const float* __restrict__ qw, const float* __restrict__ kw) {
  const int row = blockIdx.x;  // b*S + s
  const int hh = blockIdx.y;
  const int d = threadIdx.x;
  float* buf;
  const float* w;
  int nh, h;
  if (hh < H) { buf = g_q; w = qw; nh = H; h = hh; }
  else        { buf = g_k; w = kw; nh = KV; h = hh - H; }
  float* x = &buf[((size_t)row * nh + h) * D];
  float v = x[d];
  float ss = v * v;
#pragma unroll
  for (int o = 16; o > 0; o >>= 1) ss += __shfl_xor_sync(0xffffffffu, ss, o);
  __shared__ float red[8];
  __shared__ float xs[D];
  if ((d & 31) == 0) red[d >> 5] = ss;
  __syncthreads();
  float tot = 0.f;
#pragma unroll
  for (int i = 0; i < 8; i++) tot += red[i];
  float inv = rsqrtf(tot * (1.0f / D) + EPS);
  float xn = v * inv * (1.0f + w[d]);
  xs[d] = xn;
  __syncthreads();
  float rot = (d < D / 2) ? -xs[d + D / 2] : xs[d - D / 2];
  x[d] = xn * cosb[(size_t)row * D + d] + rot * sinb[(size_t)row * D + d];
}

// ============= mma.sync tf32 flash attention (sliding window) ============
#define QLD 260
#define PLD 68
#define ATT_SMEM ((3 * 64 * QLD + 64 * PLD + 3 * 64 + 2 * 128 + 64) * 4)
#define NEGF (-1e30f)

__global__ __launch_bounds__(256) void attn_mma(const int* __restrict__ am) {
  extern __shared__ float smf[];
  float* Qs = smf;                    // [64][QLD]
  float* Ks = Qs + 64 * QLD;          // [64][QLD]
  float* Vs = Ks + 64 * QLD;          // [64][QLD]
  float* Ps = Vs + 64 * QLD;          // [64][PLD]
  float* row_m = Ps + 64 * PLD;       // [64]
  float* row_l = row_m + 64;          // [64]
  float* row_a = row_l + 64;          // [64]
  float* pm = row_a + 64;             // [2][64]
  float* pl = pm + 128;               // [2][64]
  int* ams = (int*)(pl + 128);        // [64]

  const int tid = threadIdx.x;
  const int lane = tid & 31;
  const int w = tid >> 5;
  const int mt = w & 3;
  const int half = w >> 2;
  const int lr = lane >> 2;
  const int lc = lane & 3;

  const int q0 = blockIdx.x * 64;
  const int h = blockIdx.y;
  const int b = blockIdx.z;
  const int hk = h / (H / KV);

  for (int i = tid; i < 64 * 64; i += 256) {
    int r = i >> 6, c4 = (i & 63) << 2;
    float4 q4 = *(const float4*)&g_q[(((size_t)(b * S + q0 + r) * H + h) * D) + c4];
    uint4 u;
    u.x = f2tf32(q4.x * 0.0625f);
    u.y = f2tf32(q4.y * 0.0625f);
    u.z = f2tf32(q4.z * 0.0625f);
    u.w = f2tf32(q4.w * 0.0625f);
    *(uint4*)&Qs[r * QLD + c4] = u;
  }
  if (tid < 64) {
    row_m[tid] = NEGF;
    row_l[tid] = 0.f;
  }

  float oacc[2][8][4] = {};

  int kb0 = q0 - (WIN - 1);
  if (kb0 < 0) kb0 = 0;
  kb0 &= ~63;
  const int kb_end = q0 + 63;

  for (int kb = kb0; kb <= kb_end; kb += 64) {
    __syncthreads();
    for (int i = tid; i < 64 * 64; i += 256) {
      int r = i >> 6, c4 = (i & 63) << 2;
      size_t base = ((size_t)(b * S + kb + r) * KV + hk) * D + c4;
      float4 k4 = *(const float4*)&g_k[base];
      float4 v4 = *(const float4*)&g_v[base];
      uint4 uk, uv;
      uk.x = f2tf32(k4.x); uk.y = f2tf32(k4.y);
      uk.z = f2tf32(k4.z); uk.w = f2tf32(k4.w);
      uv.x = f2tf32(v4.x); uv.y = f2tf32(v4.y);
      uv.z = f2tf32(v4.z); uv.w = f2tf32(v4.w);
      *(uint4*)&Ks[r * QLD + c4] = uk;
      *(uint4*)&Vs[r * QLD + c4] = uv;
    }
    if (tid < 64) ams[tid] = am[b * S + kb + tid];
    __syncthreads();

    float sacc[4][4] = {};
    const int arow = mt * 16 + lr;
#pragma unroll
    for (int ks = 0; ks < 32; ks++) {
      const int k0 = ks * 8 + lc;
      uint32_t a[4];
      a[0] = *(const uint32_t*)&Qs[arow * QLD + k0];
      a[1] = *(const uint32_t*)&Qs[(arow + 8) * QLD + k0];
      a[2] = *(const uint32_t*)&Qs[arow * QLD + k0 + 4];
      a[3] = *(const uint32_t*)&Qs[(arow + 8) * QLD + k0 + 4];
#pragma unroll
      for (int nt = 0; nt < 4; nt++) {
        const int n0 = half * 32 + nt * 8 + lr;
        uint32_t bfr[2];
        bfr[0] = *(const uint32_t*)&Ks[n0 * QLD + k0];
        bfr[1] = *(const uint32_t*)&Ks[n0 * QLD + k0 + 4];
        mma_tf32(sacc[nt], a, bfr);
      }
    }

    const int r0 = mt * 16 + lr;
    const int r1 = r0 + 8;
    const int qg0 = q0 + r0;
    const int qg1 = q0 + r1;
    float mx0 = NEGF, mx1 = NEGF;
#pragma unroll
    for (int nt = 0; nt < 4; nt++) {
      const int colb = half * 32 + nt * 8 + 2 * lc;
#pragma unroll
      for (int j = 0; j < 4; j++) {
        const int col = colb + (j & 1);
        const int kg = kb + col;
        const int qg = (j < 2) ? qg0 : qg1;
        bool ok = (kg <= qg) && (qg - kg < WIN) && (ams[col] != 0);
        float v = ok ? sacc[nt][j] : NEGF;
        sacc[nt][j] = v;
        if (j < 2) mx0 = fmaxf(mx0, v);
        else       mx1 = fmaxf(mx1, v);
      }
    }
    mx0 = fmaxf(mx0, __shfl_xor_sync(0xffffffffu, mx0, 1));
    mx0 = fmaxf(mx0, __shfl_xor_sync(0xffffffffu, mx0, 2));
    mx1 = fmaxf(mx1, __shfl_xor_sync(0xffffffffu, mx1, 1));
    mx1 = fmaxf(mx1, __shfl_xor_sync(0xffffffffu, mx1, 2));
    if (lc == 0) {
      pm[half * 64 + r0] = mx0;
      pm[half * 64 + r1] = mx1;
    }
    __syncthreads();
    if (tid < 64) {
      float mn = fmaxf(row_m[tid], fmaxf(pm[tid], pm[64 + tid]));
      row_a[tid] = __expf(row_m[tid] - mn);
      row_m[tid] = mn;
    }
    __syncthreads();

    const float mn0 = row_m[r0];
    const float mn1 = row_m[r1];
    float s0 = 0.f, s1 = 0.f;
#pragma unroll
    for (int nt = 0; nt < 4; nt++) {
      const int colb = half * 32 + nt * 8 + 2 * lc;
#pragma unroll
      for (int j = 0; j < 4; j++) {
        const float v = sacc[nt][j];
        const float mnj = (j < 2) ? mn0 : mn1;
        float p = (v < -5e29f) ? 0.f : __expf(v - mnj);
        if (j < 2) s0 += p; else s1 += p;
        const int row = (j < 2) ? r0 : r1;
        *(uint32_t*)&Ps[row * PLD + colb + (j & 1)] = f2tf32(p);
      }
    }
    s0 += __shfl_xor_sync(0xffffffffu, s0, 1);
    s0 += __shfl_xor_sync(0xffffffffu, s0, 2);
    s1 += __shfl_xor_sync(0xffffffffu, s1, 1);
    s1 += __shfl_xor_sync(0xffffffffu, s1, 2);
    if (lc == 0) {
      pl[half * 64 + r0] = s0;
      pl[half * 64 + r1] = s1;
    }
#pragma unroll
    for (int nt2 = 0; nt2 < 8; nt2++) {
      const int qc = nt2 * 8 + 2 * lc;
      const float a0 = row_a[qc];
      const float a1 = row_a[qc + 1];
#pragma unroll
      for (int mt2 = 0; mt2 < 2; mt2++) {
        oacc[mt2][nt2][0] *= a0;
        oacc[mt2][nt2][1] *= a1;
        oacc[mt2][nt2][2] *= a0;
        oacc[mt2][nt2][3] *= a1;
      }
    }
    __syncthreads();
    if (tid < 64) row_l[tid] = row_l[tid] * row_a[tid] + pl[tid] + pl[64 + tid];

#pragma unroll
    for (int ks2 = 0; ks2 < 8; ks2++) {
      const int kk = ks2 * 8 + lc;
      uint32_t a2[2][4];
#pragma unroll
      for (int mt2 = 0; mt2 < 2; mt2++) {
        const int d0 = w * 32 + mt2 * 16 + lr;
        a2[mt2][0] = *(const uint32_t*)&Vs[kk * QLD + d0];
        a2[mt2][1] = *(const uint32_t*)&Vs[kk * QLD + d0 + 8];
        a2[mt2][2] = *(const uint32_t*)&Vs[(kk + 4) * QLD + d0];
        a2[mt2][3] = *(const uint32_t*)&Vs[(kk + 4) * QLD + d0 + 8];
      }
#pragma unroll
      for (int nt2 = 0; nt2 < 8; nt2++) {
        const int n0 = nt2 * 8 + lr;
        uint32_t bfr[2];
        bfr[0] = *(const uint32_t*)&Ps[n0 * PLD + kk];
        bfr[1] = *(const uint32_t*)&Ps[n0 * PLD + kk + 4];
        mma_tf32(oacc[0][nt2], a2[0], bfr);
        mma_tf32(oacc[1][nt2], a2[1], bfr);
      }
    }
  }

  // epilogue: normalize, transpose via Qs, tf32-round, coalesced store
  __syncthreads();
#pragma unroll
  for (int nt2 = 0; nt2 < 8; nt2++) {
    const int qc = nt2 * 8 + 2 * lc;
    const float il0 = 1.0f / row_l[qc];
    const float il1 = 1.0f / row_l[qc + 1];
#pragma unroll
    for (int mt2 = 0; mt2 < 2; mt2++) {
      const int d0 = w * 32 + mt2 * 16 + lr;
      Qs[qc * QLD + d0] = oacc[mt2][nt2][0] * il0;
      Qs[(qc + 1) * QLD + d0] = oacc[mt2][nt2][1] * il1;
      Qs[qc * QLD + d0 + 8] = oacc[mt2][nt2][2] * il0;
      Qs[(qc + 1) * QLD + d0 + 8] = oacc[mt2][nt2][3] * il1;
    }
  }
  __syncthreads();
  for (int i = tid; i < 64 * 64; i += 256) {
    int r = i >> 6, c4 = (i & 63) << 2;
    float4 o = *(const float4*)&Qs[r * QLD + c4];
    uint4 u;
    u.x = f2tf32(o.x); u.y = f2tf32(o.y);
    u.z = f2tf32(o.z); u.w = f2tf32(o.w);
    *(uint4*)&g_o[(((size_t)(b * S + q0 + r) * H + h) * D) + c4] = u;
  }
}

// ---------------- launch ----------------
extern "C" void kernel_launch(void* const* d_in, const int* in_sizes, int n_in,
                              void* d_out, int out_size) {
  const float* hs   = (const float*)d_in[0];
  const float* cosb = (const float*)d_in[1];
  const float* sinb = (const float*)d_in[2];
  const int*   am   = (const int*)d_in[3];
  const float* Wq   = (const float*)d_in[4];
  const float* Wk   = (const float*)d_in[5];
  const float* Wv   = (const float*)d_in[6];
  const float* Wo   = (const float*)d_in[7];
  const float* qw   = (const float*)d_in[8];
  const float* kw   = (const float*)d_in[9];
  float* out = (float*)d_out;

  float *qp, *kp, *vp, *op;
  float *hst, *wqt, *wkt, *wvt, *wot;
  cudaGetSymbolAddress((void**)&qp, g_q);
  cudaGetSymbolAddress((void**)&kp, g_k);
  cudaGetSymbolAddress((void**)&vp, g_v);
  cudaGetSymbolAddress((void**)&op, g_o);
  cudaGetSymbolAddress((void**)&hst, g_hst);
  cudaGetSymbolAddress((void**)&wqt, g_wqt);
  cudaGetSymbolAddress((void**)&wkt, g_wkt);
  cudaGetSymbolAddress((void**)&wvt, g_wvt);
  cudaGetSymbolAddress((void**)&wot, g_wot);

  const int M = B * S;  // 4096

  cudaFuncSetAttribute(gemm_mma, cudaFuncAttributeMaxDynamicSharedMemorySize,
                       GEMM_SMEM);
  cudaFuncSetAttribute(attn_mma, cudaFuncAttributeMaxDynamicSharedMemorySize,
                       ATT_SMEM);

  // tf32 rounding passes
  cvt_tf32<<<4096, 256>>>((const float4*)hs, (float4*)hst, (B * S * E) / 4);
  cvt_tf32<<<2048, 256>>>((const float4*)Wq, (float4*)wqt, (E * H * D) / 4);
  cvt_tf32<<<1024, 256>>>((const float4*)Wk, (float4*)wkt, (E * KV * D) / 4);
  cvt_tf32<<<1024, 256>>>((const float4*)Wv, (float4*)wvt, (E * KV * D) / 4);
  cvt_tf32<<<2048, 256>>>((const float4*)Wo, (float4*)wot, (H * D * E) / 4);

  gemm_mma<<<dim3((H * D) / 128, M / 128), 256, GEMM_SMEM>>>(hst, wqt, qp, M, H * D, E);
  gemm_mma<<<dim3((KV * D) / 128, M / 128), 256, GEMM_SMEM>>>(hst, wkt, kp, M, KV * D, E);
  gemm_mma<<<dim3((KV * D) / 128, M / 128), 256, GEMM_SMEM>>>(hst, wvt, vp, M, KV * D, E);

  norm_rope<<<dim3(M, H + KV), 256>>>(cosb, sinb, qw, kw);

  attn_mma<<<dim3(S / 64, H, B), 256, ATT_SMEM>>>(am);

  gemm_mma<<<dim3(E / 128, M / 128), 256, GEMM_SMEM>>>(op, wot, out, M, E, E);
}

// round 7
// speedup vs baseline: 19.8028x; 1.4096x over previous
#include <cuda_runtime.h>
#include <cuda_fp16.h>
#include <math.h>
#include <stdint.h>

#define B 2
#define S 2048
#define E 2048
#define H 8
#define KV 4
#define D 256
#define WIN 1024
#define EPS 1e-6f

// ---------------- scratch (device globals; no allocation) ----------------
__device__ float g_q[(size_t)B * S * H * D];   // 32 MB
__device__ float g_k[(size_t)B * S * KV * D];  // 16 MB
__device__ float g_v[(size_t)B * S * KV * D];  // 16 MB
__device__ float g_o[(size_t)B * S * H * D];   // 32 MB
// fp16 copies for tensor-core GEMMs
__device__ __half g_hsh[(size_t)B * S * E];    // 16 MB
__device__ __half g_wqh[(size_t)E * H * D];    // 8 MB
__device__ __half g_wkh[(size_t)E * KV * D];   // 4 MB
__device__ __half g_wvh[(size_t)E * KV * D];   // 4 MB
__device__ __half g_woh[(size_t)H * D * E];    // 8 MB
__device__ __half g_oh[(size_t)B * S * H * D]; // 16 MB

// ======================= helpers =========================================
__device__ __forceinline__ uint32_t smem_u32(const void* p) {
  uint32_t a;
  asm("{ .reg .u64 t; cvta.to.shared.u64 t, %1; cvt.u32.u64 %0, t; }"
      : "=r"(a) : "l"(p));
  return a;
}
__device__ __forceinline__ uint32_t f2tf32(float x) {
  uint32_t r;
  asm("cvt.rna.tf32.f32 %0, %1;" : "=r"(r) : "f"(x));
  return r;
}
__device__ __forceinline__ void cpasync16(uint32_t dst, const void* src) {
  asm volatile("cp.async.cg.shared.global [%0], [%1], 16;"
               :: "r"(dst), "l"(src));
}
#define CP_COMMIT() asm volatile("cp.async.commit_group;" ::: "memory")
#define CP_WAIT1() asm volatile("cp.async.wait_group 1;" ::: "memory")
#define CP_WAIT0() asm volatile("cp.async.wait_group 0;" ::: "memory")

__device__ __forceinline__ void mma_tf32(float* d, const uint32_t* a,
                                         const uint32_t* b) {
  asm volatile(
      "mma.sync.aligned.m16n8k8.row.col.f32.tf32.tf32.f32 "
      "{%0,%1,%2,%3},{%4,%5,%6,%7},{%8,%9},{%0,%1,%2,%3};"
      : "+f"(d[0]), "+f"(d[1]), "+f"(d[2]), "+f"(d[3])
      : "r"(a[0]), "r"(a[1]), "r"(a[2]), "r"(a[3]), "r"(b[0]), "r"(b[1]));
}
__device__ __forceinline__ void mma_f16(float* d, const uint32_t* a,
                                        const uint32_t* b) {
  asm volatile(
      "mma.sync.aligned.m16n8k16.row.col.f32.f16.f16.f32 "
      "{%0,%1,%2,%3},{%4,%5,%6,%7},{%8,%9},{%0,%1,%2,%3};"
      : "+f"(d[0]), "+f"(d[1]), "+f"(d[2]), "+f"(d[3])
      : "r"(a[0]), "r"(a[1]), "r"(a[2]), "r"(a[3]), "r"(b[0]), "r"(b[1]));
}
#define LDMX4(r0, r1, r2, r3, addr)                                        \
  asm volatile("ldmatrix.sync.aligned.m8n8.x4.shared.b16 {%0,%1,%2,%3}, [%4];" \
               : "=r"(r0), "=r"(r1), "=r"(r2), "=r"(r3) : "r"(addr))
#define LDMX4T(r0, r1, r2, r3, addr)                                       \
  asm volatile("ldmatrix.sync.aligned.m8n8.x4.trans.shared.b16 {%0,%1,%2,%3}, [%4];" \
               : "=r"(r0), "=r"(r1), "=r"(r2), "=r"(r3) : "r"(addr))

// ---------------- fp32 -> fp16 conversion pass ---------------------------
__global__ __launch_bounds__(256) void cvt_half(const float4* __restrict__ s,
                                                uint2* __restrict__ d, int n4) {
  int i = blockIdx.x * blockDim.x + threadIdx.x;
  const int stride = gridDim.x * blockDim.x;
  for (; i < n4; i += stride) {
    float4 v = s[i];
    __half2 h0 = __floats2half2_rn(v.x, v.y);
    __half2 h1 = __floats2half2_rn(v.z, v.w);
    uint2 u;
    u.x = *reinterpret_cast<uint32_t*>(&h0);
    u.y = *reinterpret_cast<uint32_t*>(&h1);
    d[i] = u;
  }
}

// ========= fp16 mma.sync GEMM (cp.async 3-stage + ldmatrix) ==============
// C[M,N](fp32) = A[M,K](fp16) @ Bw[K,N](fp16). CTA 128x128, BK=32, 256 thr,
// 8 warps (4x2), warp tile 32x64. 2 CTAs/SM.
#define AH_LD 40                     // halves per A smem row (pad 8)
#define BH_LD 136                    // halves per B smem row (pad 8)
#define ASTG_B (128 * AH_LD * 2)     // 10240 B / stage
#define BSTG_B (32 * BH_LD * 2)      // 8704 B / stage
#define GEMMH_SMEM (3 * (ASTG_B + BSTG_B))

__global__ __launch_bounds__(256, 2) void gemm_fp16(
    const __half* __restrict__ A, const __half* __restrict__ Bw,
    float* __restrict__ C, int M, int N, int K) {
  extern __shared__ char smc[];
  const uint32_t smbA = smem_u32(smc);
  const uint32_t smbB = smbA + 3 * ASTG_B;

  const int tid = threadIdx.x;
  const int lane = tid & 31;
  const int wid = tid >> 5;
  const int bm = blockIdx.y * 128;
  const int bn = blockIdx.x * 128;
  const int wm = (wid & 3) * 32;
  const int wn = (wid >> 2) * 64;

  // cp.async granules: A 128x32h = 512 x16B (2/thr), B 32x128h = 512 x16B
  const __half* aP[2];
  const __half* bP[2];
  uint32_t aS[2], bS[2];
#pragma unroll
  for (int i = 0; i < 2; i++) {
    int idx = tid + 256 * i;
    int ar = idx >> 2, ag = idx & 3;
    int br = idx >> 4, bg = idx & 15;
    aP[i] = A + (size_t)(bm + ar) * K + ag * 8;
    bP[i] = Bw + (size_t)br * N + bn + bg * 8;
    aS[i] = smbA + (ar * AH_LD + ag * 8) * 2;
    bS[i] = smbB + (br * BH_LD + bg * 8) * 2;
  }
  const size_t bStep = (size_t)32 * N;
  const int NC = K >> 5;

#define ISSUE_H(st, c)                                               \
  do {                                                               \
    _Pragma("unroll") for (int _i = 0; _i < 2; _i++) {               \
      cpasync16(aS[_i] + (st) * ASTG_B, aP[_i] + (c) * 32);          \
      cpasync16(bS[_i] + (st) * BSTG_B, bP[_i] + (size_t)(c) * bStep); \
    }                                                                \
  } while (0)

  // ldmatrix lane addressing
  const int lrow = (lane & 7) + ((lane >> 3) & 1) * 8;  // 0..15
  const int lcol8 = (lane >> 4) * 8;                    // 0 or 8
  uint32_t aAddr[2], bAddr[4];
#pragma unroll
  for (int mf = 0; mf < 2; mf++)
    aAddr[mf] = smbA + ((wm + mf * 16 + lrow) * AH_LD + lcol8) * 2;
#pragma unroll
  for (int nb = 0; nb < 4; nb++)
    bAddr[nb] = smbB + (lrow * BH_LD + wn + nb * 16 + lcol8) * 2;

  ISSUE_H(0, 0); CP_COMMIT();
  ISSUE_H(1, 1); CP_COMMIT();

  float acc[2][8][4] = {};

  for (int c = 0; c < NC; c++) {
    if (c + 1 < NC) CP_WAIT1(); else CP_WAIT0();
    __syncthreads();
    if (c + 2 < NC) {
      ISSUE_H((c + 2) % 3, c + 2);
      CP_COMMIT();
    }
    const uint32_t aSt = (c % 3) * ASTG_B;
    const uint32_t bSt = (c % 3) * BSTG_B;
#pragma unroll
    for (int ks = 0; ks < 2; ks++) {
      uint32_t af[2][4], bf[8][2];
#pragma unroll
      for (int mf = 0; mf < 2; mf++)
        LDMX4(af[mf][0], af[mf][1], af[mf][2], af[mf][3],
              aAddr[mf] + aSt + ks * 32);  // +16 halves in k
#pragma unroll
      for (int nb = 0; nb < 4; nb++) {
        uint32_t r0, r1, r2, r3;
        LDMX4T(r0, r1, r2, r3, bAddr[nb] + bSt + ks * (16 * BH_LD * 2));
        bf[2 * nb][0] = r0; bf[2 * nb][1] = r1;
        bf[2 * nb + 1][0] = r2; bf[2 * nb + 1][1] = r3;
      }
#pragma unroll
      for (int mf = 0; mf < 2; mf++)
#pragma unroll
        for (int nf = 0; nf < 8; nf++)
          mma_f16(acc[mf][nf], af[mf], bf[nf]);
    }
  }

#pragma unroll
  for (int mf = 0; mf < 2; mf++) {
    const int r0 = bm + wm + mf * 16 + (lane >> 2);
#pragma unroll
    for (int nf = 0; nf < 8; nf++) {
      const int col = bn + wn + nf * 8 + 2 * (lane & 3);
      float2 v0, v1;
      v0.x = acc[mf][nf][0]; v0.y = acc[mf][nf][1];
      v1.x = acc[mf][nf][2]; v1.y = acc[mf][nf][3];
      *(float2*)&C[(size_t)r0 * N + col] = v0;
      *(float2*)&C[(size_t)(r0 + 8) * N + col] = v1;
    }
  }
}

// ---------------- fused RMSNorm (Gemma style: *(1+w)) + RoPE ------------
__global__ __launch_bounds__(256) void norm_rope(
    const float* __restrict__ cosb, const float* __restrict__ sinb,
    const float* __restrict__ qw, const float* __restrict__ kw) {
  const int row = blockIdx.x;  // b*S + s
  const int hh = blockIdx.y;
  const int d = threadIdx.x;
  float* buf;
  const float* w;
  int nh, h;
  if (hh < H) { buf = g_q; w = qw; nh = H; h = hh; }
  else        { buf = g_k; w = kw; nh = KV; h = hh - H; }
  float* x = &buf[((size_t)row * nh + h) * D];
  float v = x[d];
  float ss = v * v;
#pragma unroll
  for (int o = 16; o > 0; o >>= 1) ss += __shfl_xor_sync(0xffffffffu, ss, o);
  __shared__ float red[8];
  __shared__ float xs[D];
  if ((d & 31) == 0) red[d >> 5] = ss;
  __syncthreads();
  float tot = 0.f;
#pragma unroll
  for (int i = 0; i < 8; i++) tot += red[i];
  float inv = rsqrtf(tot * (1.0f / D) + EPS);
  float xn = v * inv * (1.0f + w[d]);
  xs[d] = xn;
  __syncthreads();
  float rot = (d < D / 2) ? -xs[d + D / 2] : xs[d - D / 2];
  x[d] = xn * cosb[(size_t)row * D + d] + rot * sinb[(size_t)row * D + d];
}

// ============= mma.sync tf32 flash attention (sliding window) ============
#define QLD 260
#define PLD 68
#define ATT_SMEM ((3 * 64 * QLD + 64 * PLD + 3 * 64 + 2 * 128 + 64) * 4)
#define NEGF (-1e30f)

__global__ __launch_bounds__(256) void attn_mma(const int* __restrict__ am) {
  extern __shared__ float smf[];
  float* Qs = smf;                    // [64][QLD]
  float* Ks = Qs + 64 * QLD;          // [64][QLD]
  float* Vs = Ks + 64 * QLD;          // [64][QLD]
  float* Ps = Vs + 64 * QLD;          // [64][PLD]
  float* row_m = Ps + 64 * PLD;       // [64]
  float* row_l = row_m + 64;          // [64]
  float* row_a = row_l + 64;          // [64]
  float* pm = row_a + 64;             // [2][64]
  float* pl = pm + 128;               // [2][64]
  int* ams = (int*)(pl + 128);        // [64]

  const int tid = threadIdx.x;
  const int lane = tid & 31;
  const int w = tid >> 5;
  const int mt = w & 3;
  const int half = w >> 2;
  const int lr = lane >> 2;
  const int lc = lane & 3;

  const int q0 = blockIdx.x * 64;
  const int h = blockIdx.y;
  const int b = blockIdx.z;
  const int hk = h / (H / KV);

  for (int i = tid; i < 64 * 64; i += 256) {
    int r = i >> 6, c4 = (i & 63) << 2;
    float4 q4 = *(const float4*)&g_q[(((size_t)(b * S + q0 + r) * H + h) * D) + c4];
    uint4 u;
    u.x = f2tf32(q4.x * 0.0625f);
    u.y = f2tf32(q4.y * 0.0625f);
    u.z = f2tf32(q4.z * 0.0625f);
    u.w = f2tf32(q4.w * 0.0625f);
    *(uint4*)&Qs[r * QLD + c4] = u;
  }
  if (tid < 64) {
    row_m[tid] = NEGF;
    row_l[tid] = 0.f;
  }

  float oacc[2][8][4] = {};

  int kb0 = q0 - (WIN - 1);
  if (kb0 < 0) kb0 = 0;
  kb0 &= ~63;
  const int kb_end = q0 + 63;

  for (int kb = kb0; kb <= kb_end; kb += 64) {
    __syncthreads();
    for (int i = tid; i < 64 * 64; i += 256) {
      int r = i >> 6, c4 = (i & 63) << 2;
      size_t base = ((size_t)(b * S + kb + r) * KV + hk) * D + c4;
      float4 k4 = *(const float4*)&g_k[base];
      float4 v4 = *(const float4*)&g_v[base];
      uint4 uk, uv;
      uk.x = f2tf32(k4.x); uk.y = f2tf32(k4.y);
      uk.z = f2tf32(k4.z); uk.w = f2tf32(k4.w);
      uv.x = f2tf32(v4.x); uv.y = f2tf32(v4.y);
      uv.z = f2tf32(v4.z); uv.w = f2tf32(v4.w);
      *(uint4*)&Ks[r * QLD + c4] = uk;
      *(uint4*)&Vs[r * QLD + c4] = uv;
    }
    if (tid < 64) ams[tid] = am[b * S + kb + tid];
    __syncthreads();

    float sacc[4][4] = {};
    const int arow = mt * 16 + lr;
#pragma unroll
    for (int ks = 0; ks < 32; ks++) {
      const int k0 = ks * 8 + lc;
      uint32_t a[4];
      a[0] = *(const uint32_t*)&Qs[arow * QLD + k0];
      a[1] = *(const uint32_t*)&Qs[(arow + 8) * QLD + k0];
      a[2] = *(const uint32_t*)&Qs[arow * QLD + k0 + 4];
      a[3] = *(const uint32_t*)&Qs[(arow + 8) * QLD + k0 + 4];
#pragma unroll
      for (int nt = 0; nt < 4; nt++) {
        const int n0 = half * 32 + nt * 8 + lr;
        uint32_t bfr[2];
        bfr[0] = *(const uint32_t*)&Ks[n0 * QLD + k0];
        bfr[1] = *(const uint32_t*)&Ks[n0 * QLD + k0 + 4];
        mma_tf32(sacc[nt], a, bfr);
      }
    }

    const int r0 = mt * 16 + lr;
    const int r1 = r0 + 8;
    const int qg0 = q0 + r0;
    const int qg1 = q0 + r1;
    float mx0 = NEGF, mx1 = NEGF;
#pragma unroll
    for (int nt = 0; nt < 4; nt++) {
      const int colb = half * 32 + nt * 8 + 2 * lc;
#pragma unroll
      for (int j = 0; j < 4; j++) {
        const int col = colb + (j & 1);
        const int kg = kb + col;
        const int qg = (j < 2) ? qg0 : qg1;
        bool ok = (kg <= qg) && (qg - kg < WIN) && (ams[col] != 0);
        float v = ok ? sacc[nt][j] : NEGF;
        sacc[nt][j] = v;
        if (j < 2) mx0 = fmaxf(mx0, v);
        else       mx1 = fmaxf(mx1, v);
      }
    }
    mx0 = fmaxf(mx0, __shfl_xor_sync(0xffffffffu, mx0, 1));
    mx0 = fmaxf(mx0, __shfl_xor_sync(0xffffffffu, mx0, 2));
    mx1 = fmaxf(mx1, __shfl_xor_sync(0xffffffffu, mx1, 1));
    mx1 = fmaxf(mx1, __shfl_xor_sync(0xffffffffu, mx1, 2));
    if (lc == 0) {
      pm[half * 64 + r0] = mx0;
      pm[half * 64 + r1] = mx1;
    }
    __syncthreads();
    if (tid < 64) {
      float mn = fmaxf(row_m[tid], fmaxf(pm[tid], pm[64 + tid]));
      row_a[tid] = __expf(row_m[tid] - mn);
      row_m[tid] = mn;
    }
    __syncthreads();

    const float mn0 = row_m[r0];
    const float mn1 = row_m[r1];
    float s0 = 0.f, s1 = 0.f;
#pragma unroll
    for (int nt = 0; nt < 4; nt++) {
      const int colb = half * 32 + nt * 8 + 2 * lc;
#pragma unroll
      for (int j = 0; j < 4; j++) {
        const float v = sacc[nt][j];
        const float mnj = (j < 2) ? mn0 : mn1;
        float p = (v < -5e29f) ? 0.f : __expf(v - mnj);
        if (j < 2) s0 += p; else s1 += p;
        const int row = (j < 2) ? r0 : r1;
        *(uint32_t*)&Ps[row * PLD + colb + (j & 1)] = f2tf32(p);
      }
    }
    s0 += __shfl_xor_sync(0xffffffffu, s0, 1);
    s0 += __shfl_xor_sync(0xffffffffu, s0, 2);
    s1 += __shfl_xor_sync(0xffffffffu, s1, 1);
    s1 += __shfl_xor_sync(0xffffffffu, s1, 2);
    if (lc == 0) {
      pl[half * 64 + r0] = s0;
      pl[half * 64 + r1] = s1;
    }
#pragma unroll
    for (int nt2 = 0; nt2 < 8; nt2++) {
      const int qc = nt2 * 8 + 2 * lc;
      const float a0 = row_a[qc];
      const float a1 = row_a[qc + 1];
#pragma unroll
      for (int mt2 = 0; mt2 < 2; mt2++) {
        oacc[mt2][nt2][0] *= a0;
        oacc[mt2][nt2][1] *= a1;
        oacc[mt2][nt2][2] *= a0;
        oacc[mt2][nt2][3] *= a1;
      }
    }
    __syncthreads();
    if (tid < 64) row_l[tid] = row_l[tid] * row_a[tid] + pl[tid] + pl[64 + tid];

#pragma unroll
    for (int ks2 = 0; ks2 < 8; ks2++) {
      const int kk = ks2 * 8 + lc;
      uint32_t a2[2][4];
#pragma unroll
      for (int mt2 = 0; mt2 < 2; mt2++) {
        const int d0 = w * 32 + mt2 * 16 + lr;
        a2[mt2][0] = *(const uint32_t*)&Vs[kk * QLD + d0];
        a2[mt2][1] = *(const uint32_t*)&Vs[kk * QLD + d0 + 8];
        a2[mt2][2] = *(const uint32_t*)&Vs[(kk + 4) * QLD + d0];
        a2[mt2][3] = *(const uint32_t*)&Vs[(kk + 4) * QLD + d0 + 8];
      }
#pragma unroll
      for (int nt2 = 0; nt2 < 8; nt2++) {
        const int n0 = nt2 * 8 + lr;
        uint32_t bfr[2];
        bfr[0] = *(const uint32_t*)&Ps[n0 * PLD + kk];
        bfr[1] = *(const uint32_t*)&Ps[n0 * PLD + kk + 4];
        mma_tf32(oacc[0][nt2], a2[0], bfr);
        mma_tf32(oacc[1][nt2], a2[1], bfr);
      }
    }
  }

  // epilogue: normalize, transpose via Qs, coalesced store
  __syncthreads();
#pragma unroll
  for (int nt2 = 0; nt2 < 8; nt2++) {
    const int qc = nt2 * 8 + 2 * lc;
    const float il0 = 1.0f / row_l[qc];
    const float il1 = 1.0f / row_l[qc + 1];
#pragma unroll
    for (int mt2 = 0; mt2 < 2; mt2++) {
      const int d0 = w * 32 + mt2 * 16 + lr;
      Qs[qc * QLD + d0] = oacc[mt2][nt2][0] * il0;
      Qs[(qc + 1) * QLD + d0] = oacc[mt2][nt2][1] * il1;
      Qs[qc * QLD + d0 + 8] = oacc[mt2][nt2][2] * il0;
      Qs[(qc + 1) * QLD + d0 + 8] = oacc[mt2][nt2][3] * il1;
    }
  }
  __syncthreads();
  for (int i = tid; i < 64 * 64; i += 256) {
    int r = i >> 6, c4 = (i & 63) << 2;
    float4 o = *(const float4*)&Qs[r * QLD + c4];
    *(float4*)&g_o[(((size_t)(b * S + q0 + r) * H + h) * D) + c4] = o;
  }
}

// ---------------- launch ----------------
extern "C" void kernel_launch(void* const* d_in, const int* in_sizes, int n_in,
                              void* d_out, int out_size) {
  const float* hs   = (const float*)d_in[0];
  const float* cosb = (const float*)d_in[1];
  const float* sinb = (const float*)d_in[2];
  const int*   am   = (const int*)d_in[3];
  const float* Wq   = (const float*)d_in[4];
  const float* Wk   = (const float*)d_in[5];
  const float* Wv   = (const float*)d_in[6];
  const float* Wo   = (const float*)d_in[7];
  const float* qw   = (const float*)d_in[8];
  const float* kw   = (const float*)d_in[9];
  float* out = (float*)d_out;

  float *qp, *kp, *vp, *op;
  __half *hsh, *wqh, *wkh, *wvh, *woh, *oh;
  cudaGetSymbolAddress((void**)&qp, g_q);
  cudaGetSymbolAddress((void**)&kp, g_k);
  cudaGetSymbolAddress((void**)&vp, g_v);
  cudaGetSymbolAddress((void**)&op, g_o);
  cudaGetSymbolAddress((void**)&hsh, g_hsh);
  cudaGetSymbolAddress((void**)&wqh, g_wqh);
  cudaGetSymbolAddress((void**)&wkh, g_wkh);
  cudaGetSymbolAddress((void**)&wvh, g_wvh);
  cudaGetSymbolAddress((void**)&woh, g_woh);
  cudaGetSymbolAddress((void**)&oh, g_oh);

  const int M = B * S;  // 4096

  cudaFuncSetAttribute(gemm_fp16, cudaFuncAttributeMaxDynamicSharedMemorySize,
                       GEMMH_SMEM);
  cudaFuncSetAttribute(attn_mma, cudaFuncAttributeMaxDynamicSharedMemorySize,
                       ATT_SMEM);

  // fp16 conversion passes
  cvt_half<<<2048, 256>>>((const float4*)hs, (uint2*)hsh, (B * S * E) / 4);
  cvt_half<<<1024, 256>>>((const float4*)Wq, (uint2*)wqh, (E * H * D) / 4);
  cvt_half<<<512, 256>>>((const float4*)Wk, (uint2*)wkh, (E * KV * D) / 4);
  cvt_half<<<512, 256>>>((const float4*)Wv, (uint2*)wvh, (E * KV * D) / 4);
  cvt_half<<<1024, 256>>>((const float4*)Wo, (uint2*)woh, (H * D * E) / 4);

  gemm_fp16<<<dim3((H * D) / 128, M / 128), 256, GEMMH_SMEM>>>(hsh, wqh, qp, M, H * D, E);
  gemm_fp16<<<dim3((KV * D) / 128, M / 128), 256, GEMMH_SMEM>>>(hsh, wkh, kp, M, KV * D, E);
  gemm_fp16<<<dim3((KV * D) / 128, M / 128), 256, GEMMH_SMEM>>>(hsh, wvh, vp, M, KV * D, E);

  norm_rope<<<dim3(M, H + KV), 256>>>(cosb, sinb, qw, kw);

  attn_mma<<<dim3(S / 64, H, B), 256, ATT_SMEM>>>(am);

  cvt_half<<<2048, 256>>>((const float4*)op, (uint2*)oh, (B * S * H * D) / 4);
  gemm_fp16<<<dim3(E / 128, M / 128), 256, GEMMH_SMEM>>>(oh, woh, out, M, E, E);
}

// round 8
// speedup vs baseline: 25.2878x; 1.2770x over previous
#include <cuda_runtime.h>
#include <cuda_fp16.h>
#include <math.h>
#include <stdint.h>

#define B 2
#define S 2048
#define E 2048
#define H 8
#define KV 4
#define D 256
#define WIN 1024
#define EPS 1e-6f

// ---------------- scratch (device globals; no allocation) ----------------
__device__ float g_q[(size_t)B * S * H * D];    // 32 MB (fp32 Q proj out)
__device__ float g_k[(size_t)B * S * KV * D];   // 16 MB
__device__ float g_v[(size_t)B * S * KV * D];   // 16 MB
// fp16 operands
__device__ __half g_hsh[(size_t)B * S * E];     // 16 MB
__device__ __half g_wqh[(size_t)E * H * D];     // 8 MB
__device__ __half g_wkh[(size_t)E * KV * D];    // 4 MB
__device__ __half g_wvh[(size_t)E * KV * D];    // 4 MB
__device__ __half g_woh[(size_t)H * D * E];     // 8 MB
__device__ __half g_qh[(size_t)B * S * H * D];  // 16 MB (normed+roped+scaled)
__device__ __half g_kh[(size_t)B * S * KV * D]; // 8 MB
__device__ __half g_vh[(size_t)B * S * KV * D]; // 8 MB
__device__ __half g_oh[(size_t)B * S * H * D];  // 16 MB (attn out)

// ======================= helpers =========================================
__device__ __forceinline__ uint32_t smem_u32(const void* p) {
  uint32_t a;
  asm("{ .reg .u64 t; cvta.to.shared.u64 t, %1; cvt.u32.u64 %0, t; }"
      : "=r"(a) : "l"(p));
  return a;
}
__device__ __forceinline__ void cpasync16(uint32_t dst, const void* src) {
  asm volatile("cp.async.cg.shared.global [%0], [%1], 16;"
               :: "r"(dst), "l"(src));
}
#define CP_COMMIT() asm volatile("cp.async.commit_group;" ::: "memory")
#define CP_WAIT1() asm volatile("cp.async.wait_group 1;" ::: "memory")
#define CP_WAIT0() asm volatile("cp.async.wait_group 0;" ::: "memory")

__device__ __forceinline__ void mma_f16(float* d, const uint32_t* a,
                                        const uint32_t* b) {
  asm volatile(
      "mma.sync.aligned.m16n8k16.row.col.f32.f16.f16.f32 "
      "{%0,%1,%2,%3},{%4,%5,%6,%7},{%8,%9},{%0,%1,%2,%3};"
      : "+f"(d[0]), "+f"(d[1]), "+f"(d[2]), "+f"(d[3])
      : "r"(a[0]), "r"(a[1]), "r"(a[2]), "r"(a[3]), "r"(b[0]), "r"(b[1]));
}
#define LDMX4(r0, r1, r2, r3, addr)                                        \
  asm volatile("ldmatrix.sync.aligned.m8n8.x4.shared.b16 {%0,%1,%2,%3}, [%4];" \
               : "=r"(r0), "=r"(r1), "=r"(r2), "=r"(r3) : "r"(addr))
#define LDMX4T(r0, r1, r2, r3, addr)                                       \
  asm volatile("ldmatrix.sync.aligned.m8n8.x4.trans.shared.b16 {%0,%1,%2,%3}, [%4];" \
               : "=r"(r0), "=r"(r1), "=r"(r2), "=r"(r3) : "r"(addr))

// ---------------- fp32 -> fp16 conversion pass ---------------------------
__global__ __launch_bounds__(256) void cvt_half(const float4* __restrict__ s,
                                                uint2* __restrict__ d, int n4) {
  int i = blockIdx.x * blockDim.x + threadIdx.x;
  const int stride = gridDim.x * blockDim.x;
  for (; i < n4; i += stride) {
    float4 v = s[i];
    __half2 h0 = __floats2half2_rn(v.x, v.y);
    __half2 h1 = __floats2half2_rn(v.z, v.w);
    uint2 u;
    u.x = *reinterpret_cast<uint32_t*>(&h0);
    u.y = *reinterpret_cast<uint32_t*>(&h1);
    d[i] = u;
  }
}

// ========= fp16 mma.sync GEMM (cp.async 3-stage + ldmatrix) ==============
#define AH_LD 40
#define BH_LD 136
#define ASTG_B (128 * AH_LD * 2)
#define BSTG_B (32 * BH_LD * 2)
#define GEMMH_SMEM (3 * (ASTG_B + BSTG_B))

__global__ __launch_bounds__(256, 2) void gemm_fp16(
    const __half* __restrict__ A, const __half* __restrict__ Bw,
    float* __restrict__ C, int M, int N, int K) {
  extern __shared__ char smc[];
  const uint32_t smbA = smem_u32(smc);
  const uint32_t smbB = smbA + 3 * ASTG_B;

  const int tid = threadIdx.x;
  const int lane = tid & 31;
  const int wid = tid >> 5;
  const int bm = blockIdx.y * 128;
  const int bn = blockIdx.x * 128;
  const int wm = (wid & 3) * 32;
  const int wn = (wid >> 2) * 64;

  const __half* aP[2];
  const __half* bP[2];
  uint32_t aS[2], bS[2];
#pragma unroll
  for (int i = 0; i < 2; i++) {
    int idx = tid + 256 * i;
    int ar = idx >> 2, ag = idx & 3;
    int br = idx >> 4, bg = idx & 15;
    aP[i] = A + (size_t)(bm + ar) * K + ag * 8;
    bP[i] = Bw + (size_t)br * N + bn + bg * 8;
    aS[i] = smbA + (ar * AH_LD + ag * 8) * 2;
    bS[i] = smbB + (br * BH_LD + bg * 8) * 2;
  }
  const size_t bStep = (size_t)32 * N;
  const int NC = K >> 5;

#define ISSUE_H(st, c)                                               \
  do {                                                               \
    _Pragma("unroll") for (int _i = 0; _i < 2; _i++) {               \
      cpasync16(aS[_i] + (st) * ASTG_B, aP[_i] + (c) * 32);          \
      cpasync16(bS[_i] + (st) * BSTG_B, bP[_i] + (size_t)(c) * bStep); \
    }                                                                \
  } while (0)

  const int lrow = lane & 15;
  const int lcol8 = (lane >> 4) * 8;
  uint32_t aAddr[2], bAddr[4];
#pragma unroll
  for (int mf = 0; mf < 2; mf++)
    aAddr[mf] = smbA + ((wm + mf * 16 + lrow) * AH_LD + lcol8) * 2;
#pragma unroll
  for (int nb = 0; nb < 4; nb++)
    bAddr[nb] = smbB + (lrow * BH_LD + wn + nb * 16 + lcol8) * 2;

  ISSUE_H(0, 0); CP_COMMIT();
  ISSUE_H(1, 1); CP_COMMIT();

  float acc[2][8][4] = {};

  for (int c = 0; c < NC; c++) {
    if (c + 1 < NC) CP_WAIT1(); else CP_WAIT0();
    __syncthreads();
    if (c + 2 < NC) {
      ISSUE_H((c + 2) % 3, c + 2);
      CP_COMMIT();
    }
    const uint32_t aSt = (c % 3) * ASTG_B;
    const uint32_t bSt = (c % 3) * BSTG_B;
#pragma unroll
    for (int ks = 0; ks < 2; ks++) {
      uint32_t af[2][4], bf[8][2];
#pragma unroll
      for (int mf = 0; mf < 2; mf++)
        LDMX4(af[mf][0], af[mf][1], af[mf][2], af[mf][3],
              aAddr[mf] + aSt + ks * 32);
#pragma unroll
      for (int nb = 0; nb < 4; nb++) {
        uint32_t r0, r1, r2, r3;
        LDMX4T(r0, r1, r2, r3, bAddr[nb] + bSt + ks * (16 * BH_LD * 2));
        bf[2 * nb][0] = r0; bf[2 * nb][1] = r1;
        bf[2 * nb + 1][0] = r2; bf[2 * nb + 1][1] = r3;
      }
#pragma unroll
      for (int mf = 0; mf < 2; mf++)
#pragma unroll
        for (int nf = 0; nf < 8; nf++)
          mma_f16(acc[mf][nf], af[mf], bf[nf]);
    }
  }

#pragma unroll
  for (int mf = 0; mf < 2; mf++) {
    const int r0 = bm + wm + mf * 16 + (lane >> 2);
#pragma unroll
    for (int nf = 0; nf < 8; nf++) {
      const int col = bn + wn + nf * 8 + 2 * (lane & 3);
      float2 v0, v1;
      v0.x = acc[mf][nf][0]; v0.y = acc[mf][nf][1];
      v1.x = acc[mf][nf][2]; v1.y = acc[mf][nf][3];
      *(float2*)&C[(size_t)r0 * N + col] = v0;
      *(float2*)&C[(size_t)(r0 + 8) * N + col] = v1;
    }
  }
}

// -------- fused RMSNorm + RoPE; emits fp16 (Q pre-scaled by D^-1/2) ------
__global__ __launch_bounds__(256) void norm_rope(
    const float* __restrict__ cosb, const float* __restrict__ sinb,
    const float* __restrict__ qw, const float* __restrict__ kw) {
  const int row = blockIdx.x;  // b*S + s
  const int hh = blockIdx.y;
  const int d = threadIdx.x;
  const float* src;
  __half* dst;
  const float* w;
  float oscale;
  if (hh < H) {
    src = &g_q[((size_t)row * H + hh) * D];
    dst = &g_qh[((size_t)row * H + hh) * D];
    w = qw; oscale = 0.0625f;
  } else {
    int h = hh - H;
    src = &g_k[((size_t)row * KV + h) * D];
    dst = &g_kh[((size_t)row * KV + h) * D];
    w = kw; oscale = 1.0f;
  }
  float v = src[d];
  float ss = v * v;
#pragma unroll
  for (int o = 16; o > 0; o >>= 1) ss += __shfl_xor_sync(0xffffffffu, ss, o);
  __shared__ float red[8];
  __shared__ float xs[D];
  if ((d & 31) == 0) red[d >> 5] = ss;
  __syncthreads();
  float tot = 0.f;
#pragma unroll
  for (int i = 0; i < 8; i++) tot += red[i];
  float inv = rsqrtf(tot * (1.0f / D) + EPS);
  float xn = v * inv * (1.0f + w[d]);
  xs[d] = xn;
  __syncthreads();
  float rot = (d < D / 2) ? -xs[d + D / 2] : xs[d - D / 2];
  float xr = xn * cosb[(size_t)row * D + d] + rot * sinb[(size_t)row * D + d];
  dst[d] = __float2half(xr * oscale);
}

// ============= fp16 mma flash attention (sliding window) =================
// CTA: 64 q, 256 thr = 8 warps. QK: warp -> (mt 16q, half 32keys), k=256.
// PV transposed: out^T[d][q] = V^T @ P^T; warp -> 32 d, all 64 q.
#define QHLD 264   // halves/row; 528B stride => word stride ≡ 4 mod 32
#define PHLD 72
#define ATTH_SMEM 112640
#define NEGF (-1e30f)

__global__ __launch_bounds__(256, 2) void attn_f16(const int* __restrict__ am) {
  extern __shared__ char smc[];
  __half* Qs = (__half*)smc;            // [64][QHLD]
  __half* Ks = Qs + 64 * QHLD;
  __half* Vs = Ks + 64 * QHLD;
  __half* Ps = Vs + 64 * QHLD;          // [64][PHLD]
  float* row_m = (float*)(smc + 110592);
  float* row_l = row_m + 64;
  float* row_a = row_l + 64;
  float* pm = row_a + 64;               // [2][64]
  float* pl = pm + 128;                 // [2][64]
  int* ams = (int*)(pl + 128);          // [64]

  const uint32_t uQ = smem_u32(Qs);
  const uint32_t uK = smem_u32(Ks);
  const uint32_t uV = smem_u32(Vs);
  const uint32_t uP = smem_u32(Ps);

  const int tid = threadIdx.x;
  const int lane = tid & 31;
  const int w = tid >> 5;
  const int mt = w & 3;
  const int half_ = w >> 2;
  const int lr = lane >> 2;
  const int lc = lane & 3;
  const int lrow = lane & 15;
  const int lcol8 = (lane >> 4) * 8;

  const int q0 = blockIdx.x * 64;
  const int h = blockIdx.y;
  const int b = blockIdx.z;
  const int hk = h / (H / KV);

  // stage Q (fp16, pre-scaled in norm_rope) via cp.async
  {
    const __half* qsrc = g_qh + ((size_t)(b * S + q0) * H + h) * D;
    for (int i = tid; i < 2048; i += 256) {
      int r = i >> 5, g = i & 31;
      cpasync16(uQ + (r * QHLD + g * 8) * 2, qsrc + (size_t)r * H * D + g * 8);
    }
    CP_COMMIT();
  }
  if (tid < 64) {
    row_m[tid] = NEGF;
    row_l[tid] = 0.f;
  }

  float oacc[2][8][4] = {};

  int kb0 = q0 - (WIN - 1);
  if (kb0 < 0) kb0 = 0;
  kb0 &= ~63;
  const int kb_end = q0 + 63;

  for (int kb = kb0; kb <= kb_end; kb += 64) {
    __syncthreads();  // prev iter's Ks/Vs/Ps readers done
    {
      const __half* ksrc = g_kh + ((size_t)(b * S + kb) * KV + hk) * D;
      const __half* vsrc = g_vh + ((size_t)(b * S + kb) * KV + hk) * D;
      for (int i = tid; i < 2048; i += 256) {
        int r = i >> 5, g = i & 31;
        size_t so = (size_t)r * KV * D + g * 8;
        uint32_t doff = (r * QHLD + g * 8) * 2;
        cpasync16(uK + doff, ksrc + so);
        cpasync16(uV + doff, vsrc + so);
      }
      CP_COMMIT();
    }
    if (tid < 64) ams[tid] = am[b * S + kb + tid];
    CP_WAIT0();
    __syncthreads();

    // ---- QK^T (fp16 k16): 16q x 32keys per warp ----
    float sacc[4][4] = {};
    const uint32_t qa = uQ + ((mt * 16 + lrow) * QHLD + lcol8) * 2;
    const uint32_t ka0 = uK + ((half_ * 32 + lrow) * QHLD + lcol8) * 2;
    const uint32_t ka1 = ka0 + 16 * QHLD * 2;
#pragma unroll
    for (int ks = 0; ks < 16; ks++) {
      uint32_t a[4], r0, r1, r2, r3;
      LDMX4(a[0], a[1], a[2], a[3], qa + ks * 32);
      LDMX4(r0, r1, r2, r3, ka0 + ks * 32);
      {
        uint32_t b0[2] = {r0, r2}, b1[2] = {r1, r3};
        mma_f16(sacc[0], a, b0);
        mma_f16(sacc[1], a, b1);
      }
      LDMX4(r0, r1, r2, r3, ka1 + ks * 32);
      {
        uint32_t b0[2] = {r0, r2}, b1[2] = {r1, r3};
        mma_f16(sacc[2], a, b0);
        mma_f16(sacc[3], a, b1);
      }
    }

    // ---- mask + partial row max ----
    const int r0 = mt * 16 + lr;
    const int r1 = r0 + 8;
    const int qg0 = q0 + r0;
    const int qg1 = q0 + r1;
    float mx0 = NEGF, mx1 = NEGF;
#pragma unroll
    for (int nt = 0; nt < 4; nt++) {
      const int colb = half_ * 32 + nt * 8 + 2 * lc;
#pragma unroll
      for (int j = 0; j < 4; j++) {
        const int col = colb + (j & 1);
        const int kg = kb + col;
        const int qg = (j < 2) ? qg0 : qg1;
        bool ok = (kg <= qg) && (qg - kg < WIN) && (ams[col] != 0);
        float v = ok ? sacc[nt][j] : NEGF;
        sacc[nt][j] = v;
        if (j < 2) mx0 = fmaxf(mx0, v);
        else       mx1 = fmaxf(mx1, v);
      }
    }
    mx0 = fmaxf(mx0, __shfl_xor_sync(0xffffffffu, mx0, 1));
    mx0 = fmaxf(mx0, __shfl_xor_sync(0xffffffffu, mx0, 2));
    mx1 = fmaxf(mx1, __shfl_xor_sync(0xffffffffu, mx1, 1));
    mx1 = fmaxf(mx1, __shfl_xor_sync(0xffffffffu, mx1, 2));
    if (lc == 0) {
      pm[half_ * 64 + r0] = mx0;
      pm[half_ * 64 + r1] = mx1;
    }
    __syncthreads();
    if (tid < 64) {
      float mn = fmaxf(row_m[tid], fmaxf(pm[tid], pm[64 + tid]));
      row_a[tid] = __expf(row_m[tid] - mn);
      row_m[tid] = mn;
    }
    __syncthreads();

    // ---- P = exp(s - m) -> fp16 Ps; partial sums; rescale oacc ----
    const float mn0 = row_m[r0];
    const float mn1 = row_m[r1];
    float s0 = 0.f, s1 = 0.f;
#pragma unroll
    for (int nt = 0; nt < 4; nt++) {
      const int colb = half_ * 32 + nt * 8 + 2 * lc;
      float p00 = (sacc[nt][0] < -5e29f) ? 0.f : __expf(sacc[nt][0] - mn0);
      float p01 = (sacc[nt][1] < -5e29f) ? 0.f : __expf(sacc[nt][1] - mn0);
      float p10 = (sacc[nt][2] < -5e29f) ? 0.f : __expf(sacc[nt][2] - mn1);
      float p11 = (sacc[nt][3] < -5e29f) ? 0.f : __expf(sacc[nt][3] - mn1);
      s0 += p00 + p01;
      s1 += p10 + p11;
      *(__half2*)&Ps[r0 * PHLD + colb] = __floats2half2_rn(p00, p01);
      *(__half2*)&Ps[r1 * PHLD + colb] = __floats2half2_rn(p10, p11);
    }
    s0 += __shfl_xor_sync(0xffffffffu, s0, 1);
    s0 += __shfl_xor_sync(0xffffffffu, s0, 2);
    s1 += __shfl_xor_sync(0xffffffffu, s1, 1);
    s1 += __shfl_xor_sync(0xffffffffu, s1, 2);
    if (lc == 0) {
      pl[half_ * 64 + r0] = s0;
      pl[half_ * 64 + r1] = s1;
    }
#pragma unroll
    for (int nq = 0; nq < 8; nq++) {
      const int qc = nq * 8 + 2 * lc;
      const float a0 = row_a[qc];
      const float a1 = row_a[qc + 1];
#pragma unroll
      for (int mt2 = 0; mt2 < 2; mt2++) {
        oacc[mt2][nq][0] *= a0;
        oacc[mt2][nq][1] *= a1;
        oacc[mt2][nq][2] *= a0;
        oacc[mt2][nq][3] *= a1;
      }
    }
    __syncthreads();  // Ps/pl visible
    if (tid < 64) row_l[tid] = row_l[tid] * row_a[tid] + pl[tid] + pl[64 + tid];

    // ---- PV (transposed): V^T (A, trans ldmatrix) @ P^T (B) ----
#pragma unroll
    for (int kk = 0; kk < 4; kk++) {
      uint32_t av[2][4];
#pragma unroll
      for (int mt2 = 0; mt2 < 2; mt2++) {
        uint32_t r0v, r1v, r2v, r3v;
        LDMX4T(r0v, r1v, r2v, r3v,
               uV + ((kk * 16 + lrow) * QHLD + w * 32 + mt2 * 16 + lcol8) * 2);
        av[mt2][0] = r0v; av[mt2][1] = r2v;
        av[mt2][2] = r1v; av[mt2][3] = r3v;
      }
#pragma unroll
      for (int nq = 0; nq < 4; nq++) {
        uint32_t r0p, r1p, r2p, r3p;
        LDMX4(r0p, r1p, r2p, r3p,
              uP + ((nq * 16 + lrow) * PHLD + kk * 16 + lcol8) * 2);
        uint32_t b0[2] = {r0p, r2p}, b1[2] = {r1p, r3p};
        mma_f16(oacc[0][2 * nq], av[0], b0);
        mma_f16(oacc[0][2 * nq + 1], av[0], b1);
        mma_f16(oacc[1][2 * nq], av[1], b0);
        mma_f16(oacc[1][2 * nq + 1], av[1], b1);
      }
    }
  }

  // ---- epilogue: normalize, transpose via Qs (half), coalesced store ----
  __syncthreads();
#pragma unroll
  for (int nq = 0; nq < 8; nq++) {
    const int qc = nq * 8 + 2 * lc;
    const float il0 = 1.0f / row_l[qc];
    const float il1 = 1.0f / row_l[qc + 1];
#pragma unroll
    for (int mt2 = 0; mt2 < 2; mt2++) {
      const int d0 = w * 32 + mt2 * 16 + lr;
      Qs[qc * QHLD + d0] = __float2half(oacc[mt2][nq][0] * il0);
      Qs[(qc + 1) * QHLD + d0] = __float2half(oacc[mt2][nq][1] * il1);
      Qs[qc * QHLD + d0 + 8] = __float2half(oacc[mt2][nq][2] * il0);
      Qs[(qc + 1) * QHLD + d0 + 8] = __float2half(oacc[mt2][nq][3] * il1);
    }
  }
  __syncthreads();
  for (int i = tid; i < 2048; i += 256) {
    int r = i >> 5, g = i & 31;
    uint4 u = *(uint4*)&Qs[r * QHLD + g * 8];
    *(uint4*)&g_oh[(((size_t)(b * S + q0 + r) * H + h) * D) + g * 8] = u;
  }
}

// ---------------- launch ----------------
extern "C" void kernel_launch(void* const* d_in, const int* in_sizes, int n_in,
                              void* d_out, int out_size) {
  const float* hs   = (const float*)d_in[0];
  const float* cosb = (const float*)d_in[1];
  const float* sinb = (const float*)d_in[2];
  const int*   am   = (const int*)d_in[3];
  const float* Wq   = (const float*)d_in[4];
  const float* Wk   = (const float*)d_in[5];
  const float* Wv   = (const float*)d_in[6];
  const float* Wo   = (const float*)d_in[7];
  const float* qw   = (const float*)d_in[8];
  const float* kw   = (const float*)d_in[9];
  float* out = (float*)d_out;

  float *qp, *kp, *vp;
  __half *hsh, *wqh, *wkh, *wvh, *woh, *vh, *oh;
  cudaGetSymbolAddress((void**)&qp, g_q);
  cudaGetSymbolAddress((void**)&kp, g_k);
  cudaGetSymbolAddress((void**)&vp, g_v);
  cudaGetSymbolAddress((void**)&hsh, g_hsh);
  cudaGetSymbolAddress((void**)&wqh, g_wqh);
  cudaGetSymbolAddress((void**)&wkh, g_wkh);
  cudaGetSymbolAddress((void**)&wvh, g_wvh);
  cudaGetSymbolAddress((void**)&woh, g_woh);
  cudaGetSymbolAddress((void**)&vh, g_vh);
  cudaGetSymbolAddress((void**)&oh, g_oh);

  const int M = B * S;  // 4096

  cudaFuncSetAttribute(gemm_fp16, cudaFuncAttributeMaxDynamicSharedMemorySize,
                       GEMMH_SMEM);
  cudaFuncSetAttribute(attn_f16, cudaFuncAttributeMaxDynamicSharedMemorySize,
                       ATTH_SMEM);

  // fp16 conversion passes
  cvt_half<<<2048, 256>>>((const float4*)hs, (uint2*)hsh, (B * S * E) / 4);
  cvt_half<<<1024, 256>>>((const float4*)Wq, (uint2*)wqh, (E * H * D) / 4);
  cvt_half<<<512, 256>>>((const float4*)Wk, (uint2*)wkh, (E * KV * D) / 4);
  cvt_half<<<512, 256>>>((const float4*)Wv, (uint2*)wvh, (E * KV * D) / 4);
  cvt_half<<<1024, 256>>>((const float4*)Wo, (uint2*)woh, (H * D * E) / 4);

  gemm_fp16<<<dim3((H * D) / 128, M / 128), 256, GEMMH_SMEM>>>(hsh, wqh, qp, M, H * D, E);
  gemm_fp16<<<dim3((KV * D) / 128, M / 128), 256, GEMMH_SMEM>>>(hsh, wkh, kp, M, KV * D, E);
  gemm_fp16<<<dim3((KV * D) / 128, M / 128), 256, GEMMH_SMEM>>>(hsh, wvh, vp, M, KV * D, E);

  cvt_half<<<512, 256>>>((const float4*)vp, (uint2*)vh, (B * S * KV * D) / 4);
  norm_rope<<<dim3(M, H + KV), 256>>>(cosb, sinb, qw, kw);

  attn_f16<<<dim3(S / 64, H, B), 256, ATTH_SMEM>>>(am);

  gemm_fp16<<<dim3(E / 128, M / 128), 256, GEMMH_SMEM>>>(oh, woh, out, M, E, E);
}

// round 9
// speedup vs baseline: 29.3056x; 1.1589x over previous
#include <cuda_runtime.h>
#include <cuda_fp16.h>
#include <math.h>
#include <stdint.h>

#define B 2
#define S 2048
#define E 2048
#define H 8
#define KV 4
#define D 256
#define WIN 1024
#define EPS 1e-6f

// ---------------- scratch (device globals; no allocation) ----------------
__device__ __half g_hsh[(size_t)B * S * E];        // 16 MB fp16 hidden
__device__ __half g_wqkvh[(size_t)E * 4096];       // 16 MB packed Wq|Wk|Wv
__device__ __half g_woh[(size_t)H * D * E];        // 8 MB
__device__ __half g_qkvh[(size_t)B * S * 4096];    // 32 MB packed q|k|v
__device__ __half g_oh[(size_t)B * S * H * D];     // 16 MB attn out

// packed column offsets (halves)
#define QOFF 0
#define KOFF 2048
#define VOFF 3072
#define PSTR 4096

// ======================= helpers =========================================
__device__ __forceinline__ uint32_t smem_u32(const void* p) {
  uint32_t a;
  asm("{ .reg .u64 t; cvta.to.shared.u64 t, %1; cvt.u32.u64 %0, t; }"
      : "=r"(a) : "l"(p));
  return a;
}
__device__ __forceinline__ void cpasync16(uint32_t dst, const void* src) {
  asm volatile("cp.async.cg.shared.global [%0], [%1], 16;"
               :: "r"(dst), "l"(src));
}
#define CP_COMMIT() asm volatile("cp.async.commit_group;" ::: "memory")
#define CP_WAIT1() asm volatile("cp.async.wait_group 1;" ::: "memory")
#define CP_WAIT0() asm volatile("cp.async.wait_group 0;" ::: "memory")

__device__ __forceinline__ void mma_f16(float* d, const uint32_t* a,
                                        const uint32_t* b) {
  asm volatile(
      "mma.sync.aligned.m16n8k16.row.col.f32.f16.f16.f32 "
      "{%0,%1,%2,%3},{%4,%5,%6,%7},{%8,%9},{%0,%1,%2,%3};"
      : "+f"(d[0]), "+f"(d[1]), "+f"(d[2]), "+f"(d[3])
      : "r"(a[0]), "r"(a[1]), "r"(a[2]), "r"(a[3]), "r"(b[0]), "r"(b[1]));
}
#define LDMX4(r0, r1, r2, r3, addr)                                        \
  asm volatile("ldmatrix.sync.aligned.m8n8.x4.shared.b16 {%0,%1,%2,%3}, [%4];" \
               : "=r"(r0), "=r"(r1), "=r"(r2), "=r"(r3) : "r"(addr))
#define LDMX4T(r0, r1, r2, r3, addr)                                       \
  asm volatile("ldmatrix.sync.aligned.m8n8.x4.trans.shared.b16 {%0,%1,%2,%3}, [%4];" \
               : "=r"(r0), "=r"(r1), "=r"(r2), "=r"(r3) : "r"(addr))

// ---------------- fp32 -> fp16 conversion passes --------------------------
__global__ __launch_bounds__(256) void cvt_half(const float4* __restrict__ s,
                                                uint2* __restrict__ d, int n4) {
  int i = blockIdx.x * blockDim.x + threadIdx.x;
  const int stride = gridDim.x * blockDim.x;
  for (; i < n4; i += stride) {
    float4 v = s[i];
    __half2 h0 = __floats2half2_rn(v.x, v.y);
    __half2 h1 = __floats2half2_rn(v.z, v.w);
    uint2 u;
    u.x = *reinterpret_cast<uint32_t*>(&h0);
    u.y = *reinterpret_cast<uint32_t*>(&h1);
    d[i] = u;
  }
}
// strided: scatter [rows][cols] fp32 into packed fp16 at colOff, stride PSTR
__global__ __launch_bounds__(256) void cvt_wpack(const float4* __restrict__ s,
                                                 __half* __restrict__ d,
                                                 int n4, int cols4, int colOff) {
  int i = blockIdx.x * blockDim.x + threadIdx.x;
  const int stride = gridDim.x * blockDim.x;
  for (; i < n4; i += stride) {
    float4 v = s[i];
    int row = i / cols4, c4 = i - row * cols4;
    __half2 h0 = __floats2half2_rn(v.x, v.y);
    __half2 h1 = __floats2half2_rn(v.z, v.w);
    uint2 u;
    u.x = *reinterpret_cast<uint32_t*>(&h0);
    u.y = *reinterpret_cast<uint32_t*>(&h1);
    *(uint2*)&d[(size_t)row * PSTR + colOff + c4 * 4] = u;
  }
}

// ========= fp16 mma GEMM (cp.async 3-stage + ldmatrix, BK=64) ============
#define AH_LD 72                      // 64 + 8 pad halves
#define BH_LD 136                     // 128 + 8 pad halves
#define ASTG_B (128 * AH_LD * 2)      // 18432 B
#define BSTG_B (64 * BH_LD * 2)       // 17408 B
#define GEMMH_SMEM (3 * (ASTG_B + BSTG_B))

template <typename OutT>
__global__ __launch_bounds__(256, 2) void gemm_f16(
    const __half* __restrict__ A, const __half* __restrict__ Bw,
    OutT* __restrict__ C, int M, int N, int K) {
  extern __shared__ char smc[];
  const uint32_t smbA = smem_u32(smc);
  const uint32_t smbB = smbA + 3 * ASTG_B;

  const int tid = threadIdx.x;
  const int lane = tid & 31;
  const int wid = tid >> 5;
  const int bm = blockIdx.y * 128;
  const int bn = blockIdx.x * 128;
  const int wm = (wid & 3) * 32;
  const int wn = (wid >> 2) * 64;

  // cp.async bases: A rows tid>>3 (+32i), granule tid&7; B rows tid>>4 (+16i)
  const __half* aP0 = A + (size_t)(bm + (tid >> 3)) * K + (tid & 7) * 8;
  const __half* bP0 = Bw + (size_t)(tid >> 4) * N + bn + (tid & 15) * 8;
  const uint32_t aS0 = smbA + ((tid >> 3) * AH_LD + (tid & 7) * 8) * 2;
  const uint32_t bS0 = smbB + ((tid >> 4) * BH_LD + (tid & 15) * 8) * 2;
  const int NC = K >> 6;

#define ISSUE_H(st, c)                                                       \
  do {                                                                       \
    _Pragma("unroll") for (int _i = 0; _i < 4; _i++) {                       \
      cpasync16(aS0 + (st) * ASTG_B + _i * (32 * AH_LD * 2),                 \
                aP0 + (c) * 64 + (size_t)_i * 32 * K);                       \
      cpasync16(bS0 + (st) * BSTG_B + _i * (16 * BH_LD * 2),                 \
                bP0 + (size_t)(c) * 64 * N + (size_t)_i * 16 * N);           \
    }                                                                        \
  } while (0)

  const int lrow = lane & 15;
  const int lcol8 = (lane >> 4) * 8;
  const uint32_t aAddr0 = smbA + ((wm + lrow) * AH_LD + lcol8) * 2;
  const uint32_t aAddr1 = smbA + ((wm + 16 + lrow) * AH_LD + lcol8) * 2;
  uint32_t bAddr[4];
#pragma unroll
  for (int nb = 0; nb < 4; nb++)
    bAddr[nb] = smbB + (lrow * BH_LD + wn + nb * 16 + lcol8) * 2;

  ISSUE_H(0, 0); CP_COMMIT();
  ISSUE_H(1, 1); CP_COMMIT();

  float acc[2][8][4] = {};

  for (int c = 0; c < NC; c++) {
    if (c + 1 < NC) CP_WAIT1(); else CP_WAIT0();
    __syncthreads();
    if (c + 2 < NC) {
      ISSUE_H((c + 2) % 3, c + 2);
      CP_COMMIT();
    }
    const uint32_t aSt = (c % 3) * ASTG_B;
    const uint32_t bSt = (c % 3) * BSTG_B;
#pragma unroll
    for (int ks = 0; ks < 4; ks++) {
      uint32_t af[2][4], bf[8][2];
      LDMX4(af[0][0], af[0][1], af[0][2], af[0][3], aAddr0 + aSt + ks * 32);
      LDMX4(af[1][0], af[1][1], af[1][2], af[1][3], aAddr1 + aSt + ks * 32);
#pragma unroll
      for (int nb = 0; nb < 4; nb++) {
        uint32_t r0, r1, r2, r3;
        LDMX4T(r0, r1, r2, r3, bAddr[nb] + bSt + ks * (16 * BH_LD * 2));
        bf[2 * nb][0] = r0; bf[2 * nb][1] = r1;
        bf[2 * nb + 1][0] = r2; bf[2 * nb + 1][1] = r3;
      }
#pragma unroll
      for (int mf = 0; mf < 2; mf++)
#pragma unroll
        for (int nf = 0; nf < 8; nf++)
          mma_f16(acc[mf][nf], af[mf], bf[nf]);
    }
  }

#pragma unroll
  for (int mf = 0; mf < 2; mf++) {
    const int r0 = bm + wm + mf * 16 + (lane >> 2);
#pragma unroll
    for (int nf = 0; nf < 8; nf++) {
      const int col = bn + wn + nf * 8 + 2 * (lane & 3);
      if constexpr (sizeof(OutT) == 4) {
        float2 v0, v1;
        v0.x = acc[mf][nf][0]; v0.y = acc[mf][nf][1];
        v1.x = acc[mf][nf][2]; v1.y = acc[mf][nf][3];
        *(float2*)&C[(size_t)r0 * N + col] = v0;
        *(float2*)&C[(size_t)(r0 + 8) * N + col] = v1;
      } else {
        *(__half2*)&C[(size_t)r0 * N + col] =
            __floats2half2_rn(acc[mf][nf][0], acc[mf][nf][1]);
        *(__half2*)&C[(size_t)(r0 + 8) * N + col] =
            __floats2half2_rn(acc[mf][nf][2], acc[mf][nf][3]);
      }
    }
  }
}

// -------- fused RMSNorm + RoPE on packed fp16 (Q pre-scaled) -------------
__global__ __launch_bounds__(256) void norm_rope(
    const float* __restrict__ cosb, const float* __restrict__ sinb,
    const float* __restrict__ qw, const float* __restrict__ kw) {
  const int row = blockIdx.x;  // b*S + s
  const int hh = blockIdx.y;   // 0..H+KV-1
  const int d = threadIdx.x;
  __half* ptr;
  const float* w;
  float oscale;
  if (hh < H) {
    ptr = &g_qkvh[(size_t)row * PSTR + QOFF + hh * D];
    w = qw; oscale = 0.0625f;
  } else {
    ptr = &g_qkvh[(size_t)row * PSTR + KOFF + (hh - H) * D];
    w = kw; oscale = 1.0f;
  }
  float v = __half2float(ptr[d]);
  float ss = v * v;
#pragma unroll
  for (int o = 16; o > 0; o >>= 1) ss += __shfl_xor_sync(0xffffffffu, ss, o);
  __shared__ float red[8];
  __shared__ float xs[D];
  if ((d & 31) == 0) red[d >> 5] = ss;
  __syncthreads();
  float tot = 0.f;
#pragma unroll
  for (int i = 0; i < 8; i++) tot += red[i];
  float inv = rsqrtf(tot * (1.0f / D) + EPS);
  float xn = v * inv * (1.0f + w[d]);
  xs[d] = xn;
  __syncthreads();
  float rot = (d < D / 2) ? -xs[d + D / 2] : xs[d - D / 2];
  float xr = xn * cosb[(size_t)row * D + d] + rot * sinb[(size_t)row * D + d];
  ptr[d] = __float2half(xr * oscale);
}

// ============= fp16 mma flash attention (sliding window) =================
#define QHLD 264
#define PHLD 72
#define ATTH_SMEM 112640
#define NEGF (-1e30f)

__global__ __launch_bounds__(256, 2) void attn_f16(const int* __restrict__ am) {
  extern __shared__ char smc[];
  __half* Qs = (__half*)smc;            // [64][QHLD]
  __half* Ks = Qs + 64 * QHLD;
  __half* Vs = Ks + 64 * QHLD;
  __half* Ps = Vs + 64 * QHLD;          // [64][PHLD]
  float* row_m = (float*)(smc + 110592);
  float* row_l = row_m + 64;
  float* row_a = row_l + 64;
  float* pm = row_a + 64;
  float* pl = pm + 128;
  int* ams = (int*)(pl + 128);

  const uint32_t uQ = smem_u32(Qs);
  const uint32_t uK = smem_u32(Ks);
  const uint32_t uV = smem_u32(Vs);
  const uint32_t uP = smem_u32(Ps);

  const int tid = threadIdx.x;
  const int lane = tid & 31;
  const int w = tid >> 5;
  const int mt = w & 3;
  const int half_ = w >> 2;
  const int lr = lane >> 2;
  const int lc = lane & 3;
  const int lrow = lane & 15;
  const int lcol8 = (lane >> 4) * 8;

  const int q0 = blockIdx.x * 64;
  const int h = blockIdx.y;
  const int b = blockIdx.z;
  const int hk = h / (H / KV);

  {
    const __half* qsrc = g_qkvh + (size_t)(b * S + q0) * PSTR + QOFF + h * D;
    for (int i = tid; i < 2048; i += 256) {
      int r = i >> 5, g = i & 31;
      cpasync16(uQ + (r * QHLD + g * 8) * 2, qsrc + (size_t)r * PSTR + g * 8);
    }
    CP_COMMIT();
  }
  if (tid < 64) {
    row_m[tid] = NEGF;
    row_l[tid] = 0.f;
  }

  float oacc[2][8][4] = {};

  int kb0 = q0 - (WIN - 1);
  if (kb0 < 0) kb0 = 0;
  kb0 &= ~63;
  const int kb_end = q0 + 63;

  for (int kb = kb0; kb <= kb_end; kb += 64) {
    __syncthreads();
    {
      const __half* ksrc = g_qkvh + (size_t)(b * S + kb) * PSTR + KOFF + hk * D;
      const __half* vsrc = g_qkvh + (size_t)(b * S + kb) * PSTR + VOFF + hk * D;
      for (int i = tid; i < 2048; i += 256) {
        int r = i >> 5, g = i & 31;
        size_t so = (size_t)r * PSTR + g * 8;
        uint32_t doff = (r * QHLD + g * 8) * 2;
        cpasync16(uK + doff, ksrc + so);
        cpasync16(uV + doff, vsrc + so);
      }
      CP_COMMIT();
    }
    if (tid < 64) ams[tid] = am[b * S + kb + tid];
    CP_WAIT0();
    __syncthreads();

    // ---- QK^T ----
    float sacc[4][4] = {};
    const uint32_t qa = uQ + ((mt * 16 + lrow) * QHLD + lcol8) * 2;
    const uint32_t ka0 = uK + ((half_ * 32 + lrow) * QHLD + lcol8) * 2;
    const uint32_t ka1 = ka0 + 16 * QHLD * 2;
#pragma unroll
    for (int ks = 0; ks < 16; ks++) {
      uint32_t a[4], r0, r1, r2, r3;
      LDMX4(a[0], a[1], a[2], a[3], qa + ks * 32);
      LDMX4(r0, r1, r2, r3, ka0 + ks * 32);
      {
        uint32_t b0[2] = {r0, r2}, b1[2] = {r1, r3};
        mma_f16(sacc[0], a, b0);
        mma_f16(sacc[1], a, b1);
      }
      LDMX4(r0, r1, r2, r3, ka1 + ks * 32);
      {
        uint32_t b0[2] = {r0, r2}, b1[2] = {r1, r3};
        mma_f16(sacc[2], a, b0);
        mma_f16(sacc[3], a, b1);
      }
    }

    // ---- mask + partial row max ----
    const int r0 = mt * 16 + lr;
    const int r1 = r0 + 8;
    const int qg0 = q0 + r0;
    const int qg1 = q0 + r1;
    float mx0 = NEGF, mx1 = NEGF;
#pragma unroll
    for (int nt = 0; nt < 4; nt++) {
      const int colb = half_ * 32 + nt * 8 + 2 * lc;
#pragma unroll
      for (int j = 0; j < 4; j++) {
        const int col = colb + (j & 1);
        const int kg = kb + col;
        const int qg = (j < 2) ? qg0 : qg1;
        bool ok = (kg <= qg) && (qg - kg < WIN) && (ams[col] != 0);
        float v = ok ? sacc[nt][j] : NEGF;
        sacc[nt][j] = v;
        if (j < 2) mx0 = fmaxf(mx0, v);
        else       mx1 = fmaxf(mx1, v);
      }
    }
    mx0 = fmaxf(mx0, __shfl_xor_sync(0xffffffffu, mx0, 1));
    mx0 = fmaxf(mx0, __shfl_xor_sync(0xffffffffu, mx0, 2));
    mx1 = fmaxf(mx1, __shfl_xor_sync(0xffffffffu, mx1, 1));
    mx1 = fmaxf(mx1, __shfl_xor_sync(0xffffffffu, mx1, 2));
    if (lc == 0) {
      pm[half_ * 64 + r0] = mx0;
      pm[half_ * 64 + r1] = mx1;
    }
    __syncthreads();
    if (tid < 64) {
      float mn = fmaxf(row_m[tid], fmaxf(pm[tid], pm[64 + tid]));
      row_a[tid] = __expf(row_m[tid] - mn);
      row_m[tid] = mn;
    }
    __syncthreads();

    // ---- P = exp(s-m) -> fp16; sums; rescale oacc ----
    const float mn0 = row_m[r0];
    const float mn1 = row_m[r1];
    float s0 = 0.f, s1 = 0.f;
#pragma unroll
    for (int nt = 0; nt < 4; nt++) {
      const int colb = half_ * 32 + nt * 8 + 2 * lc;
      float p00 = (sacc[nt][0] < -5e29f) ? 0.f : __expf(sacc[nt][0] - mn0);
      float p01 = (sacc[nt][1] < -5e29f) ? 0.f : __expf(sacc[nt][1] - mn0);
      float p10 = (sacc[nt][2] < -5e29f) ? 0.f : __expf(sacc[nt][2] - mn1);
      float p11 = (sacc[nt][3] < -5e29f) ? 0.f : __expf(sacc[nt][3] - mn1);
      s0 += p00 + p01;
      s1 += p10 + p11;
      *(__half2*)&Ps[r0 * PHLD + colb] = __floats2half2_rn(p00, p01);
      *(__half2*)&Ps[r1 * PHLD + colb] = __floats2half2_rn(p10, p11);
    }
    s0 += __shfl_xor_sync(0xffffffffu, s0, 1);
    s0 += __shfl_xor_sync(0xffffffffu, s0, 2);
    s1 += __shfl_xor_sync(0xffffffffu, s1, 1);
    s1 += __shfl_xor_sync(0xffffffffu, s1, 2);
    if (lc == 0) {
      pl[half_ * 64 + r0] = s0;
      pl[half_ * 64 + r1] = s1;
    }
#pragma unroll
    for (int nq = 0; nq < 8; nq++) {
      const int qc = nq * 8 + 2 * lc;
      const float a0 = row_a[qc];
      const float a1 = row_a[qc + 1];
#pragma unroll
      for (int mt2 = 0; mt2 < 2; mt2++) {
        oacc[mt2][nq][0] *= a0;
        oacc[mt2][nq][1] *= a1;
        oacc[mt2][nq][2] *= a0;
        oacc[mt2][nq][3] *= a1;
      }
    }
    __syncthreads();
    if (tid < 64) row_l[tid] = row_l[tid] * row_a[tid] + pl[tid] + pl[64 + tid];

    // ---- PV (transposed) ----
#pragma unroll
    for (int kk = 0; kk < 4; kk++) {
      uint32_t av[2][4];
#pragma unroll
      for (int mt2 = 0; mt2 < 2; mt2++) {
        uint32_t r0v, r1v, r2v, r3v;
        LDMX4T(r0v, r1v, r2v, r3v,
               uV + ((kk * 16 + lrow) * QHLD + w * 32 + mt2 * 16 + lcol8) * 2);
        av[mt2][0] = r0v; av[mt2][1] = r2v;
        av[mt2][2] = r1v; av[mt2][3] = r3v;
      }
#pragma unroll
      for (int nq = 0; nq < 4; nq++) {
        uint32_t r0p, r1p, r2p, r3p;
        LDMX4(r0p, r1p, r2p, r3p,
              uP + ((nq * 16 + lrow) * PHLD + kk * 16 + lcol8) * 2);
        uint32_t b0[2] = {r0p, r2p}, b1[2] = {r1p, r3p};
        mma_f16(oacc[0][2 * nq], av[0], b0);
        mma_f16(oacc[0][2 * nq + 1], av[0], b1);
        mma_f16(oacc[1][2 * nq], av[1], b0);
        mma_f16(oacc[1][2 * nq + 1], av[1], b1);
      }
    }
  }

  // ---- epilogue ----
  __syncthreads();
#pragma unroll
  for (int nq = 0; nq < 8; nq++) {
    const int qc = nq * 8 + 2 * lc;
    const float il0 = 1.0f / row_l[qc];
    const float il1 = 1.0f / row_l[qc + 1];
#pragma unroll
    for (int mt2 = 0; mt2 < 2; mt2++) {
      const int d0 = w * 32 + mt2 * 16 + lr;
      Qs[qc * QHLD + d0] = __float2half(oacc[mt2][nq][0] * il0);
      Qs[(qc + 1) * QHLD + d0] = __float2half(oacc[mt2][nq][1] * il1);
      Qs[qc * QHLD + d0 + 8] = __float2half(oacc[mt2][nq][2] * il0);
      Qs[(qc + 1) * QHLD + d0 + 8] = __float2half(oacc[mt2][nq][3] * il1);
    }
  }
  __syncthreads();
  for (int i = tid; i < 2048; i += 256) {
    int r = i >> 5, g = i & 31;
    uint4 u = *(uint4*)&Qs[r * QHLD + g * 8];
    *(uint4*)&g_oh[(((size_t)(b * S + q0 + r) * H + h) * D) + g * 8] = u;
  }
}

// ---------------- launch ----------------
extern "C" void kernel_launch(void* const* d_in, const int* in_sizes, int n_in,
                              void* d_out, int out_size) {
  const float* hs   = (const float*)d_in[0];
  const float* cosb = (const float*)d_in[1];
  const float* sinb = (const float*)d_in[2];
  const int*   am   = (const int*)d_in[3];
  const float* Wq   = (const float*)d_in[4];
  const float* Wk   = (const float*)d_in[5];
  const float* Wv   = (const float*)d_in[6];
  const float* Wo   = (const float*)d_in[7];
  const float* qw   = (const float*)d_in[8];
  const float* kw   = (const float*)d_in[9];
  float* out = (float*)d_out;

  __half *hsh, *wqkvh, *woh, *qkvh, *oh;
  cudaGetSymbolAddress((void**)&hsh, g_hsh);
  cudaGetSymbolAddress((void**)&wqkvh, g_wqkvh);
  cudaGetSymbolAddress((void**)&woh, g_woh);
  cudaGetSymbolAddress((void**)&qkvh, g_qkvh);
  cudaGetSymbolAddress((void**)&oh, g_oh);

  const int M = B * S;  // 4096

  cudaFuncSetAttribute(gemm_f16<__half>,
                       cudaFuncAttributeMaxDynamicSharedMemorySize, GEMMH_SMEM);
  cudaFuncSetAttribute(gemm_f16<float>,
                       cudaFuncAttributeMaxDynamicSharedMemorySize, GEMMH_SMEM);
  cudaFuncSetAttribute(attn_f16, cudaFuncAttributeMaxDynamicSharedMemorySize,
                       ATTH_SMEM);

  // fp16 conversion / packing passes
  cvt_half<<<2048, 256>>>((const float4*)hs, (uint2*)hsh, (B * S * E) / 4);
  cvt_half<<<1024, 256>>>((const float4*)Wo, (uint2*)woh, (H * D * E) / 4);
  cvt_wpack<<<1024, 256>>>((const float4*)Wq, wqkvh, (E * H * D) / 4,
                           (H * D) / 4, QOFF);
  cvt_wpack<<<512, 256>>>((const float4*)Wk, wqkvh, (E * KV * D) / 4,
                          (KV * D) / 4, KOFF);
  cvt_wpack<<<512, 256>>>((const float4*)Wv, wqkvh, (E * KV * D) / 4,
                          (KV * D) / 4, VOFF);

  // fused QKV projection (N = 4096), fp16 out
  gemm_f16<__half><<<dim3(4096 / 128, M / 128), 256, GEMMH_SMEM>>>(
      hsh, wqkvh, qkvh, M, 4096, E);

  norm_rope<<<dim3(M, H + KV), 256>>>(cosb, sinb, qw, kw);

  attn_f16<<<dim3(S / 64, H, B), 256, ATTH_SMEM>>>(am);

  gemm_f16<float><<<dim3(E / 128, M / 128), 256, GEMMH_SMEM>>>(
      oh, woh, out, M, E, E);
}

// round 10
// speedup vs baseline: 29.7510x; 1.0152x over previous
#include <cuda_runtime.h>
#include <cuda_fp16.h>
#include <math.h>
#include <stdint.h>

#define B 2
#define S 2048
#define E 2048
#define H 8
#define KV 4
#define D 256
#define WIN 1024
#define EPS 1e-6f

// ---------------- scratch (device globals; no allocation) ----------------
__device__ __half g_hsh[(size_t)B * S * E];        // 16 MB fp16 hidden
__device__ __half g_wqkvh[(size_t)E * 4096];       // 16 MB packed Wq|Wk|Wv
__device__ __half g_woh[(size_t)H * D * E];        // 8 MB
__device__ __half g_qkvh[(size_t)B * S * 4096];    // 32 MB packed q|k|v
__device__ __half g_oh[(size_t)B * S * H * D];     // 16 MB attn out

// packed column offsets (halves)
#define QOFF 0
#define KOFF 2048
#define VOFF 3072
#define PSTR 4096

// ======================= helpers =========================================
__device__ __forceinline__ uint32_t smem_u32(const void* p) {
  uint32_t a;
  asm("{ .reg .u64 t; cvta.to.shared.u64 t, %1; cvt.u32.u64 %0, t; }"
      : "=r"(a) : "l"(p));
  return a;
}
__device__ __forceinline__ void cpasync16(uint32_t dst, const void* src) {
  asm volatile("cp.async.cg.shared.global [%0], [%1], 16;"
               :: "r"(dst), "l"(src));
}
#define CP_COMMIT() asm volatile("cp.async.commit_group;" ::: "memory")
#define CP_WAIT1() asm volatile("cp.async.wait_group 1;" ::: "memory")
#define CP_WAIT0() asm volatile("cp.async.wait_group 0;" ::: "memory")

__device__ __forceinline__ void mma_f16(float* d, const uint32_t* a,
                                        const uint32_t* b) {
  asm volatile(
      "mma.sync.aligned.m16n8k16.row.col.f32.f16.f16.f32 "
      "{%0,%1,%2,%3},{%4,%5,%6,%7},{%8,%9},{%0,%1,%2,%3};"
      : "+f"(d[0]), "+f"(d[1]), "+f"(d[2]), "+f"(d[3])
      : "r"(a[0]), "r"(a[1]), "r"(a[2]), "r"(a[3]), "r"(b[0]), "r"(b[1]));
}
#define LDMX4(r0, r1, r2, r3, addr)                                        \
  asm volatile("ldmatrix.sync.aligned.m8n8.x4.shared.b16 {%0,%1,%2,%3}, [%4];" \
               : "=r"(r0), "=r"(r1), "=r"(r2), "=r"(r3) : "r"(addr))
#define LDMX4T(r0, r1, r2, r3, addr)                                       \
  asm volatile("ldmatrix.sync.aligned.m8n8.x4.trans.shared.b16 {%0,%1,%2,%3}, [%4];" \
               : "=r"(r0), "=r"(r1), "=r"(r2), "=r"(r3) : "r"(addr))

// ---------------- fp32 -> fp16 conversion passes --------------------------
__global__ __launch_bounds__(256) void cvt_half(const float4* __restrict__ s,
                                                uint2* __restrict__ d, int n4) {
  int i = blockIdx.x * blockDim.x + threadIdx.x;
  const int stride = gridDim.x * blockDim.x;
  for (; i < n4; i += stride) {
    float4 v = s[i];
    __half2 h0 = __floats2half2_rn(v.x, v.y);
    __half2 h1 = __floats2half2_rn(v.z, v.w);
    uint2 u;
    u.x = *reinterpret_cast<uint32_t*>(&h0);
    u.y = *reinterpret_cast<uint32_t*>(&h1);
    d[i] = u;
  }
}
// pack Wq|Wk|Wv (fp32) into g_wqkvh (fp16) in one pass.
// output granule g in [0,1024): cols [g*4, g*4+4) of the packed row.
__global__ __launch_bounds__(256) void cvt_packw(const float4* __restrict__ wq,
                                                 const float4* __restrict__ wk,
                                                 const float4* __restrict__ wv,
                                                 __half* __restrict__ d) {
  const int n = E * 1024;
  int i = blockIdx.x * blockDim.x + threadIdx.x;
  const int stride = gridDim.x * blockDim.x;
  for (; i < n; i += stride) {
    int row = i >> 10, g = i & 1023;
    float4 v;
    if (g < 512)       v = wq[(size_t)row * 512 + g];
    else if (g < 768)  v = wk[(size_t)row * 256 + (g - 512)];
    else               v = wv[(size_t)row * 256 + (g - 768)];
    __half2 h0 = __floats2half2_rn(v.x, v.y);
    __half2 h1 = __floats2half2_rn(v.z, v.w);
    uint2 u;
    u.x = *reinterpret_cast<uint32_t*>(&h0);
    u.y = *reinterpret_cast<uint32_t*>(&h1);
    *(uint2*)&d[(size_t)row * PSTR + g * 4] = u;
  }
}

// ========= fp16 mma GEMM (cp.async 3-stage + ldmatrix, BK=64) ============
#define AH_LD 72
#define BH_LD 136
#define ASTG_B (128 * AH_LD * 2)
#define BSTG_B (64 * BH_LD * 2)
#define GEMMH_SMEM (3 * (ASTG_B + BSTG_B))

template <typename OutT>
__global__ __launch_bounds__(256, 2) void gemm_f16(
    const __half* __restrict__ A, const __half* __restrict__ Bw,
    OutT* __restrict__ C, int M, int N, int K) {
  extern __shared__ char smc[];
  const uint32_t smbA = smem_u32(smc);
  const uint32_t smbB = smbA + 3 * ASTG_B;

  const int tid = threadIdx.x;
  const int lane = tid & 31;
  const int wid = tid >> 5;
  const int bm = blockIdx.y * 128;
  const int bn = blockIdx.x * 128;
  const int wm = (wid & 3) * 32;
  const int wn = (wid >> 2) * 64;

  const __half* aP0 = A + (size_t)(bm + (tid >> 3)) * K + (tid & 7) * 8;
  const __half* bP0 = Bw + (size_t)(tid >> 4) * N + bn + (tid & 15) * 8;
  const uint32_t aS0 = smbA + ((tid >> 3) * AH_LD + (tid & 7) * 8) * 2;
  const uint32_t bS0 = smbB + ((tid >> 4) * BH_LD + (tid & 15) * 8) * 2;
  const int NC = K >> 6;

#define ISSUE_H(st, c)                                                       \
  do {                                                                       \
    _Pragma("unroll") for (int _i = 0; _i < 4; _i++) {                       \
      cpasync16(aS0 + (st) * ASTG_B + _i * (32 * AH_LD * 2),                 \
                aP0 + (c) * 64 + (size_t)_i * 32 * K);                       \
      cpasync16(bS0 + (st) * BSTG_B + _i * (16 * BH_LD * 2),                 \
                bP0 + (size_t)(c) * 64 * N + (size_t)_i * 16 * N);           \
    }                                                                        \
  } while (0)

  const int lrow = lane & 15;
  const int lcol8 = (lane >> 4) * 8;
  const uint32_t aAddr0 = smbA + ((wm + lrow) * AH_LD + lcol8) * 2;
  const uint32_t aAddr1 = smbA + ((wm + 16 + lrow) * AH_LD + lcol8) * 2;
  uint32_t bAddr[4];
#pragma unroll
  for (int nb = 0; nb < 4; nb++)
    bAddr[nb] = smbB + (lrow * BH_LD + wn + nb * 16 + lcol8) * 2;

  ISSUE_H(0, 0); CP_COMMIT();
  ISSUE_H(1, 1); CP_COMMIT();

  float acc[2][8][4] = {};

  for (int c = 0; c < NC; c++) {
    if (c + 1 < NC) CP_WAIT1(); else CP_WAIT0();
    __syncthreads();
    if (c + 2 < NC) {
      ISSUE_H((c + 2) % 3, c + 2);
      CP_COMMIT();
    }
    const uint32_t aSt = (c % 3) * ASTG_B;
    const uint32_t bSt = (c % 3) * BSTG_B;
#pragma unroll
    for (int ks = 0; ks < 4; ks++) {
      uint32_t af[2][4], bf[8][2];
      LDMX4(af[0][0], af[0][1], af[0][2], af[0][3], aAddr0 + aSt + ks * 32);
      LDMX4(af[1][0], af[1][1], af[1][2], af[1][3], aAddr1 + aSt + ks * 32);
#pragma unroll
      for (int nb = 0; nb < 4; nb++) {
        uint32_t r0, r1, r2, r3;
        LDMX4T(r0, r1, r2, r3, bAddr[nb] + bSt + ks * (16 * BH_LD * 2));
        bf[2 * nb][0] = r0; bf[2 * nb][1] = r1;
        bf[2 * nb + 1][0] = r2; bf[2 * nb + 1][1] = r3;
      }
#pragma unroll
      for (int mf = 0; mf < 2; mf++)
#pragma unroll
        for (int nf = 0; nf < 8; nf++)
          mma_f16(acc[mf][nf], af[mf], bf[nf]);
    }
  }

#pragma unroll
  for (int mf = 0; mf < 2; mf++) {
    const int r0 = bm + wm + mf * 16 + (lane >> 2);
#pragma unroll
    for (int nf = 0; nf < 8; nf++) {
      const int col = bn + wn + nf * 8 + 2 * (lane & 3);
      if constexpr (sizeof(OutT) == 4) {
        float2 v0, v1;
        v0.x = acc[mf][nf][0]; v0.y = acc[mf][nf][1];
        v1.x = acc[mf][nf][2]; v1.y = acc[mf][nf][3];
        *(float2*)&C[(size_t)r0 * N + col] = v0;
        *(float2*)&C[(size_t)(r0 + 8) * N + col] = v1;
      } else {
        *(__half2*)&C[(size_t)r0 * N + col] =
            __floats2half2_rn(acc[mf][nf][0], acc[mf][nf][1]);
        *(__half2*)&C[(size_t)(r0 + 8) * N + col] =
            __floats2half2_rn(acc[mf][nf][2], acc[mf][nf][3]);
      }
    }
  }
}

// -------- fused RMSNorm + RoPE: one block per token row, loop heads ------
__global__ __launch_bounds__(256) void norm_rope2(
    const float* __restrict__ cosb, const float* __restrict__ sinb,
    const float* __restrict__ qw, const float* __restrict__ kw) {
  const int row = blockIdx.x;  // b*S + s
  const int d = threadIdx.x;
  __shared__ float cs[D], sn[D], xs[D], red[8];
  cs[d] = cosb[(size_t)row * D + d];
  sn[d] = sinb[(size_t)row * D + d];
  const float wqv = qw[d];
  const float wkv = kw[d];
  __half* base = &g_qkvh[(size_t)row * PSTR];
#pragma unroll
  for (int hh = 0; hh < H + KV; hh++) {
    __half* ptr = (hh < H) ? (base + QOFF + hh * D)
                           : (base + KOFF + (hh - H) * D);
    const float w = (hh < H) ? wqv : wkv;
    const float osc = (hh < H) ? 0.0625f : 1.0f;
    float v = __half2float(ptr[d]);
    float ss = v * v;
#pragma unroll
    for (int o = 16; o > 0; o >>= 1) ss += __shfl_xor_sync(0xffffffffu, ss, o);
    if ((d & 31) == 0) red[d >> 5] = ss;
    __syncthreads();
    float tot = 0.f;
#pragma unroll
    for (int i = 0; i < 8; i++) tot += red[i];
    float inv = rsqrtf(tot * (1.0f / D) + EPS);
    float xn = v * inv * (1.0f + w);
    xs[d] = xn;
    __syncthreads();
    float rot = (d < D / 2) ? -xs[d + D / 2] : xs[d - D / 2];
    ptr[d] = __float2half((xn * cs[d] + rot * sn[d]) * osc);
    __syncthreads();  // red/xs reuse next head
  }
}

// ============= fp16 mma flash attention (sliding window) =================
#define QHLD 264
#define PHLD 72
#define ATTH_SMEM 112640
#define NEGF (-1e30f)

__global__ __launch_bounds__(256, 2) void attn_f16(const int* __restrict__ am) {
  extern __shared__ char smc[];
  __half* Qs = (__half*)smc;            // [64][QHLD]
  __half* Ks = Qs + 64 * QHLD;
  __half* Vs = Ks + 64 * QHLD;
  __half* Ps = Vs + 64 * QHLD;          // [64][PHLD]
  float* row_m = (float*)(smc + 110592);
  float* row_l = row_m + 64;
  float* row_a = row_l + 64;
  float* pm = row_a + 64;
  float* pl = pm + 128;
  int* ams = (int*)(pl + 128);

  const uint32_t uQ = smem_u32(Qs);
  const uint32_t uK = smem_u32(Ks);
  const uint32_t uV = smem_u32(Vs);
  const uint32_t uP = smem_u32(Ps);

  const int tid = threadIdx.x;
  const int lane = tid & 31;
  const int w = tid >> 5;
  const int mt = w & 3;
  const int half_ = w >> 2;
  const int lr = lane >> 2;
  const int lc = lane & 3;
  const int lrow = lane & 15;
  const int lcol8 = (lane >> 4) * 8;

  const int q0 = blockIdx.x * 64;
  const int h = blockIdx.y;
  const int b = blockIdx.z;
  const int hk = h / (H / KV);

  {
    const __half* qsrc = g_qkvh + (size_t)(b * S + q0) * PSTR + QOFF + h * D;
    for (int i = tid; i < 2048; i += 256) {
      int r = i >> 5, g = i & 31;
      cpasync16(uQ + (r * QHLD + g * 8) * 2, qsrc + (size_t)r * PSTR + g * 8);
    }
    CP_COMMIT();
  }
  if (tid < 64) {
    row_m[tid] = NEGF;
    row_l[tid] = 0.f;
  }

  float oacc[2][8][4] = {};

  int kb0 = q0 - (WIN - 1);
  if (kb0 < 0) kb0 = 0;
  kb0 &= ~63;
  const int kb_end = q0 + 63;

  for (int kb = kb0; kb <= kb_end; kb += 64) {
    __syncthreads();  // prev iter's smem readers done
    {
      const __half* ksrc = g_qkvh + (size_t)(b * S + kb) * PSTR + KOFF + hk * D;
      for (int i = tid; i < 2048; i += 256) {
        int r = i >> 5, g = i & 31;
        cpasync16(uK + (r * QHLD + g * 8) * 2, ksrc + (size_t)r * PSTR + g * 8);
      }
      CP_COMMIT();  // K group
      const __half* vsrc = g_qkvh + (size_t)(b * S + kb) * PSTR + VOFF + hk * D;
      for (int i = tid; i < 2048; i += 256) {
        int r = i >> 5, g = i & 31;
        cpasync16(uV + (r * QHLD + g * 8) * 2, vsrc + (size_t)r * PSTR + g * 8);
      }
      CP_COMMIT();  // V group
    }
    if (tid < 64) ams[tid] = am[b * S + kb + tid];
    CP_WAIT1();       // Q (first iter) + K complete; V may be in flight
    __syncthreads();

    // ---- QK^T ----
    float sacc[4][4] = {};
    const uint32_t qa = uQ + ((mt * 16 + lrow) * QHLD + lcol8) * 2;
    const uint32_t ka0 = uK + ((half_ * 32 + lrow) * QHLD + lcol8) * 2;
    const uint32_t ka1 = ka0 + 16 * QHLD * 2;
#pragma unroll
    for (int ks = 0; ks < 16; ks++) {
      uint32_t a[4], r0, r1, r2, r3;
      LDMX4(a[0], a[1], a[2], a[3], qa + ks * 32);
      LDMX4(r0, r1, r2, r3, ka0 + ks * 32);
      {
        uint32_t b0[2] = {r0, r2}, b1[2] = {r1, r3};
        mma_f16(sacc[0], a, b0);
        mma_f16(sacc[1], a, b1);
      }
      LDMX4(r0, r1, r2, r3, ka1 + ks * 32);
      {
        uint32_t b0[2] = {r0, r2}, b1[2] = {r1, r3};
        mma_f16(sacc[2], a, b0);
        mma_f16(sacc[3], a, b1);
      }
    }

    // ---- mask + partial row max ----
    const int r0 = mt * 16 + lr;
    const int r1 = r0 + 8;
    const int qg0 = q0 + r0;
    const int qg1 = q0 + r1;
    float mx0 = NEGF, mx1 = NEGF;
#pragma unroll
    for (int nt = 0; nt < 4; nt++) {
      const int colb = half_ * 32 + nt * 8 + 2 * lc;
#pragma unroll
      for (int j = 0; j < 4; j++) {
        const int col = colb + (j & 1);
        const int kg = kb + col;
        const int qg = (j < 2) ? qg0 : qg1;
        bool ok = (kg <= qg) && (qg - kg < WIN) && (ams[col] != 0);
        float v = ok ? sacc[nt][j] : NEGF;
        sacc[nt][j] = v;
        if (j < 2) mx0 = fmaxf(mx0, v);
        else       mx1 = fmaxf(mx1, v);
      }
    }
    mx0 = fmaxf(mx0, __shfl_xor_sync(0xffffffffu, mx0, 1));
    mx0 = fmaxf(mx0, __shfl_xor_sync(0xffffffffu, mx0, 2));
    mx1 = fmaxf(mx1, __shfl_xor_sync(0xffffffffu, mx1, 1));
    mx1 = fmaxf(mx1, __shfl_xor_sync(0xffffffffu, mx1, 2));
    if (lc == 0) {
      pm[half_ * 64 + r0] = mx0;
      pm[half_ * 64 + r1] = mx1;
    }
    __syncthreads();
    if (tid < 64) {
      float mn = fmaxf(row_m[tid], fmaxf(pm[tid], pm[64 + tid]));
      row_a[tid] = __expf(row_m[tid] - mn);
      row_m[tid] = mn;
    }
    __syncthreads();

    // ---- P = exp(s-m) -> fp16; sums; rescale oacc ----
    const float mn0 = row_m[r0];
    const float mn1 = row_m[r1];
    float s0 = 0.f, s1 = 0.f;
#pragma unroll
    for (int nt = 0; nt < 4; nt++) {
      const int colb = half_ * 32 + nt * 8 + 2 * lc;
      float p00 = (sacc[nt][0] < -5e29f) ? 0.f : __expf(sacc[nt][0] - mn0);
      float p01 = (sacc[nt][1] < -5e29f) ? 0.f : __expf(sacc[nt][1] - mn0);
      float p10 = (sacc[nt][2] < -5e29f) ? 0.f : __expf(sacc[nt][2] - mn1);
      float p11 = (sacc[nt][3] < -5e29f) ? 0.f : __expf(sacc[nt][3] - mn1);
      s0 += p00 + p01;
      s1 += p10 + p11;
      *(__half2*)&Ps[r0 * PHLD + colb] = __floats2half2_rn(p00, p01);
      *(__half2*)&Ps[r1 * PHLD + colb] = __floats2half2_rn(p10, p11);
    }
    s0 += __shfl_xor_sync(0xffffffffu, s0, 1);
    s0 += __shfl_xor_sync(0xffffffffu, s0, 2);
    s1 += __shfl_xor_sync(0xffffffffu, s1, 1);
    s1 += __shfl_xor_sync(0xffffffffu, s1, 2);
    if (lc == 0) {
      pl[half_ * 64 + r0] = s0;
      pl[half_ * 64 + r1] = s1;
    }
#pragma unroll
    for (int nq = 0; nq < 8; nq++) {
      const int qc = nq * 8 + 2 * lc;
      const float a0 = row_a[qc];
      const float a1 = row_a[qc + 1];
#pragma unroll
      for (int mt2 = 0; mt2 < 2; mt2++) {
        oacc[mt2][nq][0] *= a0;
        oacc[mt2][nq][1] *= a1;
        oacc[mt2][nq][2] *= a0;
        oacc[mt2][nq][3] *= a1;
      }
    }
    CP_WAIT0();       // V complete
    __syncthreads();  // Ps/pl/V visible
    if (tid < 64) row_l[tid] = row_l[tid] * row_a[tid] + pl[tid] + pl[64 + tid];

    // ---- PV (transposed) ----
#pragma unroll
    for (int kk = 0; kk < 4; kk++) {
      uint32_t av[2][4];
#pragma unroll
      for (int mt2 = 0; mt2 < 2; mt2++) {
        uint32_t r0v, r1v, r2v, r3v;
        LDMX4T(r0v, r1v, r2v, r3v,
               uV + ((kk * 16 + lrow) * QHLD + w * 32 + mt2 * 16 + lcol8) * 2);
        av[mt2][0] = r0v; av[mt2][1] = r2v;
        av[mt2][2] = r1v; av[mt2][3] = r3v;
      }
#pragma unroll
      for (int nq = 0; nq < 4; nq++) {
        uint32_t r0p, r1p, r2p, r3p;
        LDMX4(r0p, r1p, r2p, r3p,
              uP + ((nq * 16 + lrow) * PHLD + kk * 16 + lcol8) * 2);
        uint32_t b0[2] = {r0p, r2p}, b1[2] = {r1p, r3p};
        mma_f16(oacc[0][2 * nq], av[0], b0);
        mma_f16(oacc[0][2 * nq + 1], av[0], b1);
        mma_f16(oacc[1][2 * nq], av[1], b0);
        mma_f16(oacc[1][2 * nq + 1], av[1], b1);
      }
    }
  }

  // ---- epilogue ----
  __syncthreads();
#pragma unroll
  for (int nq = 0; nq < 8; nq++) {
    const int qc = nq * 8 + 2 * lc;
    const float il0 = 1.0f / row_l[qc];
    const float il1 = 1.0f / row_l[qc + 1];
#pragma unroll
    for (int mt2 = 0; mt2 < 2; mt2++) {
      const int d0 = w * 32 + mt2 * 16 + lr;
      Qs[qc * QHLD + d0] = __float2half(oacc[mt2][nq][0] * il0);
      Qs[(qc + 1) * QHLD + d0] = __float2half(oacc[mt2][nq][1] * il1);
      Qs[qc * QHLD + d0 + 8] = __float2half(oacc[mt2][nq][2] * il0);
      Qs[(qc + 1) * QHLD + d0 + 8] = __float2half(oacc[mt2][nq][3] * il1);
    }
  }
  __syncthreads();
  for (int i = tid; i < 2048; i += 256) {
    int r = i >> 5, g = i & 31;
    uint4 u = *(uint4*)&Qs[r * QHLD + g * 8];
    *(uint4*)&g_oh[(((size_t)(b * S + q0 + r) * H + h) * D) + g * 8] = u;
  }
}

// ---------------- launch ----------------
extern "C" void kernel_launch(void* const* d_in, const int* in_sizes, int n_in,
                              void* d_out, int out_size) {
  const float* hs   = (const float*)d_in[0];
  const float* cosb = (const float*)d_in[1];
  const float* sinb = (const float*)d_in[2];
  const int*   am   = (const int*)d_in[3];
  const float* Wq   = (const float*)d_in[4];
  const float* Wk   = (const float*)d_in[5];
  const float* Wv   = (const float*)d_in[6];
  const float* Wo   = (const float*)d_in[7];
  const float* qw   = (const float*)d_in[8];
  const float* kw   = (const float*)d_in[9];
  float* out = (float*)d_out;

  __half *hsh, *wqkvh, *woh, *qkvh, *oh;
  cudaGetSymbolAddress((void**)&hsh, g_hsh);
  cudaGetSymbolAddress((void**)&wqkvh, g_wqkvh);
  cudaGetSymbolAddress((void**)&woh, g_woh);
  cudaGetSymbolAddress((void**)&qkvh, g_qkvh);
  cudaGetSymbolAddress((void**)&oh, g_oh);

  const int M = B * S;  // 4096

  cudaFuncSetAttribute(gemm_f16<__half>,
                       cudaFuncAttributeMaxDynamicSharedMemorySize, GEMMH_SMEM);
  cudaFuncSetAttribute(gemm_f16<float>,
                       cudaFuncAttributeMaxDynamicSharedMemorySize, GEMMH_SMEM);
  cudaFuncSetAttribute(attn_f16, cudaFuncAttributeMaxDynamicSharedMemorySize,
                       ATTH_SMEM);

  // fp16 conversion / packing passes (3 launches)
  cvt_half<<<2048, 256>>>((const float4*)hs, (uint2*)hsh, (B * S * E) / 4);
  cvt_half<<<1024, 256>>>((const float4*)Wo, (uint2*)woh, (H * D * E) / 4);
  cvt_packw<<<2048, 256>>>((const float4*)Wq, (const float4*)Wk,
                           (const float4*)Wv, wqkvh);

  // fused QKV projection (N = 4096), fp16 out
  gemm_f16<__half><<<dim3(4096 / 128, M / 128), 256, GEMMH_SMEM>>>(
      hsh, wqkvh, qkvh, M, 4096, E);

  norm_rope2<<<M, 256>>>(cosb, sinb, qw, kw);

  attn_f16<<<dim3(S / 64, H, B), 256, ATTH_SMEM>>>(am);

  gemm_f16<float><<<dim3(E / 128, M / 128), 256, GEMMH_SMEM>>>(
      oh, woh, out, M, E, E);
}

// round 11
// speedup vs baseline: 31.6725x; 1.0646x over previous
#include <cuda_runtime.h>
#include <cuda_fp16.h>
#include <math.h>
#include <stdint.h>

#define B 2
#define S 2048
#define E 2048
#define H 8
#define KV 4
#define D 256
#define WIN 1024
#define EPS 1e-6f

// ---------------- scratch (device globals; no allocation) ----------------
__device__ __half g_hsh[(size_t)B * S * E];        // 16 MB fp16 hidden
__device__ __half g_wqkvh[(size_t)E * 4096];       // 16 MB packed Wq|Wk|Wv
__device__ __half g_woh[(size_t)H * D * E];        // 8 MB
__device__ __half g_qkvh[(size_t)B * S * 4096];    // 32 MB packed q|k|v
__device__ __half g_oh[(size_t)B * S * H * D];     // 16 MB attn out

// packed column offsets (halves)
#define QOFF 0
#define KOFF 2048
#define VOFF 3072
#define PSTR 4096

// ======================= helpers =========================================
__device__ __forceinline__ uint32_t smem_u32(const void* p) {
  uint32_t a;
  asm("{ .reg .u64 t; cvta.to.shared.u64 t, %1; cvt.u32.u64 %0, t; }"
      : "=r"(a) : "l"(p));
  return a;
}
__device__ __forceinline__ void cpasync16(uint32_t dst, const void* src) {
  asm volatile("cp.async.cg.shared.global [%0], [%1], 16;"
               :: "r"(dst), "l"(src));
}
#define CP_COMMIT() asm volatile("cp.async.commit_group;" ::: "memory")
#define CP_WAIT1() asm volatile("cp.async.wait_group 1;" ::: "memory")
#define CP_WAIT0() asm volatile("cp.async.wait_group 0;" ::: "memory")

__device__ __forceinline__ void mma_f16(float* d, const uint32_t* a,
                                        const uint32_t* b) {
  asm volatile(
      "mma.sync.aligned.m16n8k16.row.col.f32.f16.f16.f32 "
      "{%0,%1,%2,%3},{%4,%5,%6,%7},{%8,%9},{%0,%1,%2,%3};"
      : "+f"(d[0]), "+f"(d[1]), "+f"(d[2]), "+f"(d[3])
      : "r"(a[0]), "r"(a[1]), "r"(a[2]), "r"(a[3]), "r"(b[0]), "r"(b[1]));
}
#define LDMX4(r0, r1, r2, r3, addr)                                        \
  asm volatile("ldmatrix.sync.aligned.m8n8.x4.shared.b16 {%0,%1,%2,%3}, [%4];" \
               : "=r"(r0), "=r"(r1), "=r"(r2), "=r"(r3) : "r"(addr))
#define LDMX4T(r0, r1, r2, r3, addr)                                       \
  asm volatile("ldmatrix.sync.aligned.m8n8.x4.trans.shared.b16 {%0,%1,%2,%3}, [%4];" \
               : "=r"(r0), "=r"(r1), "=r"(r2), "=r"(r3) : "r"(addr))

// ---------------- fp32 -> fp16 conversion passes --------------------------
__global__ __launch_bounds__(256) void cvt_half(const float4* __restrict__ s,
                                                uint2* __restrict__ d, int n4) {
  int i = blockIdx.x * blockDim.x + threadIdx.x;
  const int stride = gridDim.x * blockDim.x;
  for (; i < n4; i += stride) {
    float4 v = s[i];
    __half2 h0 = __floats2half2_rn(v.x, v.y);
    __half2 h1 = __floats2half2_rn(v.z, v.w);
    uint2 u;
    u.x = *reinterpret_cast<uint32_t*>(&h0);
    u.y = *reinterpret_cast<uint32_t*>(&h1);
    d[i] = u;
  }
}
__global__ __launch_bounds__(256) void cvt_packw(const float4* __restrict__ wq,
                                                 const float4* __restrict__ wk,
                                                 const float4* __restrict__ wv,
                                                 __half* __restrict__ d) {
  const int n = E * 1024;
  int i = blockIdx.x * blockDim.x + threadIdx.x;
  const int stride = gridDim.x * blockDim.x;
  for (; i < n; i += stride) {
    int row = i >> 10, g = i & 1023;
    float4 v;
    if (g < 512)       v = wq[(size_t)row * 512 + g];
    else if (g < 768)  v = wk[(size_t)row * 256 + (g - 512)];
    else               v = wv[(size_t)row * 256 + (g - 768)];
    __half2 h0 = __floats2half2_rn(v.x, v.y);
    __half2 h1 = __floats2half2_rn(v.z, v.w);
    uint2 u;
    u.x = *reinterpret_cast<uint32_t*>(&h0);
    u.y = *reinterpret_cast<uint32_t*>(&h1);
    *(uint2*)&d[(size_t)row * PSTR + g * 4] = u;
  }
}

// ========= fp16 mma GEMM (cp.async 3-stage + ldmatrix, BK=64) ============
// cp.async issue for chunk c+2 is interleaved INTO the ks compute loop so
// LDGSTS issue hides under tensor work instead of serializing at chunk head.
#define AH_LD 72
#define BH_LD 136
#define ASTG_B (128 * AH_LD * 2)
#define BSTG_B (64 * BH_LD * 2)
#define GEMMH_SMEM (3 * (ASTG_B + BSTG_B))

template <typename OutT>
__global__ __launch_bounds__(256, 2) void gemm_f16(
    const __half* __restrict__ A, const __half* __restrict__ Bw,
    OutT* __restrict__ C, int M, int N, int K) {
  extern __shared__ char smc[];
  const uint32_t smbA = smem_u32(smc);
  const uint32_t smbB = smbA + 3 * ASTG_B;

  const int tid = threadIdx.x;
  const int lane = tid & 31;
  const int wid = tid >> 5;
  const int bm = blockIdx.y * 128;
  const int bn = blockIdx.x * 128;
  const int wm = (wid & 3) * 32;
  const int wn = (wid >> 2) * 64;

  const __half* aP0 = A + (size_t)(bm + (tid >> 3)) * K + (tid & 7) * 8;
  const __half* bP0 = Bw + (size_t)(tid >> 4) * N + bn + (tid & 15) * 8;
  const uint32_t aS0 = smbA + ((tid >> 3) * AH_LD + (tid & 7) * 8) * 2;
  const uint32_t bS0 = smbB + ((tid >> 4) * BH_LD + (tid & 15) * 8) * 2;
  const int NC = K >> 6;

#define ISSUE_ONE(st, c, _i)                                                 \
  do {                                                                       \
    cpasync16(aS0 + (st) * ASTG_B + (_i) * (32 * AH_LD * 2),                 \
              aP0 + (c) * 64 + (size_t)(_i) * 32 * K);                       \
    cpasync16(bS0 + (st) * BSTG_B + (_i) * (16 * BH_LD * 2),                 \
              bP0 + (size_t)(c) * 64 * N + (size_t)(_i) * 16 * N);           \
  } while (0)

  const int lrow = lane & 15;
  const int lcol8 = (lane >> 4) * 8;
  const uint32_t aAddr0 = smbA + ((wm + lrow) * AH_LD + lcol8) * 2;
  const uint32_t aAddr1 = smbA + ((wm + 16 + lrow) * AH_LD + lcol8) * 2;
  uint32_t bAddr[4];
#pragma unroll
  for (int nb = 0; nb < 4; nb++)
    bAddr[nb] = smbB + (lrow * BH_LD + wn + nb * 16 + lcol8) * 2;

  // prologue: chunks 0 and 1 fully issued
#pragma unroll
  for (int i = 0; i < 4; i++) ISSUE_ONE(0, 0, i);
  CP_COMMIT();
#pragma unroll
  for (int i = 0; i < 4; i++) ISSUE_ONE(1, 1, i);
  CP_COMMIT();

  float acc[2][8][4] = {};

  for (int c = 0; c < NC; c++) {
    if (c + 1 < NC) CP_WAIT1(); else CP_WAIT0();
    __syncthreads();
    const bool pref = (c + 2 < NC);
    const int st2 = (c + 2) % 3;
    const uint32_t aSt = (c % 3) * ASTG_B;
    const uint32_t bSt = (c % 3) * BSTG_B;
#pragma unroll
    for (int ks = 0; ks < 4; ks++) {
      if (pref) ISSUE_ONE(st2, c + 2, ks);  // interleaved prefetch issue
      uint32_t af[2][4], bf[8][2];
      LDMX4(af[0][0], af[0][1], af[0][2], af[0][3], aAddr0 + aSt + ks * 32);
      LDMX4(af[1][0], af[1][1], af[1][2], af[1][3], aAddr1 + aSt + ks * 32);
#pragma unroll
      for (int nb = 0; nb < 4; nb++) {
        uint32_t r0, r1, r2, r3;
        LDMX4T(r0, r1, r2, r3, bAddr[nb] + bSt + ks * (16 * BH_LD * 2));
        bf[2 * nb][0] = r0; bf[2 * nb][1] = r1;
        bf[2 * nb + 1][0] = r2; bf[2 * nb + 1][1] = r3;
      }
#pragma unroll
      for (int mf = 0; mf < 2; mf++)
#pragma unroll
        for (int nf = 0; nf < 8; nf++)
          mma_f16(acc[mf][nf], af[mf], bf[nf]);
    }
    if (pref) CP_COMMIT();
  }

#pragma unroll
  for (int mf = 0; mf < 2; mf++) {
    const int r0 = bm + wm + mf * 16 + (lane >> 2);
#pragma unroll
    for (int nf = 0; nf < 8; nf++) {
      const int col = bn + wn + nf * 8 + 2 * (lane & 3);
      if constexpr (sizeof(OutT) == 4) {
        float2 v0, v1;
        v0.x = acc[mf][nf][0]; v0.y = acc[mf][nf][1];
        v1.x = acc[mf][nf][2]; v1.y = acc[mf][nf][3];
        *(float2*)&C[(size_t)r0 * N + col] = v0;
        *(float2*)&C[(size_t)(r0 + 8) * N + col] = v1;
      } else {
        *(__half2*)&C[(size_t)r0 * N + col] =
            __floats2half2_rn(acc[mf][nf][0], acc[mf][nf][1]);
        *(__half2*)&C[(size_t)(r0 + 8) * N + col] =
            __floats2half2_rn(acc[mf][nf][2], acc[mf][nf][3]);
      }
    }
  }
}

// -------- fused RMSNorm + RoPE: one block per token row, loop heads ------
__global__ __launch_bounds__(256) void norm_rope2(
    const float* __restrict__ cosb, const float* __restrict__ sinb,
    const float* __restrict__ qw, const float* __restrict__ kw) {
  const int row = blockIdx.x;  // b*S + s
  const int d = threadIdx.x;
  __shared__ float cs[D], sn[D], xs[D], red[8];
  cs[d] = cosb[(size_t)row * D + d];
  sn[d] = sinb[(size_t)row * D + d];
  const float wqv = qw[d];
  const float wkv = kw[d];
  __half* base = &g_qkvh[(size_t)row * PSTR];
#pragma unroll
  for (int hh = 0; hh < H + KV; hh++) {
    __half* ptr = (hh < H) ? (base + QOFF + hh * D)
                           : (base + KOFF + (hh - H) * D);
    const float w = (hh < H) ? wqv : wkv;
    const float osc = (hh < H) ? 0.0625f : 1.0f;
    float v = __half2float(ptr[d]);
    float ss = v * v;
#pragma unroll
    for (int o = 16; o > 0; o >>= 1) ss += __shfl_xor_sync(0xffffffffu, ss, o);
    if ((d & 31) == 0) red[d >> 5] = ss;
    __syncthreads();
    float tot = 0.f;
#pragma unroll
    for (int i = 0; i < 8; i++) tot += red[i];
    float inv = rsqrtf(tot * (1.0f / D) + EPS);
    float xn = v * inv * (1.0f + w);
    xs[d] = xn;
    __syncthreads();
    float rot = (d < D / 2) ? -xs[d + D / 2] : xs[d - D / 2];
    ptr[d] = __float2half((xn * cs[d] + rot * sn[d]) * osc);
    __syncthreads();
  }
}

// ============= fp16 mma flash attention (sliding window) =================
#define QHLD 264
#define PHLD 72
#define ATTH_SMEM 112640
#define NEGF (-1e30f)

__global__ __launch_bounds__(256, 2) void attn_f16(const int* __restrict__ am) {
  extern __shared__ char smc[];
  __half* Qs = (__half*)smc;            // [64][QHLD]
  __half* Ks = Qs + 64 * QHLD;
  __half* Vs = Ks + 64 * QHLD;
  __half* Ps = Vs + 64 * QHLD;          // [64][PHLD]
  float* row_m = (float*)(smc + 110592);
  float* row_l = row_m + 64;
  float* row_a = row_l + 64;
  float* pm = row_a + 64;
  float* pl = pm + 128;
  int* ams = (int*)(pl + 128);

  const uint32_t uQ = smem_u32(Qs);
  const uint32_t uK = smem_u32(Ks);
  const uint32_t uV = smem_u32(Vs);
  const uint32_t uP = smem_u32(Ps);

  const int tid = threadIdx.x;
  const int lane = tid & 31;
  const int w = tid >> 5;
  const int mt = w & 3;
  const int half_ = w >> 2;
  const int lr = lane >> 2;
  const int lc = lane & 3;
  const int lrow = lane & 15;
  const int lcol8 = (lane >> 4) * 8;

  // longest-first: high q0 (more key blocks) launches first
  const int q0 = ((int)gridDim.x - 1 - (int)blockIdx.x) * 64;
  const int h = blockIdx.y;
  const int b = blockIdx.z;
  const int hk = h / (H / KV);

  {
    const __half* qsrc = g_qkvh + (size_t)(b * S + q0) * PSTR + QOFF + h * D;
    for (int i = tid; i < 2048; i += 256) {
      int r = i >> 5, g = i & 31;
      cpasync16(uQ + (r * QHLD + g * 8) * 2, qsrc + (size_t)r * PSTR + g * 8);
    }
    CP_COMMIT();
  }
  if (tid < 64) {
    row_m[tid] = NEGF;
    row_l[tid] = 0.f;
  }

  float oacc[2][8][4] = {};

  int kb0 = q0 - (WIN - 1);
  if (kb0 < 0) kb0 = 0;
  kb0 &= ~63;
  const int kb_end = q0 + 63;

  for (int kb = kb0; kb <= kb_end; kb += 64) {
    __syncthreads();
    {
      const __half* ksrc = g_qkvh + (size_t)(b * S + kb) * PSTR + KOFF + hk * D;
      for (int i = tid; i < 2048; i += 256) {
        int r = i >> 5, g = i & 31;
        cpasync16(uK + (r * QHLD + g * 8) * 2, ksrc + (size_t)r * PSTR + g * 8);
      }
      CP_COMMIT();  // K group
      const __half* vsrc = g_qkvh + (size_t)(b * S + kb) * PSTR + VOFF + hk * D;
      for (int i = tid; i < 2048; i += 256) {
        int r = i >> 5, g = i & 31;
        cpasync16(uV + (r * QHLD + g * 8) * 2, vsrc + (size_t)r * PSTR + g * 8);
      }
      CP_COMMIT();  // V group
    }
    if (tid < 64) ams[tid] = am[b * S + kb + tid];
    CP_WAIT1();       // Q(first iter)+K complete; V in flight
    __syncthreads();

    // ---- QK^T ----
    float sacc[4][4] = {};
    const uint32_t qa = uQ + ((mt * 16 + lrow) * QHLD + lcol8) * 2;
    const uint32_t ka0 = uK + ((half_ * 32 + lrow) * QHLD + lcol8) * 2;
    const uint32_t ka1 = ka0 + 16 * QHLD * 2;
#pragma unroll
    for (int ks = 0; ks < 16; ks++) {
      uint32_t a[4], r0, r1, r2, r3;
      LDMX4(a[0], a[1], a[2], a[3], qa + ks * 32);
      LDMX4(r0, r1, r2, r3, ka0 + ks * 32);
      {
        uint32_t b0[2] = {r0, r2}, b1[2] = {r1, r3};
        mma_f16(sacc[0], a, b0);
        mma_f16(sacc[1], a, b1);
      }
      LDMX4(r0, r1, r2, r3, ka1 + ks * 32);
      {
        uint32_t b0[2] = {r0, r2}, b1[2] = {r1, r3};
        mma_f16(sacc[2], a, b0);
        mma_f16(sacc[3], a, b1);
      }
    }

    // ---- mask + partial row max ----
    const int r0 = mt * 16 + lr;
    const int r1 = r0 + 8;
    const int qg0 = q0 + r0;
    const int qg1 = q0 + r1;
    float mx0 = NEGF, mx1 = NEGF;
#pragma unroll
    for (int nt = 0; nt < 4; nt++) {
      const int colb = half_ * 32 + nt * 8 + 2 * lc;
#pragma unroll
      for (int j = 0; j < 4; j++) {
        const int col = colb + (j & 1);
        const int kg = kb + col;
        const int qg = (j < 2) ? qg0 : qg1;
        bool ok = (kg <= qg) && (qg - kg < WIN) && (ams[col] != 0);
        float v = ok ? sacc[nt][j] : NEGF;
        sacc[nt][j] = v;
        if (j < 2) mx0 = fmaxf(mx0, v);
        else       mx1 = fmaxf(mx1, v);
      }
    }
    mx0 = fmaxf(mx0, __shfl_xor_sync(0xffffffffu, mx0, 1));
    mx0 = fmaxf(mx0, __shfl_xor_sync(0xffffffffu, mx0, 2));
    mx1 = fmaxf(mx1, __shfl_xor_sync(0xffffffffu, mx1, 1));
    mx1 = fmaxf(mx1, __shfl_xor_sync(0xffffffffu, mx1, 2));
    if (lc == 0) {
      pm[half_ * 64 + r0] = mx0;
      pm[half_ * 64 + r1] = mx1;
    }
    __syncthreads();
    if (tid < 64) {
      float mn = fmaxf(row_m[tid], fmaxf(pm[tid], pm[64 + tid]));
      row_a[tid] = __expf(row_m[tid] - mn);
      row_m[tid] = mn;
    }
    __syncthreads();

    // ---- P = exp(s-m) -> fp16; sums; rescale oacc ----
    const float mn0 = row_m[r0];
    const float mn1 = row_m[r1];
    float s0 = 0.f, s1 = 0.f;
#pragma unroll
    for (int nt = 0; nt < 4; nt++) {
      const int colb = half_ * 32 + nt * 8 + 2 * lc;
      float p00 = (sacc[nt][0] < -5e29f) ? 0.f : __expf(sacc[nt][0] - mn0);
      float p01 = (sacc[nt][1] < -5e29f) ? 0.f : __expf(sacc[nt][1] - mn0);
      float p10 = (sacc[nt][2] < -5e29f) ? 0.f : __expf(sacc[nt][2] - mn1);
      float p11 = (sacc[nt][3] < -5e29f) ? 0.f : __expf(sacc[nt][3] - mn1);
      s0 += p00 + p01;
      s1 += p10 + p11;
      *(__half2*)&Ps[r0 * PHLD + colb] = __floats2half2_rn(p00, p01);
      *(__half2*)&Ps[r1 * PHLD + colb] = __floats2half2_rn(p10, p11);
    }
    s0 += __shfl_xor_sync(0xffffffffu, s0, 1);
    s0 += __shfl_xor_sync(0xffffffffu, s0, 2);
    s1 += __shfl_xor_sync(0xffffffffu, s1, 1);
    s1 += __shfl_xor_sync(0xffffffffu, s1, 2);
    if (lc == 0) {
      pl[half_ * 64 + r0] = s0;
      pl[half_ * 64 + r1] = s1;
    }
#pragma unroll
    for (int nq = 0; nq < 8; nq++) {
      const int qc = nq * 8 + 2 * lc;
      const float a0 = row_a[qc];
      const float a1 = row_a[qc + 1];
#pragma unroll
      for (int mt2 = 0; mt2 < 2; mt2++) {
        oacc[mt2][nq][0] *= a0;
        oacc[mt2][nq][1] *= a1;
        oacc[mt2][nq][2] *= a0;
        oacc[mt2][nq][3] *= a1;
      }
    }
    CP_WAIT0();       // V complete
    __syncthreads();  // Ps/pl/V visible
    if (tid < 64) row_l[tid] = row_l[tid] * row_a[tid] + pl[tid] + pl[64 + tid];

    // ---- PV (transposed) ----
#pragma unroll
    for (int kk = 0; kk < 4; kk++) {
      uint32_t av[2][4];
#pragma unroll
      for (int mt2 = 0; mt2 < 2; mt2++) {
        uint32_t r0v, r1v, r2v, r3v;
        LDMX4T(r0v, r1v, r2v, r3v,
               uV + ((kk * 16 + lrow) * QHLD + w * 32 + mt2 * 16 + lcol8) * 2);
        av[mt2][0] = r0v; av[mt2][1] = r2v;
        av[mt2][2] = r1v; av[mt2][3] = r3v;
      }
#pragma unroll
      for (int nq = 0; nq < 4; nq++) {
        uint32_t r0p, r1p, r2p, r3p;
        LDMX4(r0p, r1p, r2p, r3p,
              uP + ((nq * 16 + lrow) * PHLD + kk * 16 + lcol8) * 2);
        uint32_t b0[2] = {r0p, r2p}, b1[2] = {r1p, r3p};
        mma_f16(oacc[0][2 * nq], av[0], b0);
        mma_f16(oacc[0][2 * nq + 1], av[0], b1);
        mma_f16(oacc[1][2 * nq], av[1], b0);
        mma_f16(oacc[1][2 * nq + 1], av[1], b1);
      }
    }
  }

  // ---- epilogue ----
  __syncthreads();
#pragma unroll
  for (int nq = 0; nq < 8; nq++) {
    const int qc = nq * 8 + 2 * lc;
    const float il0 = 1.0f / row_l[qc];
    const float il1 = 1.0f / row_l[qc + 1];
#pragma unroll
    for (int mt2 = 0; mt2 < 2; mt2++) {
      const int d0 = w * 32 + mt2 * 16 + lr;
      Qs[qc * QHLD + d0] = __float2half(oacc[mt2][nq][0] * il0);
      Qs[(qc + 1) * QHLD + d0] = __float2half(oacc[mt2][nq][1] * il1);
      Qs[qc * QHLD + d0 + 8] = __float2half(oacc[mt2][nq][2] * il0);
      Qs[(qc + 1) * QHLD + d0 + 8] = __float2half(oacc[mt2][nq][3] * il1);
    }
  }
  __syncthreads();
  for (int i = tid; i < 2048; i += 256) {
    int r = i >> 5, g = i & 31;
    uint4 u = *(uint4*)&Qs[r * QHLD + g * 8];
    *(uint4*)&g_oh[(((size_t)(b * S + q0 + r) * H + h) * D) + g * 8] = u;
  }
}

// ---------------- launch ----------------
extern "C" void kernel_launch(void* const* d_in, const int* in_sizes, int n_in,
                              void* d_out, int out_size) {
  const float* hs   = (const float*)d_in[0];
  const float* cosb = (const float*)d_in[1];
  const float* sinb = (const float*)d_in[2];
  const int*   am   = (const int*)d_in[3];
  const float* Wq   = (const float*)d_in[4];
  const float* Wk   = (const float*)d_in[5];
  const float* Wv   = (const float*)d_in[6];
  const float* Wo   = (const float*)d_in[7];
  const float* qw   = (const float*)d_in[8];
  const float* kw   = (const float*)d_in[9];
  float* out = (float*)d_out;

  __half *hsh, *wqkvh, *woh, *qkvh, *oh;
  cudaGetSymbolAddress((void**)&hsh, g_hsh);
  cudaGetSymbolAddress((void**)&wqkvh, g_wqkvh);
  cudaGetSymbolAddress((void**)&woh, g_woh);
  cudaGetSymbolAddress((void**)&qkvh, g_qkvh);
  cudaGetSymbolAddress((void**)&oh, g_oh);

  const int M = B * S;  // 4096

  cudaFuncSetAttribute(gemm_f16<__half>,
                       cudaFuncAttributeMaxDynamicSharedMemorySize, GEMMH_SMEM);
  cudaFuncSetAttribute(gemm_f16<float>,
                       cudaFuncAttributeMaxDynamicSharedMemorySize, GEMMH_SMEM);
  cudaFuncSetAttribute(attn_f16, cudaFuncAttributeMaxDynamicSharedMemorySize,
                       ATTH_SMEM);

  // fp16 conversion / packing passes
  cvt_half<<<2048, 256>>>((const float4*)hs, (uint2*)hsh, (B * S * E) / 4);
  cvt_half<<<1024, 256>>>((const float4*)Wo, (uint2*)woh, (H * D * E) / 4);
  cvt_packw<<<2048, 256>>>((const float4*)Wq, (const float4*)Wk,
                           (const float4*)Wv, wqkvh);

  // fused QKV projection (N = 4096), fp16 out
  gemm_f16<__half><<<dim3(4096 / 128, M / 128), 256, GEMMH_SMEM>>>(
      hsh, wqkvh, qkvh, M, 4096, E);

  norm_rope2<<<M, 256>>>(cosb, sinb, qw, kw);

  attn_f16<<<dim3(S / 64, H, B), 256, ATTH_SMEM>>>(am);

  gemm_f16<float><<<dim3(E / 128, M / 128), 256, GEMMH_SMEM>>>(
      oh, woh, out, M, E, E);
}

// round 12
// speedup vs baseline: 31.9796x; 1.0097x over previous
#include <cuda_runtime.h>
#include <cuda_fp16.h>
#include <math.h>
#include <stdint.h>

#define B 2
#define S 2048
#define E 2048
#define H 8
#define KV 4
#define D 256
#define WIN 1024
#define EPS 1e-6f

// ---------------- scratch (device globals; no allocation) ----------------
__device__ __half g_hsh[(size_t)B * S * E];        // 16 MB fp16 hidden
__device__ __half g_wqkvh[(size_t)E * 4096];       // 16 MB packed Wq|Wk|Wv
__device__ __half g_woh[(size_t)H * D * E];        // 8 MB
__device__ __half g_qkvh[(size_t)B * S * 4096];    // 32 MB packed q|k|v
__device__ __half g_oh[(size_t)B * S * H * D];     // 16 MB attn out

// packed column offsets (halves)
#define QOFF 0
#define KOFF 2048
#define VOFF 3072
#define PSTR 4096

// ======================= helpers =========================================
__device__ __forceinline__ uint32_t smem_u32(const void* p) {
  uint32_t a;
  asm("{ .reg .u64 t; cvta.to.shared.u64 t, %1; cvt.u32.u64 %0, t; }"
      : "=r"(a) : "l"(p));
  return a;
}
__device__ __forceinline__ void cpasync16(uint32_t dst, const void* src) {
  asm volatile("cp.async.cg.shared.global [%0], [%1], 16;"
               :: "r"(dst), "l"(src));
}
#define CP_COMMIT() asm volatile("cp.async.commit_group;" ::: "memory")
#define CP_WAIT1() asm volatile("cp.async.wait_group 1;" ::: "memory")
#define CP_WAIT0() asm volatile("cp.async.wait_group 0;" ::: "memory")

__device__ __forceinline__ void mma_f16(float* d, const uint32_t* a,
                                        const uint32_t* b) {
  asm volatile(
      "mma.sync.aligned.m16n8k16.row.col.f32.f16.f16.f32 "
      "{%0,%1,%2,%3},{%4,%5,%6,%7},{%8,%9},{%0,%1,%2,%3};"
      : "+f"(d[0]), "+f"(d[1]), "+f"(d[2]), "+f"(d[3])
      : "r"(a[0]), "r"(a[1]), "r"(a[2]), "r"(a[3]), "r"(b[0]), "r"(b[1]));
}
#define LDMX4(r0, r1, r2, r3, addr)                                        \
  asm volatile("ldmatrix.sync.aligned.m8n8.x4.shared.b16 {%0,%1,%2,%3}, [%4];" \
               : "=r"(r0), "=r"(r1), "=r"(r2), "=r"(r3) : "r"(addr))
#define LDMX4T(r0, r1, r2, r3, addr)                                       \
  asm volatile("ldmatrix.sync.aligned.m8n8.x4.trans.shared.b16 {%0,%1,%2,%3}, [%4];" \
               : "=r"(r0), "=r"(r1), "=r"(r2), "=r"(r3) : "r"(addr))

// -------- ONE fused fp32 -> fp16 conversion/packing pass -----------------
#define HS4 ((B * S * E) / 4)
#define WO4 ((H * D * E) / 4)
#define PW4 (E * 1024)
__global__ __launch_bounds__(256) void cvt_all(
    const float4* __restrict__ hs, const float4* __restrict__ wo,
    const float4* __restrict__ wq, const float4* __restrict__ wk,
    const float4* __restrict__ wv) {
  const int total = HS4 + WO4 + PW4;
  int i = blockIdx.x * blockDim.x + threadIdx.x;
  const int stride = gridDim.x * blockDim.x;
  for (; i < total; i += stride) {
    float4 v;
    uint2* dst;
    if (i < HS4) {
      v = hs[i];
      dst = (uint2*)g_hsh + i;
    } else if (i < HS4 + WO4) {
      int j = i - HS4;
      v = wo[j];
      dst = (uint2*)g_woh + j;
    } else {
      int j = i - HS4 - WO4;
      int row = j >> 10, g = j & 1023;
      if (g < 512)       v = wq[(size_t)row * 512 + g];
      else if (g < 768)  v = wk[(size_t)row * 256 + (g - 512)];
      else               v = wv[(size_t)row * 256 + (g - 768)];
      dst = (uint2*)&g_wqkvh[(size_t)row * PSTR + g * 4];
    }
    __half2 h0 = __floats2half2_rn(v.x, v.y);
    __half2 h1 = __floats2half2_rn(v.z, v.w);
    uint2 u;
    u.x = *reinterpret_cast<uint32_t*>(&h0);
    u.y = *reinterpret_cast<uint32_t*>(&h1);
    *dst = u;
  }
}

// ========= fp16 mma GEMM (cp.async 3-stage + ldmatrix, BK=64) ============
#define AH_LD 72
#define BH_LD 136
#define ASTG_B (128 * AH_LD * 2)
#define BSTG_B (64 * BH_LD * 2)
#define GEMMH_SMEM (3 * (ASTG_B + BSTG_B))

template <typename OutT>
__global__ __launch_bounds__(256, 2) void gemm_f16(
    const __half* __restrict__ A, const __half* __restrict__ Bw,
    OutT* __restrict__ C, int M, int N, int K) {
  extern __shared__ char smc[];
  const uint32_t smbA = smem_u32(smc);
  const uint32_t smbB = smbA + 3 * ASTG_B;

  const int tid = threadIdx.x;
  const int lane = tid & 31;
  const int wid = tid >> 5;
  const int bm = blockIdx.y * 128;
  const int bn = blockIdx.x * 128;
  const int wm = (wid & 3) * 32;
  const int wn = (wid >> 2) * 64;

  const __half* aP0 = A + (size_t)(bm + (tid >> 3)) * K + (tid & 7) * 8;
  const __half* bP0 = Bw + (size_t)(tid >> 4) * N + bn + (tid & 15) * 8;
  const uint32_t aS0 = smbA + ((tid >> 3) * AH_LD + (tid & 7) * 8) * 2;
  const uint32_t bS0 = smbB + ((tid >> 4) * BH_LD + (tid & 15) * 8) * 2;
  const int NC = K >> 6;

#define ISSUE_ONE(st, c, _i)                                                 \
  do {                                                                       \
    cpasync16(aS0 + (st) * ASTG_B + (_i) * (32 * AH_LD * 2),                 \
              aP0 + (c) * 64 + (size_t)(_i) * 32 * K);                       \
    cpasync16(bS0 + (st) * BSTG_B + (_i) * (16 * BH_LD * 2),                 \
              bP0 + (size_t)(c) * 64 * N + (size_t)(_i) * 16 * N);           \
  } while (0)

  const int lrow = lane & 15;
  const int lcol8 = (lane >> 4) * 8;
  const uint32_t aAddr0 = smbA + ((wm + lrow) * AH_LD + lcol8) * 2;
  const uint32_t aAddr1 = smbA + ((wm + 16 + lrow) * AH_LD + lcol8) * 2;
  uint32_t bAddr[4];
#pragma unroll
  for (int nb = 0; nb < 4; nb++)
    bAddr[nb] = smbB + (lrow * BH_LD + wn + nb * 16 + lcol8) * 2;

#pragma unroll
  for (int i = 0; i < 4; i++) ISSUE_ONE(0, 0, i);
  CP_COMMIT();
#pragma unroll
  for (int i = 0; i < 4; i++) ISSUE_ONE(1, 1, i);
  CP_COMMIT();

  float acc[2][8][4] = {};

  for (int c = 0; c < NC; c++) {
    if (c + 1 < NC) CP_WAIT1(); else CP_WAIT0();
    __syncthreads();
    const bool pref = (c + 2 < NC);
    const int st2 = (c + 2) % 3;
    const uint32_t aSt = (c % 3) * ASTG_B;
    const uint32_t bSt = (c % 3) * BSTG_B;
#pragma unroll
    for (int ks = 0; ks < 4; ks++) {
      if (pref) ISSUE_ONE(st2, c + 2, ks);
      uint32_t af[2][4], bf[8][2];
      LDMX4(af[0][0], af[0][1], af[0][2], af[0][3], aAddr0 + aSt + ks * 32);
      LDMX4(af[1][0], af[1][1], af[1][2], af[1][3], aAddr1 + aSt + ks * 32);
#pragma unroll
      for (int nb = 0; nb < 4; nb++) {
        uint32_t r0, r1, r2, r3;
        LDMX4T(r0, r1, r2, r3, bAddr[nb] + bSt + ks * (16 * BH_LD * 2));
        bf[2 * nb][0] = r0; bf[2 * nb][1] = r1;
        bf[2 * nb + 1][0] = r2; bf[2 * nb + 1][1] = r3;
      }
#pragma unroll
      for (int mf = 0; mf < 2; mf++)
#pragma unroll
        for (int nf = 0; nf < 8; nf++)
          mma_f16(acc[mf][nf], af[mf], bf[nf]);
    }
    if (pref) CP_COMMIT();
  }

#pragma unroll
  for (int mf = 0; mf < 2; mf++) {
    const int r0 = bm + wm + mf * 16 + (lane >> 2);
#pragma unroll
    for (int nf = 0; nf < 8; nf++) {
      const int col = bn + wn + nf * 8 + 2 * (lane & 3);
      if constexpr (sizeof(OutT) == 4) {
        float2 v0, v1;
        v0.x = acc[mf][nf][0]; v0.y = acc[mf][nf][1];
        v1.x = acc[mf][nf][2]; v1.y = acc[mf][nf][3];
        *(float2*)&C[(size_t)r0 * N + col] = v0;
        *(float2*)&C[(size_t)(r0 + 8) * N + col] = v1;
      } else {
        *(__half2*)&C[(size_t)r0 * N + col] =
            __floats2half2_rn(acc[mf][nf][0], acc[mf][nf][1]);
        *(__half2*)&C[(size_t)(r0 + 8) * N + col] =
            __floats2half2_rn(acc[mf][nf][2], acc[mf][nf][3]);
      }
    }
  }
}

// -------- fused RMSNorm + RoPE: one block per token row, loop heads ------
__global__ __launch_bounds__(256) void norm_rope2(
    const float* __restrict__ cosb, const float* __restrict__ sinb,
    const float* __restrict__ qw, const float* __restrict__ kw) {
  const int row = blockIdx.x;  // b*S + s
  const int d = threadIdx.x;
  __shared__ float cs[D], sn[D], xs[D], red[8];
  cs[d] = cosb[(size_t)row * D + d];
  sn[d] = sinb[(size_t)row * D + d];
  const float wqv = qw[d];
  const float wkv = kw[d];
  __half* base = &g_qkvh[(size_t)row * PSTR];
#pragma unroll
  for (int hh = 0; hh < H + KV; hh++) {
    __half* ptr = (hh < H) ? (base + QOFF + hh * D)
                           : (base + KOFF + (hh - H) * D);
    const float w = (hh < H) ? wqv : wkv;
    const float osc = (hh < H) ? 0.0625f : 1.0f;
    float v = __half2float(ptr[d]);
    float ss = v * v;
#pragma unroll
    for (int o = 16; o > 0; o >>= 1) ss += __shfl_xor_sync(0xffffffffu, ss, o);
    if ((d & 31) == 0) red[d >> 5] = ss;
    __syncthreads();
    float tot = 0.f;
#pragma unroll
    for (int i = 0; i < 8; i++) tot += red[i];
    float inv = rsqrtf(tot * (1.0f / D) + EPS);
    float xn = v * inv * (1.0f + w);
    xs[d] = xn;
    __syncthreads();
    float rot = (d < D / 2) ? -xs[d + D / 2] : xs[d - D / 2];
    ptr[d] = __float2half((xn * cs[d] + rot * sn[d]) * osc);
    __syncthreads();
  }
}

// ============= fp16 mma flash attention (K-prefetch pipeline) ============
#define QHLD 264
#define PHLD 72
#define ATTH_SMEM 112640
#define NEGF (-1e30f)

__global__ __launch_bounds__(256, 2) void attn_f16(const int* __restrict__ am) {
  extern __shared__ char smc[];
  __half* Qs = (__half*)smc;            // [64][QHLD]
  __half* Ks = Qs + 64 * QHLD;
  __half* Vs = Ks + 64 * QHLD;
  __half* Ps = Vs + 64 * QHLD;          // [64][PHLD]
  float* row_m = (float*)(smc + 110592);
  float* row_l = row_m + 64;
  float* row_a = row_l + 64;
  float* pm = row_a + 64;
  float* pl = pm + 128;
  int* ams = (int*)(pl + 128);

  const uint32_t uQ = smem_u32(Qs);
  const uint32_t uK = smem_u32(Ks);
  const uint32_t uV = smem_u32(Vs);
  const uint32_t uP = smem_u32(Ps);

  const int tid = threadIdx.x;
  const int lane = tid & 31;
  const int w = tid >> 5;
  const int mt = w & 3;
  const int half_ = w >> 2;
  const int lr = lane >> 2;
  const int lc = lane & 3;
  const int lrow = lane & 15;
  const int lcol8 = (lane >> 4) * 8;

  const int q0 = ((int)gridDim.x - 1 - (int)blockIdx.x) * 64;
  const int h = blockIdx.y;
  const int b = blockIdx.z;
  const int hk = h / (H / KV);

  int kb0 = q0 - (WIN - 1);
  if (kb0 < 0) kb0 = 0;
  kb0 &= ~63;
  const int kb_end = q0 + 63;

  // prologue: Q group, then K(kb0) group
  {
    const __half* qsrc = g_qkvh + (size_t)(b * S + q0) * PSTR + QOFF + h * D;
    for (int i = tid; i < 2048; i += 256) {
      int r = i >> 5, g = i & 31;
      cpasync16(uQ + (r * QHLD + g * 8) * 2, qsrc + (size_t)r * PSTR + g * 8);
    }
    CP_COMMIT();  // Q
    const __half* ksrc = g_qkvh + (size_t)(b * S + kb0) * PSTR + KOFF + hk * D;
    for (int i = tid; i < 2048; i += 256) {
      int r = i >> 5, g = i & 31;
      cpasync16(uK + (r * QHLD + g * 8) * 2, ksrc + (size_t)r * PSTR + g * 8);
    }
    CP_COMMIT();  // K(kb0)
  }
  if (tid < 64) {
    row_m[tid] = NEGF;
    row_l[tid] = 0.f;
  }

  float oacc[2][8][4] = {};

  for (int kb = kb0; kb <= kb_end; kb += 64) {
    __syncthreads();  // prior PV readers done -> Vs reusable; Ps reusable
    {
      const __half* vsrc = g_qkvh + (size_t)(b * S + kb) * PSTR + VOFF + hk * D;
      for (int i = tid; i < 2048; i += 256) {
        int r = i >> 5, g = i & 31;
        cpasync16(uV + (r * QHLD + g * 8) * 2, vsrc + (size_t)r * PSTR + g * 8);
      }
      CP_COMMIT();  // V(kb)
    }
    if (tid < 64) ams[tid] = am[b * S + kb + tid];
    CP_WAIT1();       // all but V(kb) complete: Q + K(kb) ready
    __syncthreads();

    // ---- QK^T ----
    float sacc[4][4] = {};
    const uint32_t qa = uQ + ((mt * 16 + lrow) * QHLD + lcol8) * 2;
    const uint32_t ka0 = uK + ((half_ * 32 + lrow) * QHLD + lcol8) * 2;
    const uint32_t ka1 = ka0 + 16 * QHLD * 2;
#pragma unroll
    for (int ks = 0; ks < 16; ks++) {
      uint32_t a[4], r0, r1, r2, r3;
      LDMX4(a[0], a[1], a[2], a[3], qa + ks * 32);
      LDMX4(r0, r1, r2, r3, ka0 + ks * 32);
      {
        uint32_t b0[2] = {r0, r2}, b1[2] = {r1, r3};
        mma_f16(sacc[0], a, b0);
        mma_f16(sacc[1], a, b1);
      }
      LDMX4(r0, r1, r2, r3, ka1 + ks * 32);
      {
        uint32_t b0[2] = {r0, r2}, b1[2] = {r1, r3};
        mma_f16(sacc[2], a, b0);
        mma_f16(sacc[3], a, b1);
      }
    }

    // ---- mask + partial row max ----
    const int r0 = mt * 16 + lr;
    const int r1 = r0 + 8;
    const int qg0 = q0 + r0;
    const int qg1 = q0 + r1;
    float mx0 = NEGF, mx1 = NEGF;
#pragma unroll
    for (int nt = 0; nt < 4; nt++) {
      const int colb = half_ * 32 + nt * 8 + 2 * lc;
#pragma unroll
      for (int j = 0; j < 4; j++) {
        const int col = colb + (j & 1);
        const int kg = kb + col;
        const int qg = (j < 2) ? qg0 : qg1;
        bool ok = (kg <= qg) && (qg - kg < WIN) && (ams[col] != 0);
        float v = ok ? sacc[nt][j] : NEGF;
        sacc[nt][j] = v;
        if (j < 2) mx0 = fmaxf(mx0, v);
        else       mx1 = fmaxf(mx1, v);
      }
    }
    mx0 = fmaxf(mx0, __shfl_xor_sync(0xffffffffu, mx0, 1));
    mx0 = fmaxf(mx0, __shfl_xor_sync(0xffffffffu, mx0, 2));
    mx1 = fmaxf(mx1, __shfl_xor_sync(0xffffffffu, mx1, 1));
    mx1 = fmaxf(mx1, __shfl_xor_sync(0xffffffffu, mx1, 2));
    if (lc == 0) {
      pm[half_ * 64 + r0] = mx0;
      pm[half_ * 64 + r1] = mx1;
    }
    __syncthreads();  // pm visible; ALL warps past QK -> Ks reusable

    // prefetch K(kb+64) into Ks while softmax+PV run
    const bool hasnext = (kb + 64 <= kb_end);
    if (hasnext) {
      const __half* ksrc =
          g_qkvh + (size_t)(b * S + kb + 64) * PSTR + KOFF + hk * D;
      for (int i = tid; i < 2048; i += 256) {
        int r = i >> 5, g = i & 31;
        cpasync16(uK + (r * QHLD + g * 8) * 2, ksrc + (size_t)r * PSTR + g * 8);
      }
      CP_COMMIT();  // K(kb+64)
    }
    if (tid < 64) {
      float mn = fmaxf(row_m[tid], fmaxf(pm[tid], pm[64 + tid]));
      row_a[tid] = __expf(row_m[tid] - mn);
      row_m[tid] = mn;
    }
    __syncthreads();

    // ---- P = exp(s-m) -> fp16; sums; rescale oacc ----
    const float mn0 = row_m[r0];
    const float mn1 = row_m[r1];
    float s0 = 0.f, s1 = 0.f;
#pragma unroll
    for (int nt = 0; nt < 4; nt++) {
      const int colb = half_ * 32 + nt * 8 + 2 * lc;
      float p00 = (sacc[nt][0] < -5e29f) ? 0.f : __expf(sacc[nt][0] - mn0);
      float p01 = (sacc[nt][1] < -5e29f) ? 0.f : __expf(sacc[nt][1] - mn0);
      float p10 = (sacc[nt][2] < -5e29f) ? 0.f : __expf(sacc[nt][2] - mn1);
      float p11 = (sacc[nt][3] < -5e29f) ? 0.f : __expf(sacc[nt][3] - mn1);
      s0 += p00 + p01;
      s1 += p10 + p11;
      *(__half2*)&Ps[r0 * PHLD + colb] = __floats2half2_rn(p00, p01);
      *(__half2*)&Ps[r1 * PHLD + colb] = __floats2half2_rn(p10, p11);
    }
    s0 += __shfl_xor_sync(0xffffffffu, s0, 1);
    s0 += __shfl_xor_sync(0xffffffffu, s0, 2);
    s1 += __shfl_xor_sync(0xffffffffu, s1, 1);
    s1 += __shfl_xor_sync(0xffffffffu, s1, 2);
    if (lc == 0) {
      pl[half_ * 64 + r0] = s0;
      pl[half_ * 64 + r1] = s1;
    }
#pragma unroll
    for (int nq = 0; nq < 8; nq++) {
      const int qc = nq * 8 + 2 * lc;
      const float a0 = row_a[qc];
      const float a1 = row_a[qc + 1];
#pragma unroll
      for (int mt2 = 0; mt2 < 2; mt2++) {
        oacc[mt2][nq][0] *= a0;
        oacc[mt2][nq][1] *= a1;
        oacc[mt2][nq][2] *= a0;
        oacc[mt2][nq][3] *= a1;
      }
    }
    if (hasnext) CP_WAIT1(); else CP_WAIT0();  // V(kb) complete
    __syncthreads();  // Ps/pl/V visible
    if (tid < 64) row_l[tid] = row_l[tid] * row_a[tid] + pl[tid] + pl[64 + tid];

    // ---- PV (transposed) ----
#pragma unroll
    for (int kk = 0; kk < 4; kk++) {
      uint32_t av[2][4];
#pragma unroll
      for (int mt2 = 0; mt2 < 2; mt2++) {
        uint32_t r0v, r1v, r2v, r3v;
        LDMX4T(r0v, r1v, r2v, r3v,
               uV + ((kk * 16 + lrow) * QHLD + w * 32 + mt2 * 16 + lcol8) * 2);
        av[mt2][0] = r0v; av[mt2][1] = r2v;
        av[mt2][2] = r1v; av[mt2][3] = r3v;
      }
#pragma unroll
      for (int nq = 0; nq < 4; nq++) {
        uint32_t r0p, r1p, r2p, r3p;
        LDMX4(r0p, r1p, r2p, r3p,
              uP + ((nq * 16 + lrow) * PHLD + kk * 16 + lcol8) * 2);
        uint32_t b0[2] = {r0p, r2p}, b1[2] = {r1p, r3p};
        mma_f16(oacc[0][2 * nq], av[0], b0);
        mma_f16(oacc[0][2 * nq + 1], av[0], b1);
        mma_f16(oacc[1][2 * nq], av[1], b0);
        mma_f16(oacc[1][2 * nq + 1], av[1], b1);
      }
    }
  }

  // ---- epilogue ----
  __syncthreads();
#pragma unroll
  for (int nq = 0; nq < 8; nq++) {
    const int qc = nq * 8 + 2 * lc;
    const float il0 = 1.0f / row_l[qc];
    const float il1 = 1.0f / row_l[qc + 1];
#pragma unroll
    for (int mt2 = 0; mt2 < 2; mt2++) {
      const int d0 = w * 32 + mt2 * 16 + lr;
      Qs[qc * QHLD + d0] = __float2half(oacc[mt2][nq][0] * il0);
      Qs[(qc + 1) * QHLD + d0] = __float2half(oacc[mt2][nq][1] * il1);
      Qs[qc * QHLD + d0 + 8] = __float2half(oacc[mt2][nq][2] * il0);
      Qs[(qc + 1) * QHLD + d0 + 8] = __float2half(oacc[mt2][nq][3] * il1);
    }
  }
  __syncthreads();
  for (int i = tid; i < 2048; i += 256) {
    int r = i >> 5, g = i & 31;
    uint4 u = *(uint4*)&Qs[r * QHLD + g * 8];
    *(uint4*)&g_oh[(((size_t)(b * S + q0 + r) * H + h) * D) + g * 8] = u;
  }
}

// ---------------- launch ----------------
extern "C" void kernel_launch(void* const* d_in, const int* in_sizes, int n_in,
                              void* d_out, int out_size) {
  const float* hs   = (const float*)d_in[0];
  const float* cosb = (const float*)d_in[1];
  const float* sinb = (const float*)d_in[2];
  const int*   am   = (const int*)d_in[3];
  const float* Wq   = (const float*)d_in[4];
  const float* Wk   = (const float*)d_in[5];
  const float* Wv   = (const float*)d_in[6];
  const float* Wo   = (const float*)d_in[7];
  const float* qw   = (const float*)d_in[8];
  const float* kw   = (const float*)d_in[9];
  float* out = (float*)d_out;

  __half *hsh, *wqkvh, *woh, *qkvh, *oh;
  cudaGetSymbolAddress((void**)&hsh, g_hsh);
  cudaGetSymbolAddress((void**)&wqkvh, g_wqkvh);
  cudaGetSymbolAddress((void**)&woh, g_woh);
  cudaGetSymbolAddress((void**)&qkvh, g_qkvh);
  cudaGetSymbolAddress((void**)&oh, g_oh);

  const int M = B * S;  // 4096

  cudaFuncSetAttribute(gemm_f16<__half>,
                       cudaFuncAttributeMaxDynamicSharedMemorySize, GEMMH_SMEM);
  cudaFuncSetAttribute(gemm_f16<float>,
                       cudaFuncAttributeMaxDynamicSharedMemorySize, GEMMH_SMEM);
  cudaFuncSetAttribute(attn_f16, cudaFuncAttributeMaxDynamicSharedMemorySize,
                       ATTH_SMEM);

  // single fused conversion/packing pass
  cvt_all<<<4096, 256>>>((const float4*)hs, (const float4*)Wo,
                         (const float4*)Wq, (const float4*)Wk,
                         (const float4*)Wv);

  // fused QKV projection (N = 4096), fp16 out
  gemm_f16<__half><<<dim3(4096 / 128, M / 128), 256, GEMMH_SMEM>>>(
      hsh, wqkvh, qkvh, M, 4096, E);

  norm_rope2<<<M, 256>>>(cosb, sinb, qw, kw);

  attn_f16<<<dim3(S / 64, H, B), 256, ATTH_SMEM>>>(am);

  gemm_f16<float><<<dim3(E / 128, M / 128), 256, GEMMH_SMEM>>>(
      oh, woh, out, M, E, E);
}

// round 13
// speedup vs baseline: 32.1365x; 1.0049x over previous
#include <cuda_runtime.h>
#include <cuda_fp16.h>
#include <math.h>
#include <stdint.h>

#define B 2
#define S 2048
#define E 2048
#define H 8
#define KV 4
#define D 256
#define WIN 1024
#define EPS 1e-6f

// ---------------- scratch (device globals; no allocation) ----------------
__device__ __half g_hsh[(size_t)B * S * E];        // 16 MB fp16 hidden
__device__ __half g_wqkvh[(size_t)E * 4096];       // 16 MB packed Wq|Wk|Wv
__device__ __half g_woh[(size_t)H * D * E];        // 8 MB
__device__ __half g_qkvh[(size_t)B * S * 4096];    // 32 MB packed q|k|v
__device__ __half g_oh[(size_t)B * S * H * D];     // 16 MB attn out

// packed column offsets (halves)
#define QOFF 0
#define KOFF 2048
#define VOFF 3072
#define PSTR 4096

// ======================= helpers =========================================
__device__ __forceinline__ uint32_t smem_u32(const void* p) {
  uint32_t a;
  asm("{ .reg .u64 t; cvta.to.shared.u64 t, %1; cvt.u32.u64 %0, t; }"
      : "=r"(a) : "l"(p));
  return a;
}
__device__ __forceinline__ void cpasync16(uint32_t dst, const void* src) {
  asm volatile("cp.async.cg.shared.global [%0], [%1], 16;"
               :: "r"(dst), "l"(src));
}
#define CP_COMMIT() asm volatile("cp.async.commit_group;" ::: "memory")
#define CP_WAIT1() asm volatile("cp.async.wait_group 1;" ::: "memory")
#define CP_WAIT0() asm volatile("cp.async.wait_group 0;" ::: "memory")

__device__ __forceinline__ void mma_f16(float* d, const uint32_t* a,
                                        const uint32_t* b) {
  asm volatile(
      "mma.sync.aligned.m16n8k16.row.col.f32.f16.f16.f32 "
      "{%0,%1,%2,%3},{%4,%5,%6,%7},{%8,%9},{%0,%1,%2,%3};"
      : "+f"(d[0]), "+f"(d[1]), "+f"(d[2]), "+f"(d[3])
      : "r"(a[0]), "r"(a[1]), "r"(a[2]), "r"(a[3]), "r"(b[0]), "r"(b[1]));
}
#define LDMX4(r0, r1, r2, r3, addr)                                        \
  asm volatile("ldmatrix.sync.aligned.m8n8.x4.shared.b16 {%0,%1,%2,%3}, [%4];" \
               : "=r"(r0), "=r"(r1), "=r"(r2), "=r"(r3) : "r"(addr))
#define LDMX4T(r0, r1, r2, r3, addr)                                       \
  asm volatile("ldmatrix.sync.aligned.m8n8.x4.trans.shared.b16 {%0,%1,%2,%3}, [%4];" \
               : "=r"(r0), "=r"(r1), "=r"(r2), "=r"(r3) : "r"(addr))

// -------- ONE fused fp32 -> fp16 conversion/packing pass -----------------
#define HS4 ((B * S * E) / 4)
#define WO4 ((H * D * E) / 4)
#define PW4 (E * 1024)
__global__ __launch_bounds__(256) void cvt_all(
    const float4* __restrict__ hs, const float4* __restrict__ wo,
    const float4* __restrict__ wq, const float4* __restrict__ wk,
    const float4* __restrict__ wv) {
  const int total = HS4 + WO4 + PW4;
  int i = blockIdx.x * blockDim.x + threadIdx.x;
  const int stride = gridDim.x * blockDim.x;
  for (; i < total; i += stride) {
    float4 v;
    uint2* dst;
    if (i < HS4) {
      v = hs[i];
      dst = (uint2*)g_hsh + i;
    } else if (i < HS4 + WO4) {
      int j = i - HS4;
      v = wo[j];
      dst = (uint2*)g_woh + j;
    } else {
      int j = i - HS4 - WO4;
      int row = j >> 10, g = j & 1023;
      if (g < 512)       v = wq[(size_t)row * 512 + g];
      else if (g < 768)  v = wk[(size_t)row * 256 + (g - 512)];
      else               v = wv[(size_t)row * 256 + (g - 768)];
      dst = (uint2*)&g_wqkvh[(size_t)row * PSTR + g * 4];
    }
    __half2 h0 = __floats2half2_rn(v.x, v.y);
    __half2 h1 = __floats2half2_rn(v.z, v.w);
    uint2 u;
    u.x = *reinterpret_cast<uint32_t*>(&h0);
    u.y = *reinterpret_cast<uint32_t*>(&h1);
    *dst = u;
  }
}

// ========= fp16 mma GEMM (cp.async 3-stage + ldmatrix, BK=64) ============
#define AH_LD 72
#define BH_LD 136
#define ASTG_B (128 * AH_LD * 2)
#define BSTG_B (64 * BH_LD * 2)
#define GEMMH_SMEM (3 * (ASTG_B + BSTG_B))

template <typename OutT>
__global__ __launch_bounds__(256, 2) void gemm_f16(
    const __half* __restrict__ A, const __half* __restrict__ Bw,
    OutT* __restrict__ C, int M, int N, int K) {
  extern __shared__ char smc[];
  const uint32_t smbA = smem_u32(smc);
  const uint32_t smbB = smbA + 3 * ASTG_B;

  const int tid = threadIdx.x;
  const int lane = tid & 31;
  const int wid = tid >> 5;
  const int bm = blockIdx.y * 128;
  const int bn = blockIdx.x * 128;
  const int wm = (wid & 3) * 32;
  const int wn = (wid >> 2) * 64;

  const __half* aP0 = A + (size_t)(bm + (tid >> 3)) * K + (tid & 7) * 8;
  const __half* bP0 = Bw + (size_t)(tid >> 4) * N + bn + (tid & 15) * 8;
  const uint32_t aS0 = smbA + ((tid >> 3) * AH_LD + (tid & 7) * 8) * 2;
  const uint32_t bS0 = smbB + ((tid >> 4) * BH_LD + (tid & 15) * 8) * 2;
  const int NC = K >> 6;

#define ISSUE_ONE(st, c, _i)                                                 \
  do {                                                                       \
    cpasync16(aS0 + (st) * ASTG_B + (_i) * (32 * AH_LD * 2),                 \
              aP0 + (c) * 64 + (size_t)(_i) * 32 * K);                       \
    cpasync16(bS0 + (st) * BSTG_B + (_i) * (16 * BH_LD * 2),                 \
              bP0 + (size_t)(c) * 64 * N + (size_t)(_i) * 16 * N);           \
  } while (0)

  const int lrow = lane & 15;
  const int lcol8 = (lane >> 4) * 8;
  const uint32_t aAddr0 = smbA + ((wm + lrow) * AH_LD + lcol8) * 2;
  const uint32_t aAddr1 = smbA + ((wm + 16 + lrow) * AH_LD + lcol8) * 2;
  uint32_t bAddr[4];
#pragma unroll
  for (int nb = 0; nb < 4; nb++)
    bAddr[nb] = smbB + (lrow * BH_LD + wn + nb * 16 + lcol8) * 2;

#pragma unroll
  for (int i = 0; i < 4; i++) ISSUE_ONE(0, 0, i);
  CP_COMMIT();
#pragma unroll
  for (int i = 0; i < 4; i++) ISSUE_ONE(1, 1, i);
  CP_COMMIT();

  float acc[2][8][4] = {};

  for (int c = 0; c < NC; c++) {
    if (c + 1 < NC) CP_WAIT1(); else CP_WAIT0();
    __syncthreads();
    const bool pref = (c + 2 < NC);
    const int st2 = (c + 2) % 3;
    const uint32_t aSt = (c % 3) * ASTG_B;
    const uint32_t bSt = (c % 3) * BSTG_B;
#pragma unroll
    for (int ks = 0; ks < 4; ks++) {
      if (pref) ISSUE_ONE(st2, c + 2, ks);
      uint32_t af[2][4], bf[8][2];
      LDMX4(af[0][0], af[0][1], af[0][2], af[0][3], aAddr0 + aSt + ks * 32);
      LDMX4(af[1][0], af[1][1], af[1][2], af[1][3], aAddr1 + aSt + ks * 32);
#pragma unroll
      for (int nb = 0; nb < 4; nb++) {
        uint32_t r0, r1, r2, r3;
        LDMX4T(r0, r1, r2, r3, bAddr[nb] + bSt + ks * (16 * BH_LD * 2));
        bf[2 * nb][0] = r0; bf[2 * nb][1] = r1;
        bf[2 * nb + 1][0] = r2; bf[2 * nb + 1][1] = r3;
      }
#pragma unroll
      for (int mf = 0; mf < 2; mf++)
#pragma unroll
        for (int nf = 0; nf < 8; nf++)
          mma_f16(acc[mf][nf], af[mf], bf[nf]);
    }
    if (pref) CP_COMMIT();
  }

#pragma unroll
  for (int mf = 0; mf < 2; mf++) {
    const int r0 = bm + wm + mf * 16 + (lane >> 2);
#pragma unroll
    for (int nf = 0; nf < 8; nf++) {
      const int col = bn + wn + nf * 8 + 2 * (lane & 3);
      if constexpr (sizeof(OutT) == 4) {
        float2 v0, v1;
        v0.x = acc[mf][nf][0]; v0.y = acc[mf][nf][1];
        v1.x = acc[mf][nf][2]; v1.y = acc[mf][nf][3];
        *(float2*)&C[(size_t)r0 * N + col] = v0;
        *(float2*)&C[(size_t)(r0 + 8) * N + col] = v1;
      } else {
        *(__half2*)&C[(size_t)r0 * N + col] =
            __floats2half2_rn(acc[mf][nf][0], acc[mf][nf][1]);
        *(__half2*)&C[(size_t)(r0 + 8) * N + col] =
            __floats2half2_rn(acc[mf][nf][2], acc[mf][nf][3]);
      }
    }
  }
}

// -------- fused RMSNorm + RoPE: one block per token row, loop heads ------
__global__ __launch_bounds__(256) void norm_rope2(
    const float* __restrict__ cosb, const float* __restrict__ sinb,
    const float* __restrict__ qw, const float* __restrict__ kw) {
  const int row = blockIdx.x;  // b*S + s
  const int d = threadIdx.x;
  __shared__ float cs[D], sn[D], xs[D], red[8];
  cs[d] = cosb[(size_t)row * D + d];
  sn[d] = sinb[(size_t)row * D + d];
  const float wqv = qw[d];
  const float wkv = kw[d];
  __half* base = &g_qkvh[(size_t)row * PSTR];
#pragma unroll
  for (int hh = 0; hh < H + KV; hh++) {
    __half* ptr = (hh < H) ? (base + QOFF + hh * D)
                           : (base + KOFF + (hh - H) * D);
    const float w = (hh < H) ? wqv : wkv;
    const float osc = (hh < H) ? 0.0625f : 1.0f;
    float v = __half2float(ptr[d]);
    float ss = v * v;
#pragma unroll
    for (int o = 16; o > 0; o >>= 1) ss += __shfl_xor_sync(0xffffffffu, ss, o);
    if ((d & 31) == 0) red[d >> 5] = ss;
    __syncthreads();
    float tot = 0.f;
#pragma unroll
    for (int i = 0; i < 8; i++) tot += red[i];
    float inv = rsqrtf(tot * (1.0f / D) + EPS);
    float xn = v * inv * (1.0f + w);
    xs[d] = xn;
    __syncthreads();
    float rot = (d < D / 2) ? -xs[d + D / 2] : xs[d - D / 2];
    ptr[d] = __float2half((xn * cs[d] + rot * sn[d]) * osc);
    __syncthreads();
  }
}

// ====== fp16 mma flash attention: register softmax state, 4 syncs/iter ===
#define QHLD 264
#define PHLD 72
#define ATTH_SMEM 112640
#define NEGF (-1e30f)

__global__ __launch_bounds__(256, 2) void attn_f16(const int* __restrict__ am) {
  extern __shared__ char smc[];
  __half* Qs = (__half*)smc;            // [64][QHLD]
  __half* Ks = Qs + 64 * QHLD;
  __half* Vs = Ks + 64 * QHLD;
  __half* Ps = Vs + 64 * QHLD;          // [64][PHLD]
  float* row_a = (float*)(smc + 110592);  // [64]
  float* pm = row_a + 64;                 // [2][64]
  float* pl = pm + 128;                   // [2][64]
  int* ams = (int*)(pl + 128);            // [64]

  const uint32_t uQ = smem_u32(Qs);
  const uint32_t uK = smem_u32(Ks);
  const uint32_t uV = smem_u32(Vs);
  const uint32_t uP = smem_u32(Ps);

  const int tid = threadIdx.x;
  const int lane = tid & 31;
  const int w = tid >> 5;
  const int mt = w & 3;
  const int half_ = w >> 2;
  const int lr = lane >> 2;
  const int lc = lane & 3;
  const int lrow = lane & 15;
  const int lcol8 = (lane >> 4) * 8;

  const int q0 = ((int)gridDim.x - 1 - (int)blockIdx.x) * 64;
  const int h = blockIdx.y;
  const int b = blockIdx.z;
  const int hk = h / (H / KV);

  int kb0 = q0 - (WIN - 1);
  if (kb0 < 0) kb0 = 0;
  kb0 &= ~63;
  const int kb_end = q0 + 63;

  // prologue: Q group, then K(kb0) group
  {
    const __half* qsrc = g_qkvh + (size_t)(b * S + q0) * PSTR + QOFF + h * D;
    for (int i = tid; i < 2048; i += 256) {
      int r = i >> 5, g = i & 31;
      cpasync16(uQ + (r * QHLD + g * 8) * 2, qsrc + (size_t)r * PSTR + g * 8);
    }
    CP_COMMIT();  // Q
    const __half* ksrc = g_qkvh + (size_t)(b * S + kb0) * PSTR + KOFF + hk * D;
    for (int i = tid; i < 2048; i += 256) {
      int r = i >> 5, g = i & 31;
      cpasync16(uK + (r * QHLD + g * 8) * 2, ksrc + (size_t)r * PSTR + g * 8);
    }
    CP_COMMIT();  // K(kb0)
  }

  // register softmax state: rows r0 = mt*16+lr, r1 = r0+8
  const int r0 = mt * 16 + lr;
  const int r1 = r0 + 8;
  float m0 = NEGF, m1 = NEGF;  // replicated across quad + both halves
  float l0 = 0.f, l1 = 0.f;    // per-half partial (linear split)

  float oacc[2][8][4] = {};

  for (int kb = kb0; kb <= kb_end; kb += 64) {
    __syncthreads();  // (a) prev PV readers done -> Vs/Ps reusable
    {
      const __half* vsrc = g_qkvh + (size_t)(b * S + kb) * PSTR + VOFF + hk * D;
      for (int i = tid; i < 2048; i += 256) {
        int r = i >> 5, g = i & 31;
        cpasync16(uV + (r * QHLD + g * 8) * 2, vsrc + (size_t)r * PSTR + g * 8);
      }
      CP_COMMIT();  // V(kb)
    }
    if (tid < 64) ams[tid] = am[b * S + kb + tid];
    CP_WAIT1();       // Q + K(kb) ready (V(kb) may be in flight)
    __syncthreads();  // (b)

    // ---- QK^T ----
    float sacc[4][4] = {};
    const uint32_t qa = uQ + ((mt * 16 + lrow) * QHLD + lcol8) * 2;
    const uint32_t ka0 = uK + ((half_ * 32 + lrow) * QHLD + lcol8) * 2;
    const uint32_t ka1 = ka0 + 16 * QHLD * 2;
#pragma unroll
    for (int ks = 0; ks < 16; ks++) {
      uint32_t a[4], t0, t1, t2, t3;
      LDMX4(a[0], a[1], a[2], a[3], qa + ks * 32);
      LDMX4(t0, t1, t2, t3, ka0 + ks * 32);
      {
        uint32_t b0[2] = {t0, t2}, b1[2] = {t1, t3};
        mma_f16(sacc[0], a, b0);
        mma_f16(sacc[1], a, b1);
      }
      LDMX4(t0, t1, t2, t3, ka1 + ks * 32);
      {
        uint32_t b0[2] = {t0, t2}, b1[2] = {t1, t3};
        mma_f16(sacc[2], a, b0);
        mma_f16(sacc[3], a, b1);
      }
    }

    // ---- mask + partial row max ----
    const int qg0 = q0 + r0;
    const int qg1 = q0 + r1;
    float mx0 = NEGF, mx1 = NEGF;
#pragma unroll
    for (int nt = 0; nt < 4; nt++) {
      const int colb = half_ * 32 + nt * 8 + 2 * lc;
#pragma unroll
      for (int j = 0; j < 4; j++) {
        const int col = colb + (j & 1);
        const int kg = kb + col;
        const int qg = (j < 2) ? qg0 : qg1;
        bool ok = (kg <= qg) && (qg - kg < WIN) && (ams[col] != 0);
        float v = ok ? sacc[nt][j] : NEGF;
        sacc[nt][j] = v;
        if (j < 2) mx0 = fmaxf(mx0, v);
        else       mx1 = fmaxf(mx1, v);
      }
    }
    mx0 = fmaxf(mx0, __shfl_xor_sync(0xffffffffu, mx0, 1));
    mx0 = fmaxf(mx0, __shfl_xor_sync(0xffffffffu, mx0, 2));
    mx1 = fmaxf(mx1, __shfl_xor_sync(0xffffffffu, mx1, 1));
    mx1 = fmaxf(mx1, __shfl_xor_sync(0xffffffffu, mx1, 2));
    if (lc == 0) {
      pm[half_ * 64 + r0] = mx0;
      pm[half_ * 64 + r1] = mx1;
    }
    __syncthreads();  // (c) pm visible; all warps past QK -> Ks reusable

    // prefetch K(kb+64) while softmax+PV run
    const bool hasnext = (kb + 64 <= kb_end);
    if (hasnext) {
      const __half* ksrc =
          g_qkvh + (size_t)(b * S + kb + 64) * PSTR + KOFF + hk * D;
      for (int i = tid; i < 2048; i += 256) {
        int r = i >> 5, g = i & 31;
        cpasync16(uK + (r * QHLD + g * 8) * 2, ksrc + (size_t)r * PSTR + g * 8);
      }
      CP_COMMIT();  // K(kb+64)
    }

    // ---- per-thread m/a update (registers; replicated in quad+halves) ----
    const float mn0 = fmaxf(m0, fmaxf(pm[r0], pm[64 + r0]));
    const float mn1 = fmaxf(m1, fmaxf(pm[r1], pm[64 + r1]));
    const float a0 = __expf(m0 - mn0);
    const float a1 = __expf(m1 - mn1);
    m0 = mn0;
    m1 = mn1;
    if (half_ == 0 && lc == 0) {
      row_a[r0] = a0;
      row_a[r1] = a1;
    }

    // ---- P = exp(s-m) -> fp16 Ps; partial sums -> register l ----
    float s0 = 0.f, s1 = 0.f;
#pragma unroll
    for (int nt = 0; nt < 4; nt++) {
      const int colb = half_ * 32 + nt * 8 + 2 * lc;
      float p00 = (sacc[nt][0] < -5e29f) ? 0.f : __expf(sacc[nt][0] - mn0);
      float p01 = (sacc[nt][1] < -5e29f) ? 0.f : __expf(sacc[nt][1] - mn0);
      float p10 = (sacc[nt][2] < -5e29f) ? 0.f : __expf(sacc[nt][2] - mn1);
      float p11 = (sacc[nt][3] < -5e29f) ? 0.f : __expf(sacc[nt][3] - mn1);
      s0 += p00 + p01;
      s1 += p10 + p11;
      *(__half2*)&Ps[r0 * PHLD + colb] = __floats2half2_rn(p00, p01);
      *(__half2*)&Ps[r1 * PHLD + colb] = __floats2half2_rn(p10, p11);
    }
    s0 += __shfl_xor_sync(0xffffffffu, s0, 1);
    s0 += __shfl_xor_sync(0xffffffffu, s0, 2);
    s1 += __shfl_xor_sync(0xffffffffu, s1, 1);
    s1 += __shfl_xor_sync(0xffffffffu, s1, 2);
    l0 = l0 * a0 + s0;  // per-half partial; halves sum at epilogue
    l1 = l1 * a1 + s1;

    if (hasnext) CP_WAIT1(); else CP_WAIT0();  // V(kb) complete
    __syncthreads();  // (d) row_a + Ps + Vs visible

    // ---- rescale oacc with row_a[q-col] ----
#pragma unroll
    for (int nq = 0; nq < 8; nq++) {
      const int qc = nq * 8 + 2 * lc;
      const float ra0 = row_a[qc];
      const float ra1 = row_a[qc + 1];
#pragma unroll
      for (int mt2 = 0; mt2 < 2; mt2++) {
        oacc[mt2][nq][0] *= ra0;
        oacc[mt2][nq][1] *= ra1;
        oacc[mt2][nq][2] *= ra0;
        oacc[mt2][nq][3] *= ra1;
      }
    }

    // ---- PV (transposed) ----
#pragma unroll
    for (int kk = 0; kk < 4; kk++) {
      uint32_t av[2][4];
#pragma unroll
      for (int mt2 = 0; mt2 < 2; mt2++) {
        uint32_t t0, t1, t2, t3;
        LDMX4T(t0, t1, t2, t3,
               uV + ((kk * 16 + lrow) * QHLD + w * 32 + mt2 * 16 + lcol8) * 2);
        av[mt2][0] = t0; av[mt2][1] = t2;
        av[mt2][2] = t1; av[mt2][3] = t3;
      }
#pragma unroll
      for (int nq = 0; nq < 4; nq++) {
        uint32_t t0, t1, t2, t3;
        LDMX4(t0, t1, t2, t3,
              uP + ((nq * 16 + lrow) * PHLD + kk * 16 + lcol8) * 2);
        uint32_t b0[2] = {t0, t2}, b1[2] = {t1, t3};
        mma_f16(oacc[0][2 * nq], av[0], b0);
        mma_f16(oacc[0][2 * nq + 1], av[0], b1);
        mma_f16(oacc[1][2 * nq], av[1], b0);
        mma_f16(oacc[1][2 * nq + 1], av[1], b1);
      }
    }
  }

  // ---- epilogue: combine per-half l, normalize, transpose, store ----
  if (lc == 0) {
    pl[half_ * 64 + r0] = l0;
    pl[half_ * 64 + r1] = l1;
  }
  __syncthreads();
#pragma unroll
  for (int nq = 0; nq < 8; nq++) {
    const int qc = nq * 8 + 2 * lc;
    const float il0 = 1.0f / (pl[qc] + pl[64 + qc]);
    const float il1 = 1.0f / (pl[qc + 1] + pl[64 + qc + 1]);
#pragma unroll
    for (int mt2 = 0; mt2 < 2; mt2++) {
      const int d0 = w * 32 + mt2 * 16 + lr;
      Qs[qc * QHLD + d0] = __float2half(oacc[mt2][nq][0] * il0);
      Qs[(qc + 1) * QHLD + d0] = __float2half(oacc[mt2][nq][1] * il1);
      Qs[qc * QHLD + d0 + 8] = __float2half(oacc[mt2][nq][2] * il0);
      Qs[(qc + 1) * QHLD + d0 + 8] = __float2half(oacc[mt2][nq][3] * il1);
    }
  }
  __syncthreads();
  for (int i = tid; i < 2048; i += 256) {
    int r = i >> 5, g = i & 31;
    uint4 u = *(uint4*)&Qs[r * QHLD + g * 8];
    *(uint4*)&g_oh[(((size_t)(b * S + q0 + r) * H + h) * D) + g * 8] = u;
  }
}

// ---------------- launch ----------------
extern "C" void kernel_launch(void* const* d_in, const int* in_sizes, int n_in,
                              void* d_out, int out_size) {
  const float* hs   = (const float*)d_in[0];
  const float* cosb = (const float*)d_in[1];
  const float* sinb = (const float*)d_in[2];
  const int*   am   = (const int*)d_in[3];
  const float* Wq   = (const float*)d_in[4];
  const float* Wk   = (const float*)d_in[5];
  const float* Wv   = (const float*)d_in[6];
  const float* Wo   = (const float*)d_in[7];
  const float* qw   = (const float*)d_in[8];
  const float* kw   = (const float*)d_in[9];
  float* out = (float*)d_out;

  __half *hsh, *wqkvh, *woh, *qkvh, *oh;
  cudaGetSymbolAddress((void**)&hsh, g_hsh);
  cudaGetSymbolAddress((void**)&wqkvh, g_wqkvh);
  cudaGetSymbolAddress((void**)&woh, g_woh);
  cudaGetSymbolAddress((void**)&qkvh, g_qkvh);
  cudaGetSymbolAddress((void**)&oh, g_oh);

  const int M = B * S;  // 4096

  cudaFuncSetAttribute(gemm_f16<__half>,
                       cudaFuncAttributeMaxDynamicSharedMemorySize, GEMMH_SMEM);
  cudaFuncSetAttribute(gemm_f16<float>,
                       cudaFuncAttributeMaxDynamicSharedMemorySize, GEMMH_SMEM);
  cudaFuncSetAttribute(attn_f16, cudaFuncAttributeMaxDynamicSharedMemorySize,
                       ATTH_SMEM);

  // single fused conversion/packing pass
  cvt_all<<<4096, 256>>>((const float4*)hs, (const float4*)Wo,
                         (const float4*)Wq, (const float4*)Wk,
                         (const float4*)Wv);

  // fused QKV projection (N = 4096), fp16 out
  gemm_f16<__half><<<dim3(4096 / 128, M / 128), 256, GEMMH_SMEM>>>(
      hsh, wqkvh, qkvh, M, 4096, E);

  norm_rope2<<<M, 256>>>(cosb, sinb, qw, kw);

  attn_f16<<<dim3(S / 64, H, B), 256, ATTH_SMEM>>>(am);

  gemm_f16<float><<<dim3(E / 128, M / 128), 256, GEMMH_SMEM>>>(
      oh, woh, out, M, E, E);
}

// round 14
// speedup vs baseline: 35.1604x; 1.0941x over previous
#include <cuda_runtime.h>
#include <cuda_fp16.h>
#include <math.h>
#include <stdint.h>

#define B 2
#define S 2048
#define E 2048
#define H 8
#define KV 4
#define D 256
#define WIN 1024
#define EPS 1e-6f

// ---------------- scratch (device globals; no allocation) ----------------
__device__ __half g_hsh[(size_t)B * S * E];        // 16 MB fp16 hidden
__device__ __half g_wqkvh[(size_t)E * 4096];       // 16 MB packed Wq|Wk|Wv
__device__ __half g_woh[(size_t)H * D * E];        // 8 MB
__device__ __half g_qkvh[(size_t)B * S * 4096];    // 32 MB packed q|k|v
__device__ __half g_oh[(size_t)B * S * H * D];     // 16 MB attn out
__device__ int g_ctr;                              // persistent-tile counter

// packed column offsets (halves)
#define QOFF 0
#define KOFF 2048
#define VOFF 3072
#define PSTR 4096

#define NPERS 304                 // persistent attention CTAs
#define NTILES ((S / 64) * H * B) // 512

// ======================= helpers =========================================
__device__ __forceinline__ uint32_t smem_u32(const void* p) {
  uint32_t a;
  asm("{ .reg .u64 t; cvta.to.shared.u64 t, %1; cvt.u32.u64 %0, t; }"
      : "=r"(a) : "l"(p));
  return a;
}
__device__ __forceinline__ void cpasync16(uint32_t dst, const void* src) {
  asm volatile("cp.async.cg.shared.global [%0], [%1], 16;"
               :: "r"(dst), "l"(src));
}
#define CP_COMMIT() asm volatile("cp.async.commit_group;" ::: "memory")
#define CP_WAIT1() asm volatile("cp.async.wait_group 1;" ::: "memory")
#define CP_WAIT0() asm volatile("cp.async.wait_group 0;" ::: "memory")

__device__ __forceinline__ void mma_f16(float* d, const uint32_t* a,
                                        const uint32_t* b) {
  asm volatile(
      "mma.sync.aligned.m16n8k16.row.col.f32.f16.f16.f32 "
      "{%0,%1,%2,%3},{%4,%5,%6,%7},{%8,%9},{%0,%1,%2,%3};"
      : "+f"(d[0]), "+f"(d[1]), "+f"(d[2]), "+f"(d[3])
      : "r"(a[0]), "r"(a[1]), "r"(a[2]), "r"(a[3]), "r"(b[0]), "r"(b[1]));
}
#define LDMX4(r0, r1, r2, r3, addr)                                        \
  asm volatile("ldmatrix.sync.aligned.m8n8.x4.shared.b16 {%0,%1,%2,%3}, [%4];" \
               : "=r"(r0), "=r"(r1), "=r"(r2), "=r"(r3) : "r"(addr))
#define LDMX4T(r0, r1, r2, r3, addr)                                       \
  asm volatile("ldmatrix.sync.aligned.m8n8.x4.trans.shared.b16 {%0,%1,%2,%3}, [%4];" \
               : "=r"(r0), "=r"(r1), "=r"(r2), "=r"(r3) : "r"(addr))

// -------- ONE fused fp32 -> fp16 conversion/packing pass -----------------
#define HS4 ((B * S * E) / 4)
#define WO4 ((H * D * E) / 4)
#define PW4 (E * 1024)
__global__ __launch_bounds__(256) void cvt_all(
    const float4* __restrict__ hs, const float4* __restrict__ wo,
    const float4* __restrict__ wq, const float4* __restrict__ wk,
    const float4* __restrict__ wv) {
  if (blockIdx.x == 0 && threadIdx.x == 0) g_ctr = NPERS;  // reset scheduler
  const int total = HS4 + WO4 + PW4;
  int i = blockIdx.x * blockDim.x + threadIdx.x;
  const int stride = gridDim.x * blockDim.x;
  for (; i < total; i += stride) {
    float4 v;
    uint2* dst;
    if (i < HS4) {
      v = hs[i];
      dst = (uint2*)g_hsh + i;
    } else if (i < HS4 + WO4) {
      int j = i - HS4;
      v = wo[j];
      dst = (uint2*)g_woh + j;
    } else {
      int j = i - HS4 - WO4;
      int row = j >> 10, g = j & 1023;
      if (g < 512)       v = wq[(size_t)row * 512 + g];
      else if (g < 768)  v = wk[(size_t)row * 256 + (g - 512)];
      else               v = wv[(size_t)row * 256 + (g - 768)];
      dst = (uint2*)&g_wqkvh[(size_t)row * PSTR + g * 4];
    }
    __half2 h0 = __floats2half2_rn(v.x, v.y);
    __half2 h1 = __floats2half2_rn(v.z, v.w);
    uint2 u;
    u.x = *reinterpret_cast<uint32_t*>(&h0);
    u.y = *reinterpret_cast<uint32_t*>(&h1);
    *dst = u;
  }
}

// ========= fp16 mma GEMM (cp.async 3-stage + ldmatrix, BK=64) ============
#define AH_LD 72
#define BH_LD 136
#define ASTG_B (128 * AH_LD * 2)
#define BSTG_B (64 * BH_LD * 2)
#define GEMMH_SMEM (3 * (ASTG_B + BSTG_B))

template <typename OutT>
__global__ __launch_bounds__(256, 2) void gemm_f16(
    const __half* __restrict__ A, const __half* __restrict__ Bw,
    OutT* __restrict__ C, int M, int N, int K) {
  extern __shared__ char smc[];
  const uint32_t smbA = smem_u32(smc);
  const uint32_t smbB = smbA + 3 * ASTG_B;

  const int tid = threadIdx.x;
  const int lane = tid & 31;
  const int wid = tid >> 5;
  const int bm = blockIdx.y * 128;
  const int bn = blockIdx.x * 128;
  const int wm = (wid & 3) * 32;
  const int wn = (wid >> 2) * 64;

  const __half* aP0 = A + (size_t)(bm + (tid >> 3)) * K + (tid & 7) * 8;
  const __half* bP0 = Bw + (size_t)(tid >> 4) * N + bn + (tid & 15) * 8;
  const uint32_t aS0 = smbA + ((tid >> 3) * AH_LD + (tid & 7) * 8) * 2;
  const uint32_t bS0 = smbB + ((tid >> 4) * BH_LD + (tid & 15) * 8) * 2;
  const int NC = K >> 6;

#define ISSUE_ONE(st, c, _i)                                                 \
  do {                                                                       \
    cpasync16(aS0 + (st) * ASTG_B + (_i) * (32 * AH_LD * 2),                 \
              aP0 + (c) * 64 + (size_t)(_i) * 32 * K);                       \
    cpasync16(bS0 + (st) * BSTG_B + (_i) * (16 * BH_LD * 2),                 \
              bP0 + (size_t)(c) * 64 * N + (size_t)(_i) * 16 * N);           \
  } while (0)

  const int lrow = lane & 15;
  const int lcol8 = (lane >> 4) * 8;
  const uint32_t aAddr0 = smbA + ((wm + lrow) * AH_LD + lcol8) * 2;
  const uint32_t aAddr1 = smbA + ((wm + 16 + lrow) * AH_LD + lcol8) * 2;
  uint32_t bAddr[4];
#pragma unroll
  for (int nb = 0; nb < 4; nb++)
    bAddr[nb] = smbB + (lrow * BH_LD + wn + nb * 16 + lcol8) * 2;

#pragma unroll
  for (int i = 0; i < 4; i++) ISSUE_ONE(0, 0, i);
  CP_COMMIT();
#pragma unroll
  for (int i = 0; i < 4; i++) ISSUE_ONE(1, 1, i);
  CP_COMMIT();

  float acc[2][8][4] = {};

  for (int c = 0; c < NC; c++) {
    if (c + 1 < NC) CP_WAIT1(); else CP_WAIT0();
    __syncthreads();
    const bool pref = (c + 2 < NC);
    const int st2 = (c + 2) % 3;
    const uint32_t aSt = (c % 3) * ASTG_B;
    const uint32_t bSt = (c % 3) * BSTG_B;
#pragma unroll
    for (int ks = 0; ks < 4; ks++) {
      if (pref) ISSUE_ONE(st2, c + 2, ks);
      uint32_t af[2][4], bf[8][2];
      LDMX4(af[0][0], af[0][1], af[0][2], af[0][3], aAddr0 + aSt + ks * 32);
      LDMX4(af[1][0], af[1][1], af[1][2], af[1][3], aAddr1 + aSt + ks * 32);
#pragma unroll
      for (int nb = 0; nb < 4; nb++) {
        uint32_t r0, r1, r2, r3;
        LDMX4T(r0, r1, r2, r3, bAddr[nb] + bSt + ks * (16 * BH_LD * 2));
        bf[2 * nb][0] = r0; bf[2 * nb][1] = r1;
        bf[2 * nb + 1][0] = r2; bf[2 * nb + 1][1] = r3;
      }
#pragma unroll
      for (int mf = 0; mf < 2; mf++)
#pragma unroll
        for (int nf = 0; nf < 8; nf++)
          mma_f16(acc[mf][nf], af[mf], bf[nf]);
    }
    if (pref) CP_COMMIT();
  }

#pragma unroll
  for (int mf = 0; mf < 2; mf++) {
    const int r0 = bm + wm + mf * 16 + (lane >> 2);
#pragma unroll
    for (int nf = 0; nf < 8; nf++) {
      const int col = bn + wn + nf * 8 + 2 * (lane & 3);
      if constexpr (sizeof(OutT) == 4) {
        float2 v0, v1;
        v0.x = acc[mf][nf][0]; v0.y = acc[mf][nf][1];
        v1.x = acc[mf][nf][2]; v1.y = acc[mf][nf][3];
        *(float2*)&C[(size_t)r0 * N + col] = v0;
        *(float2*)&C[(size_t)(r0 + 8) * N + col] = v1;
      } else {
        *(__half2*)&C[(size_t)r0 * N + col] =
            __floats2half2_rn(acc[mf][nf][0], acc[mf][nf][1]);
        *(__half2*)&C[(size_t)(r0 + 8) * N + col] =
            __floats2half2_rn(acc[mf][nf][2], acc[mf][nf][3]);
      }
    }
  }
}

// -------- fused RMSNorm + RoPE: one block per token row, loop heads ------
__global__ __launch_bounds__(256) void norm_rope2(
    const float* __restrict__ cosb, const float* __restrict__ sinb,
    const float* __restrict__ qw, const float* __restrict__ kw) {
  const int row = blockIdx.x;  // b*S + s
  const int d = threadIdx.x;
  __shared__ float cs[D], sn[D], xs[D], red[8];
  cs[d] = cosb[(size_t)row * D + d];
  sn[d] = sinb[(size_t)row * D + d];
  const float wqv = qw[d];
  const float wkv = kw[d];
  __half* base = &g_qkvh[(size_t)row * PSTR];
#pragma unroll
  for (int hh = 0; hh < H + KV; hh++) {
    __half* ptr = (hh < H) ? (base + QOFF + hh * D)
                           : (base + KOFF + (hh - H) * D);
    const float w = (hh < H) ? wqv : wkv;
    const float osc = (hh < H) ? 0.0625f : 1.0f;
    float v = __half2float(ptr[d]);
    float ss = v * v;
#pragma unroll
    for (int o = 16; o > 0; o >>= 1) ss += __shfl_xor_sync(0xffffffffu, ss, o);
    if ((d & 31) == 0) red[d >> 5] = ss;
    __syncthreads();
    float tot = 0.f;
#pragma unroll
    for (int i = 0; i < 8; i++) tot += red[i];
    float inv = rsqrtf(tot * (1.0f / D) + EPS);
    float xn = v * inv * (1.0f + w);
    xs[d] = xn;
    __syncthreads();
    float rot = (d < D / 2) ? -xs[d + D / 2] : xs[d - D / 2];
    ptr[d] = __float2half((xn * cs[d] + rot * sn[d]) * osc);
    __syncthreads();
  }
}

// == persistent fp16 mma flash attention: dynamic tiles + interior path ===
#define QHLD 264
#define PHLD 72
#define ATTH_SMEM 112640
#define NEGF (-1e30f)

__global__ __launch_bounds__(256, 2) void attn_f16(const int* __restrict__ am) {
  extern __shared__ char smc[];
  __half* Qs = (__half*)smc;            // [64][QHLD]
  __half* Ks = Qs + 64 * QHLD;
  __half* Vs = Ks + 64 * QHLD;
  __half* Ps = Vs + 64 * QHLD;          // [64][PHLD]
  float* row_a = (float*)(smc + 110592);  // [64]
  float* pm = row_a + 64;                 // [2][64]
  float* pl = pm + 128;                   // [2][64]
  int* ams = (int*)(pl + 128);            // [64]
  int* nxt = ams + 64;                    // [1]

  const uint32_t uQ = smem_u32(Qs);
  const uint32_t uK = smem_u32(Ks);
  const uint32_t uV = smem_u32(Vs);
  const uint32_t uP = smem_u32(Ps);

  const int tid = threadIdx.x;
  const int lane = tid & 31;
  const int w = tid >> 5;
  const int mt = w & 3;
  const int half_ = w >> 2;
  const int lr = lane >> 2;
  const int lc = lane & 3;
  const int lrow = lane & 15;
  const int lcol8 = (lane >> 4) * 8;

  const int r0 = mt * 16 + lr;
  const int r1 = r0 + 8;

  int tile = blockIdx.x;
  while (tile < NTILES) {
    // decode: longest q-tiles first
    const int qi = 31 - (tile >> 4);
    const int h = (tile >> 1) & 7;
    const int b = tile & 1;
    const int q0 = qi * 64;
    const int hk = h / (H / KV);

    int kb0 = q0 - (WIN - 1);
    if (kb0 < 0) kb0 = 0;
    kb0 &= ~63;
    const int kb_end = q0 + 63;

    // prologue: Q group, then K(kb0) group
    {
      const __half* qsrc = g_qkvh + (size_t)(b * S + q0) * PSTR + QOFF + h * D;
      for (int i = tid; i < 2048; i += 256) {
        int r = i >> 5, g = i & 31;
        cpasync16(uQ + (r * QHLD + g * 8) * 2, qsrc + (size_t)r * PSTR + g * 8);
      }
      CP_COMMIT();  // Q
      const __half* ksrc = g_qkvh + (size_t)(b * S + kb0) * PSTR + KOFF + hk * D;
      for (int i = tid; i < 2048; i += 256) {
        int r = i >> 5, g = i & 31;
        cpasync16(uK + (r * QHLD + g * 8) * 2, ksrc + (size_t)r * PSTR + g * 8);
      }
      CP_COMMIT();  // K(kb0)
    }

    float m0 = NEGF, m1 = NEGF;
    float l0 = 0.f, l1 = 0.f;
    float oacc[2][8][4] = {};

    for (int kb = kb0; kb <= kb_end; kb += 64) {
      __syncthreads();  // (a) prev PV readers done -> Vs/Ps reusable
      {
        const __half* vsrc =
            g_qkvh + (size_t)(b * S + kb) * PSTR + VOFF + hk * D;
        for (int i = tid; i < 2048; i += 256) {
          int r = i >> 5, g = i & 31;
          cpasync16(uV + (r * QHLD + g * 8) * 2,
                    vsrc + (size_t)r * PSTR + g * 8);
        }
        CP_COMMIT();  // V(kb)
      }
      int padok = 1;
      if (tid < 64) {
        int v = am[b * S + kb + tid];
        ams[tid] = v;
        padok = (v != 0);
      }
      CP_WAIT1();  // Q + K(kb) ready (V(kb) may be in flight)
      const int allpad = __syncthreads_and(padok);  // (b) barrier + pad flag
      const bool interior =
          allpad && (kb + 63 <= q0) && (kb >= q0 + 64 - WIN);

      // ---- QK^T ----
      float sacc[4][4] = {};
      const uint32_t qa = uQ + ((mt * 16 + lrow) * QHLD + lcol8) * 2;
      const uint32_t ka0 = uK + ((half_ * 32 + lrow) * QHLD + lcol8) * 2;
      const uint32_t ka1 = ka0 + 16 * QHLD * 2;
#pragma unroll
      for (int ks = 0; ks < 16; ks++) {
        uint32_t a[4], t0, t1, t2, t3;
        LDMX4(a[0], a[1], a[2], a[3], qa + ks * 32);
        LDMX4(t0, t1, t2, t3, ka0 + ks * 32);
        {
          uint32_t b0[2] = {t0, t2}, b1[2] = {t1, t3};
          mma_f16(sacc[0], a, b0);
          mma_f16(sacc[1], a, b1);
        }
        LDMX4(t0, t1, t2, t3, ka1 + ks * 32);
        {
          uint32_t b0[2] = {t0, t2}, b1[2] = {t1, t3};
          mma_f16(sacc[2], a, b0);
          mma_f16(sacc[3], a, b1);
        }
      }

      // ---- mask (boundary only) + partial row max ----
      float mx0 = NEGF, mx1 = NEGF;
      if (interior) {
#pragma unroll
        for (int nt = 0; nt < 4; nt++) {
          mx0 = fmaxf(mx0, fmaxf(sacc[nt][0], sacc[nt][1]));
          mx1 = fmaxf(mx1, fmaxf(sacc[nt][2], sacc[nt][3]));
        }
      } else {
        const int qg0 = q0 + r0;
        const int qg1 = q0 + r1;
#pragma unroll
        for (int nt = 0; nt < 4; nt++) {
          const int colb = half_ * 32 + nt * 8 + 2 * lc;
#pragma unroll
          for (int j = 0; j < 4; j++) {
            const int col = colb + (j & 1);
            const int kg = kb + col;
            const int qg = (j < 2) ? qg0 : qg1;
            bool ok = (kg <= qg) && (qg - kg < WIN) && (ams[col] != 0);
            float v = ok ? sacc[nt][j] : NEGF;
            sacc[nt][j] = v;
            if (j < 2) mx0 = fmaxf(mx0, v);
            else       mx1 = fmaxf(mx1, v);
          }
        }
      }
      mx0 = fmaxf(mx0, __shfl_xor_sync(0xffffffffu, mx0, 1));
      mx0 = fmaxf(mx0, __shfl_xor_sync(0xffffffffu, mx0, 2));
      mx1 = fmaxf(mx1, __shfl_xor_sync(0xffffffffu, mx1, 1));
      mx1 = fmaxf(mx1, __shfl_xor_sync(0xffffffffu, mx1, 2));
      if (lc == 0) {
        pm[half_ * 64 + r0] = mx0;
        pm[half_ * 64 + r1] = mx1;
      }
      __syncthreads();  // (c) pm visible; all warps past QK -> Ks reusable

      // prefetch K(kb+64) while softmax+PV run
      const bool hasnext = (kb + 64 <= kb_end);
      if (hasnext) {
        const __half* ksrc =
            g_qkvh + (size_t)(b * S + kb + 64) * PSTR + KOFF + hk * D;
        for (int i = tid; i < 2048; i += 256) {
          int r = i >> 5, g = i & 31;
          cpasync16(uK + (r * QHLD + g * 8) * 2,
                    ksrc + (size_t)r * PSTR + g * 8);
        }
        CP_COMMIT();  // K(kb+64)
      }

      // ---- per-thread m/a update ----
      const float mn0 = fmaxf(m0, fmaxf(pm[r0], pm[64 + r0]));
      const float mn1 = fmaxf(m1, fmaxf(pm[r1], pm[64 + r1]));
      const float a0 = __expf(m0 - mn0);
      const float a1 = __expf(m1 - mn1);
      m0 = mn0;
      m1 = mn1;
      if (half_ == 0 && lc == 0) {
        row_a[r0] = a0;
        row_a[r1] = a1;
      }

      // ---- P = exp(s-m) -> fp16 Ps; partial sums -> register l ----
      float s0 = 0.f, s1 = 0.f;
      if (interior) {
#pragma unroll
        for (int nt = 0; nt < 4; nt++) {
          const int colb = half_ * 32 + nt * 8 + 2 * lc;
          float p00 = __expf(sacc[nt][0] - mn0);
          float p01 = __expf(sacc[nt][1] - mn0);
          float p10 = __expf(sacc[nt][2] - mn1);
          float p11 = __expf(sacc[nt][3] - mn1);
          s0 += p00 + p01;
          s1 += p10 + p11;
          *(__half2*)&Ps[r0 * PHLD + colb] = __floats2half2_rn(p00, p01);
          *(__half2*)&Ps[r1 * PHLD + colb] = __floats2half2_rn(p10, p11);
        }
      } else {
#pragma unroll
        for (int nt = 0; nt < 4; nt++) {
          const int colb = half_ * 32 + nt * 8 + 2 * lc;
          float p00 = (sacc[nt][0] < -5e29f) ? 0.f : __expf(sacc[nt][0] - mn0);
          float p01 = (sacc[nt][1] < -5e29f) ? 0.f : __expf(sacc[nt][1] - mn0);
          float p10 = (sacc[nt][2] < -5e29f) ? 0.f : __expf(sacc[nt][2] - mn1);
          float p11 = (sacc[nt][3] < -5e29f) ? 0.f : __expf(sacc[nt][3] - mn1);
          s0 += p00 + p01;
          s1 += p10 + p11;
          *(__half2*)&Ps[r0 * PHLD + colb] = __floats2half2_rn(p00, p01);
          *(__half2*)&Ps[r1 * PHLD + colb] = __floats2half2_rn(p10, p11);
        }
      }
      s0 += __shfl_xor_sync(0xffffffffu, s0, 1);
      s0 += __shfl_xor_sync(0xffffffffu, s0, 2);
      s1 += __shfl_xor_sync(0xffffffffu, s1, 1);
      s1 += __shfl_xor_sync(0xffffffffu, s1, 2);
      l0 = l0 * a0 + s0;
      l1 = l1 * a1 + s1;

      if (hasnext) CP_WAIT1(); else CP_WAIT0();  // V(kb) complete
      __syncthreads();  // (d) row_a + Ps + Vs visible

      // ---- rescale oacc with row_a[q-col] ----
#pragma unroll
      for (int nq = 0; nq < 8; nq++) {
        const int qc = nq * 8 + 2 * lc;
        const float ra0 = row_a[qc];
        const float ra1 = row_a[qc + 1];
#pragma unroll
        for (int mt2 = 0; mt2 < 2; mt2++) {
          oacc[mt2][nq][0] *= ra0;
          oacc[mt2][nq][1] *= ra1;
          oacc[mt2][nq][2] *= ra0;
          oacc[mt2][nq][3] *= ra1;
        }
      }

      // ---- PV (transposed) ----
#pragma unroll
      for (int kk = 0; kk < 4; kk++) {
        uint32_t av[2][4];
#pragma unroll
        for (int mt2 = 0; mt2 < 2; mt2++) {
          uint32_t t0, t1, t2, t3;
          LDMX4T(t0, t1, t2, t3,
                 uV + ((kk * 16 + lrow) * QHLD + w * 32 + mt2 * 16 + lcol8) * 2);
          av[mt2][0] = t0; av[mt2][1] = t2;
          av[mt2][2] = t1; av[mt2][3] = t3;
        }
#pragma unroll
        for (int nq = 0; nq < 4; nq++) {
          uint32_t t0, t1, t2, t3;
          LDMX4(t0, t1, t2, t3,
                uP + ((nq * 16 + lrow) * PHLD + kk * 16 + lcol8) * 2);
          uint32_t b0[2] = {t0, t2}, b1[2] = {t1, t3};
          mma_f16(oacc[0][2 * nq], av[0], b0);
          mma_f16(oacc[0][2 * nq + 1], av[0], b1);
          mma_f16(oacc[1][2 * nq], av[1], b0);
          mma_f16(oacc[1][2 * nq + 1], av[1], b1);
        }
      }
    }

    // ---- epilogue: combine per-half l, normalize, transpose, store ----
    if (lc == 0) {
      pl[half_ * 64 + r0] = l0;
      pl[half_ * 64 + r1] = l1;
    }
    __syncthreads();
#pragma unroll
    for (int nq = 0; nq < 8; nq++) {
      const int qc = nq * 8 + 2 * lc;
      const float il0 = 1.0f / (pl[qc] + pl[64 + qc]);
      const float il1 = 1.0f / (pl[qc + 1] + pl[64 + qc + 1]);
#pragma unroll
      for (int mt2 = 0; mt2 < 2; mt2++) {
        const int d0 = w * 32 + mt2 * 16 + lr;
        Qs[qc * QHLD + d0] = __float2half(oacc[mt2][nq][0] * il0);
        Qs[(qc + 1) * QHLD + d0] = __float2half(oacc[mt2][nq][1] * il1);
        Qs[qc * QHLD + d0 + 8] = __float2half(oacc[mt2][nq][2] * il0);
        Qs[(qc + 1) * QHLD + d0 + 8] = __float2half(oacc[mt2][nq][3] * il1);
      }
    }
    __syncthreads();
    for (int i = tid; i < 2048; i += 256) {
      int r = i >> 5, g = i & 31;
      uint4 u = *(uint4*)&Qs[r * QHLD + g * 8];
      *(uint4*)&g_oh[(((size_t)(b * S + q0 + r) * H + h) * D) + g * 8] = u;
    }

    // ---- claim next tile ----
    __syncthreads();  // epilogue reads of Qs done before next Q load
    if (tid == 0) *nxt = atomicAdd(&g_ctr, 1);
    __syncthreads();
    tile = *nxt;
  }
}

// ---------------- launch ----------------
extern "C" void kernel_launch(void* const* d_in, const int* in_sizes, int n_in,
                              void* d_out, int out_size) {
  const float* hs   = (const float*)d_in[0];
  const float* cosb = (const float*)d_in[1];
  const float* sinb = (const float*)d_in[2];
  const int*   am   = (const int*)d_in[3];
  const float* Wq   = (const float*)d_in[4];
  const float* Wk   = (const float*)d_in[5];
  const float* Wv   = (const float*)d_in[6];
  const float* Wo   = (const float*)d_in[7];
  const float* qw   = (const float*)d_in[8];
  const float* kw   = (const float*)d_in[9];
  float* out = (float*)d_out;

  __half *hsh, *wqkvh, *woh, *qkvh, *oh;
  cudaGetSymbolAddress((void**)&hsh, g_hsh);
  cudaGetSymbolAddress((void**)&wqkvh, g_wqkvh);
  cudaGetSymbolAddress((void**)&woh, g_woh);
  cudaGetSymbolAddress((void**)&qkvh, g_qkvh);
  cudaGetSymbolAddress((void**)&oh, g_oh);

  const int M = B * S;  // 4096

  cudaFuncSetAttribute(gemm_f16<__half>,
                       cudaFuncAttributeMaxDynamicSharedMemorySize, GEMMH_SMEM);
  cudaFuncSetAttribute(gemm_f16<float>,
                       cudaFuncAttributeMaxDynamicSharedMemorySize, GEMMH_SMEM);
  cudaFuncSetAttribute(attn_f16, cudaFuncAttributeMaxDynamicSharedMemorySize,
                       ATTH_SMEM);

  // single fused conversion/packing pass (also resets tile counter)
  cvt_all<<<4096, 256>>>((const float4*)hs, (const float4*)Wo,
                         (const float4*)Wq, (const float4*)Wk,
                         (const float4*)Wv);

  // fused QKV projection (N = 4096), fp16 out
  gemm_f16<__half><<<dim3(4096 / 128, M / 128), 256, GEMMH_SMEM>>>(
      hsh, wqkvh, qkvh, M, 4096, E);

  norm_rope2<<<M, 256>>>(cosb, sinb, qw, kw);

  attn_f16<<<NPERS, 256, ATTH_SMEM>>>(am);

  gemm_f16<float><<<dim3(E / 128, M / 128), 256, GEMMH_SMEM>>>(
      oh, woh, out, M, E, E);
}

// round 15
// speedup vs baseline: 36.5220x; 1.0387x over previous
#include <cuda_runtime.h>
#include <cuda_fp16.h>
#include <math.h>
#include <stdint.h>

#define B 2
#define S 2048
#define E 2048
#define H 8
#define KV 4
#define D 256
#define WIN 1024
#define EPS 1e-6f

// ---------------- scratch (device globals; no allocation) ----------------
__device__ __half g_hsh[(size_t)B * S * E];        // 16 MB fp16 hidden
__device__ __half g_wqkvh[(size_t)E * 4096];       // 16 MB packed Wq|Wk|Wv
__device__ __half g_woh[(size_t)H * D * E];        // 8 MB
__device__ __half g_qkvh[(size_t)B * S * 4096];    // 32 MB packed q|k|v
__device__ __half g_oh[(size_t)B * S * H * D];     // 16 MB attn out
__device__ int g_ctr;                              // persistent-tile counter

// packed column offsets (halves)
#define QOFF 0
#define KOFF 2048
#define VOFF 3072
#define PSTR 4096

#define NPERS 304                 // persistent attention CTAs
#define NTILES ((S / 64) * H * B) // 512

// ======================= helpers =========================================
__device__ __forceinline__ uint32_t smem_u32(const void* p) {
  uint32_t a;
  asm("{ .reg .u64 t; cvta.to.shared.u64 t, %1; cvt.u32.u64 %0, t; }"
      : "=r"(a) : "l"(p));
  return a;
}
__device__ __forceinline__ void cpasync16(uint32_t dst, const void* src) {
  asm volatile("cp.async.cg.shared.global [%0], [%1], 16;"
               :: "r"(dst), "l"(src));
}
#define CP_COMMIT() asm volatile("cp.async.commit_group;" ::: "memory")
#define CP_WAIT1() asm volatile("cp.async.wait_group 1;" ::: "memory")
#define CP_WAIT0() asm volatile("cp.async.wait_group 0;" ::: "memory")

__device__ __forceinline__ void mma_f16(float* d, const uint32_t* a,
                                        const uint32_t* b) {
  asm volatile(
      "mma.sync.aligned.m16n8k16.row.col.f32.f16.f16.f32 "
      "{%0,%1,%2,%3},{%4,%5,%6,%7},{%8,%9},{%0,%1,%2,%3};"
      : "+f"(d[0]), "+f"(d[1]), "+f"(d[2]), "+f"(d[3])
      : "r"(a[0]), "r"(a[1]), "r"(a[2]), "r"(a[3]), "r"(b[0]), "r"(b[1]));
}
#define LDMX4(r0, r1, r2, r3, addr)                                        \
  asm volatile("ldmatrix.sync.aligned.m8n8.x4.shared.b16 {%0,%1,%2,%3}, [%4];" \
               : "=r"(r0), "=r"(r1), "=r"(r2), "=r"(r3) : "r"(addr))
#define LDMX4T(r0, r1, r2, r3, addr)                                       \
  asm volatile("ldmatrix.sync.aligned.m8n8.x4.trans.shared.b16 {%0,%1,%2,%3}, [%4];" \
               : "=r"(r0), "=r"(r1), "=r"(r2), "=r"(r3) : "r"(addr))

// -------- ONE fused fp32 -> fp16 conversion/packing pass -----------------
#define HS4 ((B * S * E) / 4)
#define WO4 ((H * D * E) / 4)
#define PW4 (E * 1024)
__global__ __launch_bounds__(256) void cvt_all(
    const float4* __restrict__ hs, const float4* __restrict__ wo,
    const float4* __restrict__ wq, const float4* __restrict__ wk,
    const float4* __restrict__ wv) {
  if (blockIdx.x == 0 && threadIdx.x == 0) g_ctr = NPERS;  // reset scheduler
  const int total = HS4 + WO4 + PW4;
  int i = blockIdx.x * blockDim.x + threadIdx.x;
  const int stride = gridDim.x * blockDim.x;
  for (; i < total; i += stride) {
    float4 v;
    uint2* dst;
    if (i < HS4) {
      v = hs[i];
      dst = (uint2*)g_hsh + i;
    } else if (i < HS4 + WO4) {
      int j = i - HS4;
      v = wo[j];
      dst = (uint2*)g_woh + j;
    } else {
      int j = i - HS4 - WO4;
      int row = j >> 10, g = j & 1023;
      if (g < 512)       v = wq[(size_t)row * 512 + g];
      else if (g < 768)  v = wk[(size_t)row * 256 + (g - 512)];
      else               v = wv[(size_t)row * 256 + (g - 768)];
      dst = (uint2*)&g_wqkvh[(size_t)row * PSTR + g * 4];
    }
    __half2 h0 = __floats2half2_rn(v.x, v.y);
    __half2 h1 = __floats2half2_rn(v.z, v.w);
    uint2 u;
    u.x = *reinterpret_cast<uint32_t*>(&h0);
    u.y = *reinterpret_cast<uint32_t*>(&h1);
    *dst = u;
  }
}

// ========= fp16 mma GEMM (cp.async 3-stage + ldmatrix, BK=64) ============
#define AH_LD 72
#define BH_LD 136
#define ASTG_B (128 * AH_LD * 2)
#define BSTG_B (64 * BH_LD * 2)
#define GEMMH_SMEM (3 * (ASTG_B + BSTG_B))

template <typename OutT>
__global__ __launch_bounds__(256, 2) void gemm_f16(
    const __half* __restrict__ A, const __half* __restrict__ Bw,
    OutT* __restrict__ C, int M, int N, int K) {
  extern __shared__ char smc[];
  const uint32_t smbA = smem_u32(smc);
  const uint32_t smbB = smbA + 3 * ASTG_B;

  const int tid = threadIdx.x;
  const int lane = tid & 31;
  const int wid = tid >> 5;
  const int bm = blockIdx.y * 128;
  const int bn = blockIdx.x * 128;
  const int wm = (wid & 3) * 32;
  const int wn = (wid >> 2) * 64;

  const __half* aP0 = A + (size_t)(bm + (tid >> 3)) * K + (tid & 7) * 8;
  const __half* bP0 = Bw + (size_t)(tid >> 4) * N + bn + (tid & 15) * 8;
  const uint32_t aS0 = smbA + ((tid >> 3) * AH_LD + (tid & 7) * 8) * 2;
  const uint32_t bS0 = smbB + ((tid >> 4) * BH_LD + (tid & 15) * 8) * 2;
  const int NC = K >> 6;

#define ISSUE_ONE(st, c, _i)                                                 \
  do {                                                                       \
    cpasync16(aS0 + (st) * ASTG_B + (_i) * (32 * AH_LD * 2),                 \
              aP0 + (c) * 64 + (size_t)(_i) * 32 * K);                       \
    cpasync16(bS0 + (st) * BSTG_B + (_i) * (16 * BH_LD * 2),                 \
              bP0 + (size_t)(c) * 64 * N + (size_t)(_i) * 16 * N);           \
  } while (0)

  const int lrow = lane & 15;
  const int lcol8 = (lane >> 4) * 8;
  const uint32_t aAddr0 = smbA + ((wm + lrow) * AH_LD + lcol8) * 2;
  const uint32_t aAddr1 = smbA + ((wm + 16 + lrow) * AH_LD + lcol8) * 2;
  uint32_t bAddr[4];
#pragma unroll
  for (int nb = 0; nb < 4; nb++)
    bAddr[nb] = smbB + (lrow * BH_LD + wn + nb * 16 + lcol8) * 2;

#pragma unroll
  for (int i = 0; i < 4; i++) ISSUE_ONE(0, 0, i);
  CP_COMMIT();
#pragma unroll
  for (int i = 0; i < 4; i++) ISSUE_ONE(1, 1, i);
  CP_COMMIT();

  float acc[2][8][4] = {};

  for (int c = 0; c < NC; c++) {
    if (c + 1 < NC) CP_WAIT1(); else CP_WAIT0();
    __syncthreads();
    const bool pref = (c + 2 < NC);
    const int st2 = (c + 2) % 3;
    const uint32_t aSt = (c % 3) * ASTG_B;
    const uint32_t bSt = (c % 3) * BSTG_B;
#pragma unroll
    for (int ks = 0; ks < 4; ks++) {
      if (pref) ISSUE_ONE(st2, c + 2, ks);
      uint32_t af[2][4], bf[8][2];
      LDMX4(af[0][0], af[0][1], af[0][2], af[0][3], aAddr0 + aSt + ks * 32);
      LDMX4(af[1][0], af[1][1], af[1][2], af[1][3], aAddr1 + aSt + ks * 32);
#pragma unroll
      for (int nb = 0; nb < 4; nb++) {
        uint32_t r0, r1, r2, r3;
        LDMX4T(r0, r1, r2, r3, bAddr[nb] + bSt + ks * (16 * BH_LD * 2));
        bf[2 * nb][0] = r0; bf[2 * nb][1] = r1;
        bf[2 * nb + 1][0] = r2; bf[2 * nb + 1][1] = r3;
      }
#pragma unroll
      for (int mf = 0; mf < 2; mf++)
#pragma unroll
        for (int nf = 0; nf < 8; nf++)
          mma_f16(acc[mf][nf], af[mf], bf[nf]);
    }
    if (pref) CP_COMMIT();
  }

#pragma unroll
  for (int mf = 0; mf < 2; mf++) {
    const int r0 = bm + wm + mf * 16 + (lane >> 2);
#pragma unroll
    for (int nf = 0; nf < 8; nf++) {
      const int col = bn + wn + nf * 8 + 2 * (lane & 3);
      if constexpr (sizeof(OutT) == 4) {
        float2 v0, v1;
        v0.x = acc[mf][nf][0]; v0.y = acc[mf][nf][1];
        v1.x = acc[mf][nf][2]; v1.y = acc[mf][nf][3];
        *(float2*)&C[(size_t)r0 * N + col] = v0;
        *(float2*)&C[(size_t)(r0 + 8) * N + col] = v1;
      } else {
        *(__half2*)&C[(size_t)r0 * N + col] =
            __floats2half2_rn(acc[mf][nf][0], acc[mf][nf][1]);
        *(__half2*)&C[(size_t)(r0 + 8) * N + col] =
            __floats2half2_rn(acc[mf][nf][2], acc[mf][nf][3]);
      }
    }
  }
}

// ---- warp-parallel RMSNorm + RoPE: one warp per (token, head) -----------
// Lane owns 8 contiguous elements (uint4 of halves). RMS via shfl reduce.
// RoPE partner of element p is p^128 == same slot in lane^16.
__global__ __launch_bounds__(256) void norm_rope3(
    const float* __restrict__ cosb, const float* __restrict__ sinb,
    const float* __restrict__ qw, const float* __restrict__ kw) {
  const int gw = blockIdx.x * 8 + (threadIdx.x >> 5);  // global warp id
  const int lane = threadIdx.x & 31;
  const int row = gw / (H + KV);
  const int hh = gw - row * (H + KV);

  __half* ptr;
  const float* wv;
  float osc;
  if (hh < H) {
    ptr = &g_qkvh[(size_t)row * PSTR + QOFF + hh * D];
    wv = qw; osc = 0.0625f;
  } else {
    ptr = &g_qkvh[(size_t)row * PSTR + KOFF + (hh - H) * D];
    wv = kw; osc = 1.0f;
  }
  const int p0 = lane * 8;

  // load 8 halves
  uint4 raw = *(const uint4*)&ptr[p0];
  __half2 h01 = *(__half2*)&raw.x;
  __half2 h23 = *(__half2*)&raw.y;
  __half2 h45 = *(__half2*)&raw.z;
  __half2 h67 = *(__half2*)&raw.w;
  float x[8];
  x[0] = __half2float(h01.x); x[1] = __half2float(h01.y);
  x[2] = __half2float(h23.x); x[3] = __half2float(h23.y);
  x[4] = __half2float(h45.x); x[5] = __half2float(h45.y);
  x[6] = __half2float(h67.x); x[7] = __half2float(h67.y);

  float ss = 0.f;
#pragma unroll
  for (int j = 0; j < 8; j++) ss += x[j] * x[j];
#pragma unroll
  for (int o = 16; o > 0; o >>= 1) ss += __shfl_xor_sync(0xffffffffu, ss, o);
  const float inv = rsqrtf(ss * (1.0f / D) + EPS);

  float4 w0 = *(const float4*)&wv[p0];
  float4 w1 = *(const float4*)&wv[p0 + 4];
  float xn[8];
  xn[0] = x[0] * inv * (1.0f + w0.x);
  xn[1] = x[1] * inv * (1.0f + w0.y);
  xn[2] = x[2] * inv * (1.0f + w0.z);
  xn[3] = x[3] * inv * (1.0f + w0.w);
  xn[4] = x[4] * inv * (1.0f + w1.x);
  xn[5] = x[5] * inv * (1.0f + w1.y);
  xn[6] = x[6] * inv * (1.0f + w1.z);
  xn[7] = x[7] * inv * (1.0f + w1.w);

  const float* cb = &cosb[(size_t)row * D + p0];
  const float* sb = &sinb[(size_t)row * D + p0];
  float4 c0 = *(const float4*)cb;
  float4 c1 = *(const float4*)(cb + 4);
  float4 s0 = *(const float4*)sb;
  float4 s1 = *(const float4*)(sb + 4);
  const float cs[8] = {c0.x, c0.y, c0.z, c0.w, c1.x, c1.y, c1.z, c1.w};
  const float sn[8] = {s0.x, s0.y, s0.z, s0.w, s1.x, s1.y, s1.z, s1.w};

  const float rsgn = (lane < 16) ? -1.0f : 1.0f;
  float o[8];
#pragma unroll
  for (int j = 0; j < 8; j++) {
    float other = __shfl_xor_sync(0xffffffffu, xn[j], 16);
    o[j] = (xn[j] * cs[j] + rsgn * other * sn[j]) * osc;
  }
  uint4 out;
  __half2 t;
  t = __floats2half2_rn(o[0], o[1]); out.x = *(uint32_t*)&t;
  t = __floats2half2_rn(o[2], o[3]); out.y = *(uint32_t*)&t;
  t = __floats2half2_rn(o[4], o[5]); out.z = *(uint32_t*)&t;
  t = __floats2half2_rn(o[6], o[7]); out.w = *(uint32_t*)&t;
  *(uint4*)&ptr[p0] = out;
}

// == persistent fp16 mma flash attention: dynamic tiles + interior path ===
#define QHLD 264
#define PHLD 72
#define ATTH_SMEM 112640
#define NEGF (-1e30f)

__global__ __launch_bounds__(256, 2) void attn_f16(const int* __restrict__ am) {
  extern __shared__ char smc[];
  __half* Qs = (__half*)smc;            // [64][QHLD]
  __half* Ks = Qs + 64 * QHLD;
  __half* Vs = Ks + 64 * QHLD;
  __half* Ps = Vs + 64 * QHLD;          // [64][PHLD]
  float* row_a = (float*)(smc + 110592);  // [64]
  float* pm = row_a + 64;                 // [2][64]
  float* pl = pm + 128;                   // [2][64]
  int* ams = (int*)(pl + 128);            // [64]
  int* nxt = ams + 64;                    // [1]

  const uint32_t uQ = smem_u32(Qs);
  const uint32_t uK = smem_u32(Ks);
  const uint32_t uV = smem_u32(Vs);
  const uint32_t uP = smem_u32(Ps);

  const int tid = threadIdx.x;
  const int lane = tid & 31;
  const int w = tid >> 5;
  const int mt = w & 3;
  const int half_ = w >> 2;
  const int lr = lane >> 2;
  const int lc = lane & 3;
  const int lrow = lane & 15;
  const int lcol8 = (lane >> 4) * 8;

  const int r0 = mt * 16 + lr;
  const int r1 = r0 + 8;

  int tile = blockIdx.x;
  while (tile < NTILES) {
    const int qi = 31 - (tile >> 4);
    const int h = (tile >> 1) & 7;
    const int b = tile & 1;
    const int q0 = qi * 64;
    const int hk = h / (H / KV);

    int kb0 = q0 - (WIN - 1);
    if (kb0 < 0) kb0 = 0;
    kb0 &= ~63;
    const int kb_end = q0 + 63;

    // prologue: Q group, then K(kb0) group
    {
      const __half* qsrc = g_qkvh + (size_t)(b * S + q0) * PSTR + QOFF + h * D;
      for (int i = tid; i < 2048; i += 256) {
        int r = i >> 5, g = i & 31;
        cpasync16(uQ + (r * QHLD + g * 8) * 2, qsrc + (size_t)r * PSTR + g * 8);
      }
      CP_COMMIT();  // Q
      const __half* ksrc = g_qkvh + (size_t)(b * S + kb0) * PSTR + KOFF + hk * D;
      for (int i = tid; i < 2048; i += 256) {
        int r = i >> 5, g = i & 31;
        cpasync16(uK + (r * QHLD + g * 8) * 2, ksrc + (size_t)r * PSTR + g * 8);
      }
      CP_COMMIT();  // K(kb0)
    }

    float m0 = NEGF, m1 = NEGF;
    float l0 = 0.f, l1 = 0.f;
    float oacc[2][8][4] = {};

    for (int kb = kb0; kb <= kb_end; kb += 64) {
      __syncthreads();  // (a) prev PV readers done -> Vs/Ps reusable
      {
        const __half* vsrc =
            g_qkvh + (size_t)(b * S + kb) * PSTR + VOFF + hk * D;
        for (int i = tid; i < 2048; i += 256) {
          int r = i >> 5, g = i & 31;
          cpasync16(uV + (r * QHLD + g * 8) * 2,
                    vsrc + (size_t)r * PSTR + g * 8);
        }
        CP_COMMIT();  // V(kb)
      }
      int padok = 1;
      if (tid < 64) {
        int v = am[b * S + kb + tid];
        ams[tid] = v;
        padok = (v != 0);
      }
      CP_WAIT1();  // Q + K(kb) ready (V(kb) may be in flight)
      const int allpad = __syncthreads_and(padok);  // (b)
      const bool interior =
          allpad && (kb + 63 <= q0) && (kb >= q0 + 64 - WIN);

      // ---- QK^T ----
      float sacc[4][4] = {};
      const uint32_t qa = uQ + ((mt * 16 + lrow) * QHLD + lcol8) * 2;
      const uint32_t ka0 = uK + ((half_ * 32 + lrow) * QHLD + lcol8) * 2;
      const uint32_t ka1 = ka0 + 16 * QHLD * 2;
#pragma unroll
      for (int ks = 0; ks < 16; ks++) {
        uint32_t a[4], t0, t1, t2, t3;
        LDMX4(a[0], a[1], a[2], a[3], qa + ks * 32);
        LDMX4(t0, t1, t2, t3, ka0 + ks * 32);
        {
          uint32_t b0[2] = {t0, t2}, b1[2] = {t1, t3};
          mma_f16(sacc[0], a, b0);
          mma_f16(sacc[1], a, b1);
        }
        LDMX4(t0, t1, t2, t3, ka1 + ks * 32);
        {
          uint32_t b0[2] = {t0, t2}, b1[2] = {t1, t3};
          mma_f16(sacc[2], a, b0);
          mma_f16(sacc[3], a, b1);
        }
      }

      // ---- mask (boundary only) + partial row max ----
      float mx0 = NEGF, mx1 = NEGF;
      if (interior) {
#pragma unroll
        for (int nt = 0; nt < 4; nt++) {
          mx0 = fmaxf(mx0, fmaxf(sacc[nt][0], sacc[nt][1]));
          mx1 = fmaxf(mx1, fmaxf(sacc[nt][2], sacc[nt][3]));
        }
      } else {
        const int qg0 = q0 + r0;
        const int qg1 = q0 + r1;
#pragma unroll
        for (int nt = 0; nt < 4; nt++) {
          const int colb = half_ * 32 + nt * 8 + 2 * lc;
#pragma unroll
          for (int j = 0; j < 4; j++) {
            const int col = colb + (j & 1);
            const int kg = kb + col;
            const int qg = (j < 2) ? qg0 : qg1;
            bool ok = (kg <= qg) && (qg - kg < WIN) && (ams[col] != 0);
            float v = ok ? sacc[nt][j] : NEGF;
            sacc[nt][j] = v;
            if (j < 2) mx0 = fmaxf(mx0, v);
            else       mx1 = fmaxf(mx1, v);
          }
        }
      }
      mx0 = fmaxf(mx0, __shfl_xor_sync(0xffffffffu, mx0, 1));
      mx0 = fmaxf(mx0, __shfl_xor_sync(0xffffffffu, mx0, 2));
      mx1 = fmaxf(mx1, __shfl_xor_sync(0xffffffffu, mx1, 1));
      mx1 = fmaxf(mx1, __shfl_xor_sync(0xffffffffu, mx1, 2));
      if (lc == 0) {
        pm[half_ * 64 + r0] = mx0;
        pm[half_ * 64 + r1] = mx1;
      }
      __syncthreads();  // (c) pm visible; all warps past QK -> Ks reusable

      const bool hasnext = (kb + 64 <= kb_end);
      if (hasnext) {
        const __half* ksrc =
            g_qkvh + (size_t)(b * S + kb + 64) * PSTR + KOFF + hk * D;
        for (int i = tid; i < 2048; i += 256) {
          int r = i >> 5, g = i & 31;
          cpasync16(uK + (r * QHLD + g * 8) * 2,
                    ksrc + (size_t)r * PSTR + g * 8);
        }
        CP_COMMIT();  // K(kb+64)
      }

      const float mn0 = fmaxf(m0, fmaxf(pm[r0], pm[64 + r0]));
      const float mn1 = fmaxf(m1, fmaxf(pm[r1], pm[64 + r1]));
      const float a0 = __expf(m0 - mn0);
      const float a1 = __expf(m1 - mn1);
      m0 = mn0;
      m1 = mn1;
      if (half_ == 0 && lc == 0) {
        row_a[r0] = a0;
        row_a[r1] = a1;
      }

      float s0 = 0.f, s1 = 0.f;
      if (interior) {
#pragma unroll
        for (int nt = 0; nt < 4; nt++) {
          const int colb = half_ * 32 + nt * 8 + 2 * lc;
          float p00 = __expf(sacc[nt][0] - mn0);
          float p01 = __expf(sacc[nt][1] - mn0);
          float p10 = __expf(sacc[nt][2] - mn1);
          float p11 = __expf(sacc[nt][3] - mn1);
          s0 += p00 + p01;
          s1 += p10 + p11;
          *(__half2*)&Ps[r0 * PHLD + colb] = __floats2half2_rn(p00, p01);
          *(__half2*)&Ps[r1 * PHLD + colb] = __floats2half2_rn(p10, p11);
        }
      } else {
#pragma unroll
        for (int nt = 0; nt < 4; nt++) {
          const int colb = half_ * 32 + nt * 8 + 2 * lc;
          float p00 = (sacc[nt][0] < -5e29f) ? 0.f : __expf(sacc[nt][0] - mn0);
          float p01 = (sacc[nt][1] < -5e29f) ? 0.f : __expf(sacc[nt][1] - mn0);
          float p10 = (sacc[nt][2] < -5e29f) ? 0.f : __expf(sacc[nt][2] - mn1);
          float p11 = (sacc[nt][3] < -5e29f) ? 0.f : __expf(sacc[nt][3] - mn1);
          s0 += p00 + p01;
          s1 += p10 + p11;
          *(__half2*)&Ps[r0 * PHLD + colb] = __floats2half2_rn(p00, p01);
          *(__half2*)&Ps[r1 * PHLD + colb] = __floats2half2_rn(p10, p11);
        }
      }
      s0 += __shfl_xor_sync(0xffffffffu, s0, 1);
      s0 += __shfl_xor_sync(0xffffffffu, s0, 2);
      s1 += __shfl_xor_sync(0xffffffffu, s1, 1);
      s1 += __shfl_xor_sync(0xffffffffu, s1, 2);
      l0 = l0 * a0 + s0;
      l1 = l1 * a1 + s1;

      if (hasnext) CP_WAIT1(); else CP_WAIT0();  // V(kb) complete
      __syncthreads();  // (d) row_a + Ps + Vs visible

#pragma unroll
      for (int nq = 0; nq < 8; nq++) {
        const int qc = nq * 8 + 2 * lc;
        const float ra0 = row_a[qc];
        const float ra1 = row_a[qc + 1];
#pragma unroll
        for (int mt2 = 0; mt2 < 2; mt2++) {
          oacc[mt2][nq][0] *= ra0;
          oacc[mt2][nq][1] *= ra1;
          oacc[mt2][nq][2] *= ra0;
          oacc[mt2][nq][3] *= ra1;
        }
      }

#pragma unroll
      for (int kk = 0; kk < 4; kk++) {
        uint32_t av[2][4];
#pragma unroll
        for (int mt2 = 0; mt2 < 2; mt2++) {
          uint32_t t0, t1, t2, t3;
          LDMX4T(t0, t1, t2, t3,
                 uV + ((kk * 16 + lrow) * QHLD + w * 32 + mt2 * 16 + lcol8) * 2);
          av[mt2][0] = t0; av[mt2][1] = t2;
          av[mt2][2] = t1; av[mt2][3] = t3;
        }
#pragma unroll
        for (int nq = 0; nq < 4; nq++) {
          uint32_t t0, t1, t2, t3;
          LDMX4(t0, t1, t2, t3,
                uP + ((nq * 16 + lrow) * PHLD + kk * 16 + lcol8) * 2);
          uint32_t b0[2] = {t0, t2}, b1[2] = {t1, t3};
          mma_f16(oacc[0][2 * nq], av[0], b0);
          mma_f16(oacc[0][2 * nq + 1], av[0], b1);
          mma_f16(oacc[1][2 * nq], av[1], b0);
          mma_f16(oacc[1][2 * nq + 1], av[1], b1);
        }
      }
    }

    // ---- epilogue ----
    if (lc == 0) {
      pl[half_ * 64 + r0] = l0;
      pl[half_ * 64 + r1] = l1;
    }
    __syncthreads();
#pragma unroll
    for (int nq = 0; nq < 8; nq++) {
      const int qc = nq * 8 + 2 * lc;
      const float il0 = 1.0f / (pl[qc] + pl[64 + qc]);
      const float il1 = 1.0f / (pl[qc + 1] + pl[64 + qc + 1]);
#pragma unroll
      for (int mt2 = 0; mt2 < 2; mt2++) {
        const int d0 = w * 32 + mt2 * 16 + lr;
        Qs[qc * QHLD + d0] = __float2half(oacc[mt2][nq][0] * il0);
        Qs[(qc + 1) * QHLD + d0] = __float2half(oacc[mt2][nq][1] * il1);
        Qs[qc * QHLD + d0 + 8] = __float2half(oacc[mt2][nq][2] * il0);
        Qs[(qc + 1) * QHLD + d0 + 8] = __float2half(oacc[mt2][nq][3] * il1);
      }
    }
    __syncthreads();
    for (int i = tid; i < 2048; i += 256) {
      int r = i >> 5, g = i & 31;
      uint4 u = *(uint4*)&Qs[r * QHLD + g * 8];
      *(uint4*)&g_oh[(((size_t)(b * S + q0 + r) * H + h) * D) + g * 8] = u;
    }

    __syncthreads();
    if (tid == 0) *nxt = atomicAdd(&g_ctr, 1);
    __syncthreads();
    tile = *nxt;
  }
}

// ---------------- launch ----------------
extern "C" void kernel_launch(void* const* d_in, const int* in_sizes, int n_in,
                              void* d_out, int out_size) {
  const float* hs   = (const float*)d_in[0];
  const float* cosb = (const float*)d_in[1];
  const float* sinb = (const float*)d_in[2];
  const int*   am   = (const int*)d_in[3];
  const float* Wq   = (const float*)d_in[4];
  const float* Wk   = (const float*)d_in[5];
  const float* Wv   = (const float*)d_in[6];
  const float* Wo   = (const float*)d_in[7];
  const float* qw   = (const float*)d_in[8];
  const float* kw   = (const float*)d_in[9];
  float* out = (float*)d_out;

  __half *hsh, *wqkvh, *woh, *qkvh, *oh;
  cudaGetSymbolAddress((void**)&hsh, g_hsh);
  cudaGetSymbolAddress((void**)&wqkvh, g_wqkvh);
  cudaGetSymbolAddress((void**)&woh, g_woh);
  cudaGetSymbolAddress((void**)&qkvh, g_qkvh);
  cudaGetSymbolAddress((void**)&oh, g_oh);

  const int M = B * S;  // 4096

  cudaFuncSetAttribute(gemm_f16<__half>,
                       cudaFuncAttributeMaxDynamicSharedMemorySize, GEMMH_SMEM);
  cudaFuncSetAttribute(gemm_f16<float>,
                       cudaFuncAttributeMaxDynamicSharedMemorySize, GEMMH_SMEM);
  cudaFuncSetAttribute(attn_f16, cudaFuncAttributeMaxDynamicSharedMemorySize,
                       ATTH_SMEM);

  // single fused conversion/packing pass (also resets tile counter)
  cvt_all<<<4096, 256>>>((const float4*)hs, (const float4*)Wo,
                         (const float4*)Wq, (const float4*)Wk,
                         (const float4*)Wv);

  // fused QKV projection (N = 4096), fp16 out
  gemm_f16<__half><<<dim3(4096 / 128, M / 128), 256, GEMMH_SMEM>>>(
      hsh, wqkvh, qkvh, M, 4096, E);

  // warp-parallel norm+rope: one warp per (token, head); 49152 warps
  norm_rope3<<<(M * (H + KV)) / 8, 256>>>(cosb, sinb, qw, kw);

  attn_f16<<<NPERS, 256, ATTH_SMEM>>>(am);

  gemm_f16<float><<<dim3(E / 128, M / 128), 256, GEMMH_SMEM>>>(
      oh, woh, out, M, E, E);
}

// round 16
// speedup vs baseline: 36.5383x; 1.0004x over previous
#include <cuda_runtime.h>
#include <cuda_fp16.h>
#include <math.h>
#include <stdint.h>

#define B 2
#define S 2048
#define E 2048
#define H 8
#define KV 4
#define D 256
#define WIN 1024
#define EPS 1e-6f

// ---------------- scratch (device globals; no allocation) ----------------
__device__ __half g_hsh[(size_t)B * S * E];        // 16 MB fp16 hidden
__device__ __half g_wqkvh[(size_t)E * 4096];       // 16 MB packed Wq|Wk|Wv
__device__ __half g_woh[(size_t)H * D * E];        // 8 MB
__device__ __half g_qkvh[(size_t)B * S * 4096];    // 32 MB packed q|k|v
__device__ __half g_oh[(size_t)B * S * H * D];     // 16 MB attn out
__device__ int g_ctr;                              // persistent-tile counter

// packed column offsets (halves)
#define QOFF 0
#define KOFF 2048
#define VOFF 3072
#define PSTR 4096

#define NPERS 296                 // persistent attention CTAs (2 x 148 SMs)
#define NTILES ((S / 64) * H * B) // 512

// ======================= helpers =========================================
__device__ __forceinline__ uint32_t smem_u32(const void* p) {
  uint32_t a;
  asm("{ .reg .u64 t; cvta.to.shared.u64 t, %1; cvt.u32.u64 %0, t; }"
      : "=r"(a) : "l"(p));
  return a;
}
__device__ __forceinline__ void cpasync16(uint32_t dst, const void* src) {
  asm volatile("cp.async.cg.shared.global [%0], [%1], 16;"
               :: "r"(dst), "l"(src));
}
#define CP_COMMIT() asm volatile("cp.async.commit_group;" ::: "memory")
#define CP_WAIT1() asm volatile("cp.async.wait_group 1;" ::: "memory")
#define CP_WAIT0() asm volatile("cp.async.wait_group 0;" ::: "memory")

__device__ __forceinline__ void mma_f16(float* d, const uint32_t* a,
                                        const uint32_t* b) {
  asm volatile(
      "mma.sync.aligned.m16n8k16.row.col.f32.f16.f16.f32 "
      "{%0,%1,%2,%3},{%4,%5,%6,%7},{%8,%9},{%0,%1,%2,%3};"
      : "+f"(d[0]), "+f"(d[1]), "+f"(d[2]), "+f"(d[3])
      : "r"(a[0]), "r"(a[1]), "r"(a[2]), "r"(a[3]), "r"(b[0]), "r"(b[1]));
}
#define LDMX4(r0, r1, r2, r3, addr)                                        \
  asm volatile("ldmatrix.sync.aligned.m8n8.x4.shared.b16 {%0,%1,%2,%3}, [%4];" \
               : "=r"(r0), "=r"(r1), "=r"(r2), "=r"(r3) : "r"(addr))
#define LDMX4T(r0, r1, r2, r3, addr)                                       \
  asm volatile("ldmatrix.sync.aligned.m8n8.x4.trans.shared.b16 {%0,%1,%2,%3}, [%4];" \
               : "=r"(r0), "=r"(r1), "=r"(r2), "=r"(r3) : "r"(addr))

// fp16x2 exp2: one MUFU for two values; input packed half2
__device__ __forceinline__ uint32_t h2ex2(uint32_t x) {
  uint32_t r;
  asm("ex2.approx.f16x2 %0, %1;" : "=r"(r) : "r"(x));
  return r;
}
#define LOG2E 1.4426950408889634f

// -------- ONE fused fp32 -> fp16 conversion/packing pass -----------------
#define HS4 ((B * S * E) / 4)
#define WO4 ((H * D * E) / 4)
#define PW4 (E * 1024)
__global__ __launch_bounds__(256) void cvt_all(
    const float4* __restrict__ hs, const float4* __restrict__ wo,
    const float4* __restrict__ wq, const float4* __restrict__ wk,
    const float4* __restrict__ wv) {
  if (blockIdx.x == 0 && threadIdx.x == 0) g_ctr = NPERS;  // reset scheduler
  const int total = HS4 + WO4 + PW4;
  int i = blockIdx.x * blockDim.x + threadIdx.x;
  const int stride = gridDim.x * blockDim.x;
  for (; i < total; i += stride) {
    float4 v;
    uint2* dst;
    if (i < HS4) {
      v = hs[i];
      dst = (uint2*)g_hsh + i;
    } else if (i < HS4 + WO4) {
      int j = i - HS4;
      v = wo[j];
      dst = (uint2*)g_woh + j;
    } else {
      int j = i - HS4 - WO4;
      int row = j >> 10, g = j & 1023;
      if (g < 512)       v = wq[(size_t)row * 512 + g];
      else if (g < 768)  v = wk[(size_t)row * 256 + (g - 512)];
      else               v = wv[(size_t)row * 256 + (g - 768)];
      dst = (uint2*)&g_wqkvh[(size_t)row * PSTR + g * 4];
    }
    __half2 h0 = __floats2half2_rn(v.x, v.y);
    __half2 h1 = __floats2half2_rn(v.z, v.w);
    uint2 u;
    u.x = *reinterpret_cast<uint32_t*>(&h0);
    u.y = *reinterpret_cast<uint32_t*>(&h1);
    *dst = u;
  }
}

// ========= fp16 mma GEMM (cp.async 3-stage + ldmatrix, BK=64) ============
#define AH_LD 72
#define BH_LD 136
#define ASTG_B (128 * AH_LD * 2)
#define BSTG_B (64 * BH_LD * 2)
#define GEMMH_SMEM (3 * (ASTG_B + BSTG_B))

template <typename OutT>
__global__ __launch_bounds__(256, 2) void gemm_f16(
    const __half* __restrict__ A, const __half* __restrict__ Bw,
    OutT* __restrict__ C, int M, int N, int K) {
  extern __shared__ char smc[];
  const uint32_t smbA = smem_u32(smc);
  const uint32_t smbB = smbA + 3 * ASTG_B;

  const int tid = threadIdx.x;
  const int lane = tid & 31;
  const int wid = tid >> 5;
  const int bm = blockIdx.y * 128;
  const int bn = blockIdx.x * 128;
  const int wm = (wid & 3) * 32;
  const int wn = (wid >> 2) * 64;

  const __half* aP0 = A + (size_t)(bm + (tid >> 3)) * K + (tid & 7) * 8;
  const __half* bP0 = Bw + (size_t)(tid >> 4) * N + bn + (tid & 15) * 8;
  const uint32_t aS0 = smbA + ((tid >> 3) * AH_LD + (tid & 7) * 8) * 2;
  const uint32_t bS0 = smbB + ((tid >> 4) * BH_LD + (tid & 15) * 8) * 2;
  const int NC = K >> 6;

#define ISSUE_ONE(st, c, _i)                                                 \
  do {                                                                       \
    cpasync16(aS0 + (st) * ASTG_B + (_i) * (32 * AH_LD * 2),                 \
              aP0 + (c) * 64 + (size_t)(_i) * 32 * K);                       \
    cpasync16(bS0 + (st) * BSTG_B + (_i) * (16 * BH_LD * 2),                 \
              bP0 + (size_t)(c) * 64 * N + (size_t)(_i) * 16 * N);           \
  } while (0)

  const int lrow = lane & 15;
  const int lcol8 = (lane >> 4) * 8;
  const uint32_t aAddr0 = smbA + ((wm + lrow) * AH_LD + lcol8) * 2;
  const uint32_t aAddr1 = smbA + ((wm + 16 + lrow) * AH_LD + lcol8) * 2;
  uint32_t bAddr[4];
#pragma unroll
  for (int nb = 0; nb < 4; nb++)
    bAddr[nb] = smbB + (lrow * BH_LD + wn + nb * 16 + lcol8) * 2;

#pragma unroll
  for (int i = 0; i < 4; i++) ISSUE_ONE(0, 0, i);
  CP_COMMIT();
#pragma unroll
  for (int i = 0; i < 4; i++) ISSUE_ONE(1, 1, i);
  CP_COMMIT();

  float acc[2][8][4] = {};

  for (int c = 0; c < NC; c++) {
    if (c + 1 < NC) CP_WAIT1(); else CP_WAIT0();
    __syncthreads();
    const bool pref = (c + 2 < NC);
    const int st2 = (c + 2) % 3;
    const uint32_t aSt = (c % 3) * ASTG_B;
    const uint32_t bSt = (c % 3) * BSTG_B;
#pragma unroll
    for (int ks = 0; ks < 4; ks++) {
      if (pref) ISSUE_ONE(st2, c + 2, ks);
      uint32_t af[2][4], bf[8][2];
      LDMX4(af[0][0], af[0][1], af[0][2], af[0][3], aAddr0 + aSt + ks * 32);
      LDMX4(af[1][0], af[1][1], af[1][2], af[1][3], aAddr1 + aSt + ks * 32);
#pragma unroll
      for (int nb = 0; nb < 4; nb++) {
        uint32_t r0, r1, r2, r3;
        LDMX4T(r0, r1, r2, r3, bAddr[nb] + bSt + ks * (16 * BH_LD * 2));
        bf[2 * nb][0] = r0; bf[2 * nb][1] = r1;
        bf[2 * nb + 1][0] = r2; bf[2 * nb + 1][1] = r3;
      }
#pragma unroll
      for (int mf = 0; mf < 2; mf++)
#pragma unroll
        for (int nf = 0; nf < 8; nf++)
          mma_f16(acc[mf][nf], af[mf], bf[nf]);
    }
    if (pref) CP_COMMIT();
  }

#pragma unroll
  for (int mf = 0; mf < 2; mf++) {
    const int r0 = bm + wm + mf * 16 + (lane >> 2);
#pragma unroll
    for (int nf = 0; nf < 8; nf++) {
      const int col = bn + wn + nf * 8 + 2 * (lane & 3);
      if constexpr (sizeof(OutT) == 4) {
        float2 v0, v1;
        v0.x = acc[mf][nf][0]; v0.y = acc[mf][nf][1];
        v1.x = acc[mf][nf][2]; v1.y = acc[mf][nf][3];
        *(float2*)&C[(size_t)r0 * N + col] = v0;
        *(float2*)&C[(size_t)(r0 + 8) * N + col] = v1;
      } else {
        *(__half2*)&C[(size_t)r0 * N + col] =
            __floats2half2_rn(acc[mf][nf][0], acc[mf][nf][1]);
        *(__half2*)&C[(size_t)(r0 + 8) * N + col] =
            __floats2half2_rn(acc[mf][nf][2], acc[mf][nf][3]);
      }
    }
  }
}

// ---- warp-parallel RMSNorm + RoPE: one warp per (token, head) -----------
__global__ __launch_bounds__(256) void norm_rope3(
    const float* __restrict__ cosb, const float* __restrict__ sinb,
    const float* __restrict__ qw, const float* __restrict__ kw) {
  const int gw = blockIdx.x * 8 + (threadIdx.x >> 5);  // global warp id
  const int lane = threadIdx.x & 31;
  const int row = gw / (H + KV);
  const int hh = gw - row * (H + KV);

  __half* ptr;
  const float* wv;
  float osc;
  if (hh < H) {
    ptr = &g_qkvh[(size_t)row * PSTR + QOFF + hh * D];
    wv = qw; osc = 0.0625f;
  } else {
    ptr = &g_qkvh[(size_t)row * PSTR + KOFF + (hh - H) * D];
    wv = kw; osc = 1.0f;
  }
  const int p0 = lane * 8;

  uint4 raw = *(const uint4*)&ptr[p0];
  __half2 h01 = *(__half2*)&raw.x;
  __half2 h23 = *(__half2*)&raw.y;
  __half2 h45 = *(__half2*)&raw.z;
  __half2 h67 = *(__half2*)&raw.w;
  float x[8];
  x[0] = __half2float(h01.x); x[1] = __half2float(h01.y);
  x[2] = __half2float(h23.x); x[3] = __half2float(h23.y);
  x[4] = __half2float(h45.x); x[5] = __half2float(h45.y);
  x[6] = __half2float(h67.x); x[7] = __half2float(h67.y);

  float ss = 0.f;
#pragma unroll
  for (int j = 0; j < 8; j++) ss += x[j] * x[j];
#pragma unroll
  for (int o = 16; o > 0; o >>= 1) ss += __shfl_xor_sync(0xffffffffu, ss, o);
  const float inv = rsqrtf(ss * (1.0f / D) + EPS);

  float4 w0 = *(const float4*)&wv[p0];
  float4 w1 = *(const float4*)&wv[p0 + 4];
  float xn[8];
  xn[0] = x[0] * inv * (1.0f + w0.x);
  xn[1] = x[1] * inv * (1.0f + w0.y);
  xn[2] = x[2] * inv * (1.0f + w0.z);
  xn[3] = x[3] * inv * (1.0f + w0.w);
  xn[4] = x[4] * inv * (1.0f + w1.x);
  xn[5] = x[5] * inv * (1.0f + w1.y);
  xn[6] = x[6] * inv * (1.0f + w1.z);
  xn[7] = x[7] * inv * (1.0f + w1.w);

  const float* cb = &cosb[(size_t)row * D + p0];
  const float* sb = &sinb[(size_t)row * D + p0];
  float4 c0 = *(const float4*)cb;
  float4 c1 = *(const float4*)(cb + 4);
  float4 s0 = *(const float4*)sb;
  float4 s1 = *(const float4*)(sb + 4);
  const float cs[8] = {c0.x, c0.y, c0.z, c0.w, c1.x, c1.y, c1.z, c1.w};
  const float sn[8] = {s0.x, s0.y, s0.z, s0.w, s1.x, s1.y, s1.z, s1.w};

  const float rsgn = (lane < 16) ? -1.0f : 1.0f;
  float o[8];
#pragma unroll
  for (int j = 0; j < 8; j++) {
    float other = __shfl_xor_sync(0xffffffffu, xn[j], 16);
    o[j] = (xn[j] * cs[j] + rsgn * other * sn[j]) * osc;
  }
  uint4 out;
  __half2 t;
  t = __floats2half2_rn(o[0], o[1]); out.x = *(uint32_t*)&t;
  t = __floats2half2_rn(o[2], o[3]); out.y = *(uint32_t*)&t;
  t = __floats2half2_rn(o[4], o[5]); out.z = *(uint32_t*)&t;
  t = __floats2half2_rn(o[6], o[7]); out.w = *(uint32_t*)&t;
  *(uint4*)&ptr[p0] = out;
}

// == persistent fp16 mma flash attention: dynamic tiles + f16x2 exp ======
#define QHLD 264
#define PHLD 72
#define ATTH_SMEM 112640
#define NEGF (-1e30f)

__global__ __launch_bounds__(256, 2) void attn_f16(const int* __restrict__ am) {
  extern __shared__ char smc[];
  __half* Qs = (__half*)smc;            // [64][QHLD]
  __half* Ks = Qs + 64 * QHLD;
  __half* Vs = Ks + 64 * QHLD;
  __half* Ps = Vs + 64 * QHLD;          // [64][PHLD]
  float* row_a = (float*)(smc + 110592);  // [64]
  float* pm = row_a + 64;                 // [2][64]
  float* pl = pm + 128;                   // [2][64]
  int* ams = (int*)(pl + 128);            // [64]
  int* nxt = ams + 64;                    // [1]

  const uint32_t uQ = smem_u32(Qs);
  const uint32_t uK = smem_u32(Ks);
  const uint32_t uV = smem_u32(Vs);
  const uint32_t uP = smem_u32(Ps);

  const int tid = threadIdx.x;
  const int lane = tid & 31;
  const int w = tid >> 5;
  const int mt = w & 3;
  const int half_ = w >> 2;
  const int lr = lane >> 2;
  const int lc = lane & 3;
  const int lrow = lane & 15;
  const int lcol8 = (lane >> 4) * 8;

  const int r0 = mt * 16 + lr;
  const int r1 = r0 + 8;

  // hoisted staging addressing: row = w + 8j, granule = lane
  const uint32_t stDst = (uint32_t)(w * QHLD + lane * 8) * 2;
  const size_t stSrc = (size_t)w * PSTR + lane * 8;
#define STAGE8(uBase, sPtr)                                           \
  do {                                                                \
    uint32_t _d = (uBase) + stDst;                                    \
    const __half* _s = (sPtr) + stSrc;                                \
    _Pragma("unroll") for (int _j = 0; _j < 8; _j++) {                \
      cpasync16(_d, _s);                                              \
      _d += 8 * QHLD * 2;                                             \
      _s += (size_t)8 * PSTR;                                         \
    }                                                                 \
  } while (0)

  int tile = blockIdx.x;
  while (tile < NTILES) {
    const int qi = 31 - (tile >> 4);
    const int h = (tile >> 1) & 7;
    const int b = tile & 1;
    const int q0 = qi * 64;
    const int hk = h / (H / KV);

    int kb0 = q0 - (WIN - 1);
    if (kb0 < 0) kb0 = 0;
    kb0 &= ~63;
    const int kb_end = q0 + 63;

    // prologue: Q group, then K(kb0) group
    STAGE8(uQ, g_qkvh + (size_t)(b * S + q0) * PSTR + QOFF + h * D);
    CP_COMMIT();  // Q
    STAGE8(uK, g_qkvh + (size_t)(b * S + kb0) * PSTR + KOFF + hk * D);
    CP_COMMIT();  // K(kb0)

    float m0 = NEGF, m1 = NEGF;
    float l0 = 0.f, l1 = 0.f;
    float oacc[2][8][4] = {};

    for (int kb = kb0; kb <= kb_end; kb += 64) {
      __syncthreads();  // (a) prev PV readers done -> Vs/Ps reusable
      STAGE8(uV, g_qkvh + (size_t)(b * S + kb) * PSTR + VOFF + hk * D);
      CP_COMMIT();  // V(kb)
      int padok = 1;
      if (tid < 64) {
        int v = am[b * S + kb + tid];
        ams[tid] = v;
        padok = (v != 0);
      }
      CP_WAIT1();  // Q + K(kb) ready (V(kb) may be in flight)
      const int allpad = __syncthreads_and(padok);  // (b)
      const bool interior =
          allpad && (kb + 63 <= q0) && (kb >= q0 + 64 - WIN);

      // ---- QK^T ----
      float sacc[4][4] = {};
      const uint32_t qa = uQ + ((mt * 16 + lrow) * QHLD + lcol8) * 2;
      const uint32_t ka0 = uK + ((half_ * 32 + lrow) * QHLD + lcol8) * 2;
      const uint32_t ka1 = ka0 + 16 * QHLD * 2;
#pragma unroll
      for (int ks = 0; ks < 16; ks++) {
        uint32_t a[4], t0, t1, t2, t3;
        LDMX4(a[0], a[1], a[2], a[3], qa + ks * 32);
        LDMX4(t0, t1, t2, t3, ka0 + ks * 32);
        {
          uint32_t b0[2] = {t0, t2}, b1[2] = {t1, t3};
          mma_f16(sacc[0], a, b0);
          mma_f16(sacc[1], a, b1);
        }
        LDMX4(t0, t1, t2, t3, ka1 + ks * 32);
        {
          uint32_t b0[2] = {t0, t2}, b1[2] = {t1, t3};
          mma_f16(sacc[2], a, b0);
          mma_f16(sacc[3], a, b1);
        }
      }

      // ---- mask (boundary only) + partial row max ----
      float mx0 = NEGF, mx1 = NEGF;
      if (interior) {
#pragma unroll
        for (int nt = 0; nt < 4; nt++) {
          mx0 = fmaxf(mx0, fmaxf(sacc[nt][0], sacc[nt][1]));
          mx1 = fmaxf(mx1, fmaxf(sacc[nt][2], sacc[nt][3]));
        }
      } else {
        const int qg0 = q0 + r0;
        const int qg1 = q0 + r1;
#pragma unroll
        for (int nt = 0; nt < 4; nt++) {
          const int colb = half_ * 32 + nt * 8 + 2 * lc;
#pragma unroll
          for (int j = 0; j < 4; j++) {
            const int col = colb + (j & 1);
            const int kg = kb + col;
            const int qg = (j < 2) ? qg0 : qg1;
            bool ok = (kg <= qg) && (qg - kg < WIN) && (ams[col] != 0);
            float v = ok ? sacc[nt][j] : NEGF;
            sacc[nt][j] = v;
            if (j < 2) mx0 = fmaxf(mx0, v);
            else       mx1 = fmaxf(mx1, v);
          }
        }
      }
      mx0 = fmaxf(mx0, __shfl_xor_sync(0xffffffffu, mx0, 1));
      mx0 = fmaxf(mx0, __shfl_xor_sync(0xffffffffu, mx0, 2));
      mx1 = fmaxf(mx1, __shfl_xor_sync(0xffffffffu, mx1, 1));
      mx1 = fmaxf(mx1, __shfl_xor_sync(0xffffffffu, mx1, 2));
      if (lc == 0) {
        pm[half_ * 64 + r0] = mx0;
        pm[half_ * 64 + r1] = mx1;
      }
      __syncthreads();  // (c) pm visible; all warps past QK -> Ks reusable

      const bool hasnext = (kb + 64 <= kb_end);
      if (hasnext) {
        STAGE8(uK, g_qkvh + (size_t)(b * S + kb + 64) * PSTR + KOFF + hk * D);
        CP_COMMIT();  // K(kb+64)
      }

      // ---- per-thread m/a update ----
      const float mn0 = fmaxf(m0, fmaxf(pm[r0], pm[64 + r0]));
      const float mn1 = fmaxf(m1, fmaxf(pm[r1], pm[64 + r1]));
      const float a0 = __expf(m0 - mn0);
      const float a1 = __expf(m1 - mn1);
      m0 = mn0;
      m1 = mn1;
      if (half_ == 0 && lc == 0) {
        row_a[r0] = a0;
        row_a[r1] = a1;
      }

      // ---- P = exp2((s-mn)*log2e) via f16x2 MUFU; sums in fp32 ----
      // clamp mn for the exponent arg so fully-masked rows (mn = -1e30)
      // yield x = -inf -> P = 0 instead of 0 -> 1. valid |s| <= ~16.
      const float mnl0 = fmaxf(mn0, -1e4f) * LOG2E;
      const float mnl1 = fmaxf(mn1, -1e4f) * LOG2E;
      float s0 = 0.f, s1 = 0.f;
#pragma unroll
      for (int nt = 0; nt < 4; nt++) {
        const int colb = half_ * 32 + nt * 8 + 2 * lc;
        float x00 = fmaf(sacc[nt][0], LOG2E, -mnl0);
        float x01 = fmaf(sacc[nt][1], LOG2E, -mnl0);
        float x10 = fmaf(sacc[nt][2], LOG2E, -mnl1);
        float x11 = fmaf(sacc[nt][3], LOG2E, -mnl1);
        __half2 hx0 = __floats2half2_rn(x00, x01);
        __half2 hx1 = __floats2half2_rn(x10, x11);
        uint32_t e0 = h2ex2(*(uint32_t*)&hx0);
        uint32_t e1 = h2ex2(*(uint32_t*)&hx1);
        *(uint32_t*)&Ps[r0 * PHLD + colb] = e0;
        *(uint32_t*)&Ps[r1 * PHLD + colb] = e1;
        float2 f0 = __half22float2(*(__half2*)&e0);
        float2 f1 = __half22float2(*(__half2*)&e1);
        s0 += f0.x + f0.y;
        s1 += f1.x + f1.y;
      }
      s0 += __shfl_xor_sync(0xffffffffu, s0, 1);
      s0 += __shfl_xor_sync(0xffffffffu, s0, 2);
      s1 += __shfl_xor_sync(0xffffffffu, s1, 1);
      s1 += __shfl_xor_sync(0xffffffffu, s1, 2);
      l0 = l0 * a0 + s0;
      l1 = l1 * a1 + s1;

      if (hasnext) CP_WAIT1(); else CP_WAIT0();  // V(kb) complete
      __syncthreads();  // (d) row_a + Ps + Vs visible

#pragma unroll
      for (int nq = 0; nq < 8; nq++) {
        const int qc = nq * 8 + 2 * lc;
        const float ra0 = row_a[qc];
        const float ra1 = row_a[qc + 1];
#pragma unroll
        for (int mt2 = 0; mt2 < 2; mt2++) {
          oacc[mt2][nq][0] *= ra0;
          oacc[mt2][nq][1] *= ra1;
          oacc[mt2][nq][2] *= ra0;
          oacc[mt2][nq][3] *= ra1;
        }
      }

#pragma unroll
      for (int kk = 0; kk < 4; kk++) {
        uint32_t av[2][4];
#pragma unroll
        for (int mt2 = 0; mt2 < 2; mt2++) {
          uint32_t t0, t1, t2, t3;
          LDMX4T(t0, t1, t2, t3,
                 uV + ((kk * 16 + lrow) * QHLD + w * 32 + mt2 * 16 + lcol8) * 2);
          av[mt2][0] = t0; av[mt2][1] = t2;
          av[mt2][2] = t1; av[mt2][3] = t3;
        }
#pragma unroll
        for (int nq = 0; nq < 4; nq++) {
          uint32_t t0, t1, t2, t3;
          LDMX4(t0, t1, t2, t3,
                uP + ((nq * 16 + lrow) * PHLD + kk * 16 + lcol8) * 2);
          uint32_t b0[2] = {t0, t2}, b1[2] = {t1, t3};
          mma_f16(oacc[0][2 * nq], av[0], b0);
          mma_f16(oacc[0][2 * nq + 1], av[0], b1);
          mma_f16(oacc[1][2 * nq], av[1], b0);
          mma_f16(oacc[1][2 * nq + 1], av[1], b1);
        }
      }
    }

    // ---- epilogue ----
    if (lc == 0) {
      pl[half_ * 64 + r0] = l0;
      pl[half_ * 64 + r1] = l1;
    }
    __syncthreads();
#pragma unroll
    for (int nq = 0; nq < 8; nq++) {
      const int qc = nq * 8 + 2 * lc;
      const float il0 = 1.0f / (pl[qc] + pl[64 + qc]);
      const float il1 = 1.0f / (pl[qc + 1] + pl[64 + qc + 1]);
#pragma unroll
      for (int mt2 = 0; mt2 < 2; mt2++) {
        const int d0 = w * 32 + mt2 * 16 + lr;
        Qs[qc * QHLD + d0] = __float2half(oacc[mt2][nq][0] * il0);
        Qs[(qc + 1) * QHLD + d0] = __float2half(oacc[mt2][nq][1] * il1);
        Qs[qc * QHLD + d0 + 8] = __float2half(oacc[mt2][nq][2] * il0);
        Qs[(qc + 1) * QHLD + d0 + 8] = __float2half(oacc[mt2][nq][3] * il1);
      }
    }
    __syncthreads();
    {
      __half* odst = &g_oh[(((size_t)(b * S + q0) * H + h) * D)];
      uint32_t sOff = (uint32_t)(w * QHLD + lane * 8);
      size_t gOff = (size_t)w * (H * D) + lane * 8;
#pragma unroll
      for (int j = 0; j < 8; j++) {
        uint4 u = *(uint4*)&Qs[sOff];
        *(uint4*)&odst[gOff] = u;
        sOff += 8 * QHLD;
        gOff += (size_t)8 * H * D;
      }
    }

    __syncthreads();
    if (tid == 0) *nxt = atomicAdd(&g_ctr, 1);
    __syncthreads();
    tile = *nxt;
  }
}

// ---------------- launch ----------------
extern "C" void kernel_launch(void* const* d_in, const int* in_sizes, int n_in,
                              void* d_out, int out_size) {
  const float* hs   = (const float*)d_in[0];
  const float* cosb = (const float*)d_in[1];
  const float* sinb = (const float*)d_in[2];
  const int*   am   = (const int*)d_in[3];
  const float* Wq   = (const float*)d_in[4];
  const float* Wk   = (const float*)d_in[5];
  const float* Wv   = (const float*)d_in[6];
  const float* Wo   = (const float*)d_in[7];
  const float* qw   = (const float*)d_in[8];
  const float* kw   = (const float*)d_in[9];
  float* out = (float*)d_out;

  __half *hsh, *wqkvh, *woh, *qkvh, *oh;
  cudaGetSymbolAddress((void**)&hsh, g_hsh);
  cudaGetSymbolAddress((void**)&wqkvh, g_wqkvh);
  cudaGetSymbolAddress((void**)&woh, g_woh);
  cudaGetSymbolAddress((void**)&qkvh, g_qkvh);
  cudaGetSymbolAddress((void**)&oh, g_oh);

  const int M = B * S;  // 4096

  cudaFuncSetAttribute(gemm_f16<__half>,
                       cudaFuncAttributeMaxDynamicSharedMemorySize, GEMMH_SMEM);
  cudaFuncSetAttribute(gemm_f16<float>,
                       cudaFuncAttributeMaxDynamicSharedMemorySize, GEMMH_SMEM);
  cudaFuncSetAttribute(attn_f16, cudaFuncAttributeMaxDynamicSharedMemorySize,
                       ATTH_SMEM);

  // single fused conversion/packing pass (also resets tile counter)
  cvt_all<<<4096, 256>>>((const float4*)hs, (const float4*)Wo,
                         (const float4*)Wq, (const float4*)Wk,
                         (const float4*)Wv);

  // fused QKV projection (N = 4096), fp16 out
  gemm_f16<__half><<<dim3(4096 / 128, M / 128), 256, GEMMH_SMEM>>>(
      hsh, wqkvh, qkvh, M, 4096, E);

  // warp-parallel norm+rope: one warp per (token, head); 49152 warps
  norm_rope3<<<(M * (H + KV)) / 8, 256>>>(cosb, sinb, qw, kw);

  attn_f16<<<NPERS, 256, ATTH_SMEM>>>(am);

  gemm_f16<float><<<dim3(E / 128, M / 128), 256, GEMMH_SMEM>>>(
      oh, woh, out, M, E, E);
}

// round 17
// speedup vs baseline: 37.9288x; 1.0381x over previous
#include <cuda_runtime.h>
#include <cuda_fp16.h>
#include <math.h>
#include <stdint.h>

#define B 2
#define S 2048
#define E 2048
#define H 8
#define KV 4
#define D 256
#define WIN 1024
#define EPS 1e-6f

// ---------------- scratch (device globals; no allocation) ----------------
__device__ __half g_hsh[(size_t)B * S * E];        // fp16 hidden
__device__ __half g_wqkvh[(size_t)E * 4096];       // packed Wq|Wk|Wv
__device__ __half g_woh[(size_t)H * D * E];        // Wo fp16
__device__ __half g_qkvh[(size_t)B * S * 4096];    // packed q|k|v (GEMM out)
__device__ __half g_oh[(size_t)B * S * H * D];     // attn out
// padded head-major copies for bulk staging: row stride 264 halves
#define PADW 264
__device__ __half g_qpad[(size_t)B * H * S * PADW];   // ~16.5 MB
__device__ __half g_kpad[(size_t)B * KV * S * PADW];  // ~8.3 MB
__device__ __half g_vpad[(size_t)B * KV * S * PADW];  // ~8.3 MB
__device__ int g_ctr;                              // persistent-tile counter

// packed column offsets (halves)
#define QOFF 0
#define KOFF 2048
#define VOFF 3072
#define PSTR 4096

#define NPERS 296                 // persistent attention CTAs (2 x 148 SMs)
#define NTILES ((S / 64) * H * B) // 512

// ======================= helpers =========================================
__device__ __forceinline__ uint32_t smem_u32(const void* p) {
  uint32_t a;
  asm("{ .reg .u64 t; cvta.to.shared.u64 t, %1; cvt.u32.u64 %0, t; }"
      : "=r"(a) : "l"(p));
  return a;
}
__device__ __forceinline__ void cpasync16(uint32_t dst, const void* src) {
  asm volatile("cp.async.cg.shared.global [%0], [%1], 16;"
               :: "r"(dst), "l"(src));
}
#define CP_COMMIT() asm volatile("cp.async.commit_group;" ::: "memory")
#define CP_WAIT1() asm volatile("cp.async.wait_group 1;" ::: "memory")
#define CP_WAIT0() asm volatile("cp.async.wait_group 0;" ::: "memory")

// ---- mbarrier + bulk copy (sm_90 baseline PTX) ----
#define MBAR_INIT(addr) \
  asm volatile("mbarrier.init.shared.b64 [%0], 1;" :: "r"(addr) : "memory")
#define MBAR_EXPECT(addr, bytes) \
  asm volatile("mbarrier.arrive.expect_tx.shared.b64 _, [%0], %1;" \
               :: "r"(addr), "r"(bytes) : "memory")
__device__ __forceinline__ void bulkg2s(uint32_t dst, const void* src,
                                        uint32_t bytes, uint32_t mbar) {
  asm volatile(
      "cp.async.bulk.shared::cta.global.mbarrier::complete_tx::bytes "
      "[%0], [%1], %2, [%3];"
      :: "r"(dst), "l"(src), "r"(bytes), "r"(mbar) : "memory");
}
#define MBAR_WAIT(addr, ph)                                                  \
  do {                                                                       \
    uint32_t _done = 0;                                                      \
    while (!_done) {                                                         \
      asm volatile(                                                          \
          "{\n\t.reg .pred p;\n\t"                                           \
          "mbarrier.try_wait.parity.acquire.cta.shared::cta.b64 p, [%1], "   \
          "%2;\n\t"                                                          \
          "selp.b32 %0, 1, 0, p;\n\t}"                                       \
          : "=r"(_done)                                                      \
          : "r"(addr), "r"(ph)                                               \
          : "memory");                                                       \
    }                                                                        \
  } while (0)

__device__ __forceinline__ void mma_f16(float* d, const uint32_t* a,
                                        const uint32_t* b) {
  asm volatile(
      "mma.sync.aligned.m16n8k16.row.col.f32.f16.f16.f32 "
      "{%0,%1,%2,%3},{%4,%5,%6,%7},{%8,%9},{%0,%1,%2,%3};"
      : "+f"(d[0]), "+f"(d[1]), "+f"(d[2]), "+f"(d[3])
      : "r"(a[0]), "r"(a[1]), "r"(a[2]), "r"(a[3]), "r"(b[0]), "r"(b[1]));
}
#define LDMX4(r0, r1, r2, r3, addr)                                        \
  asm volatile("ldmatrix.sync.aligned.m8n8.x4.shared.b16 {%0,%1,%2,%3}, [%4];" \
               : "=r"(r0), "=r"(r1), "=r"(r2), "=r"(r3) : "r"(addr))
#define LDMX4T(r0, r1, r2, r3, addr)                                       \
  asm volatile("ldmatrix.sync.aligned.m8n8.x4.trans.shared.b16 {%0,%1,%2,%3}, [%4];" \
               : "=r"(r0), "=r"(r1), "=r"(r2), "=r"(r3) : "r"(addr))

// fp16x2 exp2
__device__ __forceinline__ uint32_t h2ex2(uint32_t x) {
  uint32_t r;
  asm("ex2.approx.f16x2 %0, %1;" : "=r"(r) : "r"(x));
  return r;
}
#define LOG2E 1.4426950408889634f

// -------- ONE fused fp32 -> fp16 conversion/packing pass -----------------
#define HS4 ((B * S * E) / 4)
#define WO4 ((H * D * E) / 4)
#define PW4 (E * 1024)
__global__ __launch_bounds__(256) void cvt_all(
    const float4* __restrict__ hs, const float4* __restrict__ wo,
    const float4* __restrict__ wq, const float4* __restrict__ wk,
    const float4* __restrict__ wv) {
  if (blockIdx.x == 0 && threadIdx.x == 0) g_ctr = NPERS;  // reset scheduler
  const int total = HS4 + WO4 + PW4;
  int i = blockIdx.x * blockDim.x + threadIdx.x;
  const int stride = gridDim.x * blockDim.x;
  for (; i < total; i += stride) {
    float4 v;
    uint2* dst;
    if (i < HS4) {
      v = hs[i];
      dst = (uint2*)g_hsh + i;
    } else if (i < HS4 + WO4) {
      int j = i - HS4;
      v = wo[j];
      dst = (uint2*)g_woh + j;
    } else {
      int j = i - HS4 - WO4;
      int row = j >> 10, g = j & 1023;
      if (g < 512)       v = wq[(size_t)row * 512 + g];
      else if (g < 768)  v = wk[(size_t)row * 256 + (g - 512)];
      else               v = wv[(size_t)row * 256 + (g - 768)];
      dst = (uint2*)&g_wqkvh[(size_t)row * PSTR + g * 4];
    }
    __half2 h0 = __floats2half2_rn(v.x, v.y);
    __half2 h1 = __floats2half2_rn(v.z, v.w);
    uint2 u;
    u.x = *reinterpret_cast<uint32_t*>(&h0);
    u.y = *reinterpret_cast<uint32_t*>(&h1);
    *dst = u;
  }
}

// ========= fp16 mma GEMM (cp.async 3-stage + ldmatrix, BK=64) ============
#define AH_LD 72
#define BH_LD 136
#define ASTG_B (128 * AH_LD * 2)
#define BSTG_B (64 * BH_LD * 2)
#define GEMMH_SMEM (3 * (ASTG_B + BSTG_B))

template <typename OutT>
__global__ __launch_bounds__(256, 2) void gemm_f16(
    const __half* __restrict__ A, const __half* __restrict__ Bw,
    OutT* __restrict__ C, int M, int N, int K) {
  extern __shared__ char smc[];
  const uint32_t smbA = smem_u32(smc);
  const uint32_t smbB = smbA + 3 * ASTG_B;

  const int tid = threadIdx.x;
  const int lane = tid & 31;
  const int wid = tid >> 5;
  const int bm = blockIdx.y * 128;
  const int bn = blockIdx.x * 128;
  const int wm = (wid & 3) * 32;
  const int wn = (wid >> 2) * 64;

  const __half* aP0 = A + (size_t)(bm + (tid >> 3)) * K + (tid & 7) * 8;
  const __half* bP0 = Bw + (size_t)(tid >> 4) * N + bn + (tid & 15) * 8;
  const uint32_t aS0 = smbA + ((tid >> 3) * AH_LD + (tid & 7) * 8) * 2;
  const uint32_t bS0 = smbB + ((tid >> 4) * BH_LD + (tid & 15) * 8) * 2;
  const int NC = K >> 6;

#define ISSUE_ONE(st, c, _i)                                                 \
  do {                                                                       \
    cpasync16(aS0 + (st) * ASTG_B + (_i) * (32 * AH_LD * 2),                 \
              aP0 + (c) * 64 + (size_t)(_i) * 32 * K);                       \
    cpasync16(bS0 + (st) * BSTG_B + (_i) * (16 * BH_LD * 2),                 \
              bP0 + (size_t)(c) * 64 * N + (size_t)(_i) * 16 * N);           \
  } while (0)

  const int lrow = lane & 15;
  const int lcol8 = (lane >> 4) * 8;
  const uint32_t aAddr0 = smbA + ((wm + lrow) * AH_LD + lcol8) * 2;
  const uint32_t aAddr1 = smbA + ((wm + 16 + lrow) * AH_LD + lcol8) * 2;
  uint32_t bAddr[4];
#pragma unroll
  for (int nb = 0; nb < 4; nb++)
    bAddr[nb] = smbB + (lrow * BH_LD + wn + nb * 16 + lcol8) * 2;

#pragma unroll
  for (int i = 0; i < 4; i++) ISSUE_ONE(0, 0, i);
  CP_COMMIT();
#pragma unroll
  for (int i = 0; i < 4; i++) ISSUE_ONE(1, 1, i);
  CP_COMMIT();

  float acc[2][8][4] = {};

  for (int c = 0; c < NC; c++) {
    if (c + 1 < NC) CP_WAIT1(); else CP_WAIT0();
    __syncthreads();
    const bool pref = (c + 2 < NC);
    const int st2 = (c + 2) % 3;
    const uint32_t aSt = (c % 3) * ASTG_B;
    const uint32_t bSt = (c % 3) * BSTG_B;
#pragma unroll
    for (int ks = 0; ks < 4; ks++) {
      if (pref) ISSUE_ONE(st2, c + 2, ks);
      uint32_t af[2][4], bf[8][2];
      LDMX4(af[0][0], af[0][1], af[0][2], af[0][3], aAddr0 + aSt + ks * 32);
      LDMX4(af[1][0], af[1][1], af[1][2], af[1][3], aAddr1 + aSt + ks * 32);
#pragma unroll
      for (int nb = 0; nb < 4; nb++) {
        uint32_t r0, r1, r2, r3;
        LDMX4T(r0, r1, r2, r3, bAddr[nb] + bSt + ks * (16 * BH_LD * 2));
        bf[2 * nb][0] = r0; bf[2 * nb][1] = r1;
        bf[2 * nb + 1][0] = r2; bf[2 * nb + 1][1] = r3;
      }
#pragma unroll
      for (int mf = 0; mf < 2; mf++)
#pragma unroll
        for (int nf = 0; nf < 8; nf++)
          mma_f16(acc[mf][nf], af[mf], bf[nf]);
    }
    if (pref) CP_COMMIT();
  }

#pragma unroll
  for (int mf = 0; mf < 2; mf++) {
    const int r0 = bm + wm + mf * 16 + (lane >> 2);
#pragma unroll
    for (int nf = 0; nf < 8; nf++) {
      const int col = bn + wn + nf * 8 + 2 * (lane & 3);
      if constexpr (sizeof(OutT) == 4) {
        float2 v0, v1;
        v0.x = acc[mf][nf][0]; v0.y = acc[mf][nf][1];
        v1.x = acc[mf][nf][2]; v1.y = acc[mf][nf][3];
        *(float2*)&C[(size_t)r0 * N + col] = v0;
        *(float2*)&C[(size_t)(r0 + 8) * N + col] = v1;
      } else {
        *(__half2*)&C[(size_t)r0 * N + col] =
            __floats2half2_rn(acc[mf][nf][0], acc[mf][nf][1]);
        *(__half2*)&C[(size_t)(r0 + 8) * N + col] =
            __floats2half2_rn(acc[mf][nf][2], acc[mf][nf][3]);
      }
    }
  }
}

// ---- warp-parallel RMSNorm + RoPE + scatter to padded head-major -------
// 16 warps per token: 0..7 Q-norm, 8..11 K-norm, 12..15 V-copy.
__global__ __launch_bounds__(256) void norm_rope4(
    const float* __restrict__ cosb, const float* __restrict__ sinb,
    const float* __restrict__ qw, const float* __restrict__ kw) {
  const int gw = blockIdx.x * 8 + (threadIdx.x >> 5);  // global warp id
  const int lane = threadIdx.x & 31;
  const int row = gw >> 4;          // token (b*S + s)
  const int hh = gw & 15;
  const int b = row >> 11;
  const int s = row & (S - 1);
  const int p0 = lane * 8;

  if (hh >= 12) {  // V copy (no norm)
    const int hv = hh - 12;
    const __half* src = &g_qkvh[(size_t)row * PSTR + VOFF + hv * D];
    __half* dst = &g_vpad[((size_t)(b * KV + hv) * S + s) * PADW];
    *(uint4*)&dst[p0] = *(const uint4*)&src[p0];
    return;
  }

  const __half* src;
  __half* dst;
  const float* wv;
  float osc;
  if (hh < H) {
    src = &g_qkvh[(size_t)row * PSTR + QOFF + hh * D];
    dst = &g_qpad[((size_t)(b * H + hh) * S + s) * PADW];
    wv = qw; osc = 0.0625f;
  } else {
    const int hkk = hh - H;
    src = &g_qkvh[(size_t)row * PSTR + KOFF + hkk * D];
    dst = &g_kpad[((size_t)(b * KV + hkk) * S + s) * PADW];
    wv = kw; osc = 1.0f;
  }

  uint4 raw = *(const uint4*)&src[p0];
  __half2 h01 = *(__half2*)&raw.x;
  __half2 h23 = *(__half2*)&raw.y;
  __half2 h45 = *(__half2*)&raw.z;
  __half2 h67 = *(__half2*)&raw.w;
  float x[8];
  x[0] = __half2float(h01.x); x[1] = __half2float(h01.y);
  x[2] = __half2float(h23.x); x[3] = __half2float(h23.y);
  x[4] = __half2float(h45.x); x[5] = __half2float(h45.y);
  x[6] = __half2float(h67.x); x[7] = __half2float(h67.y);

  float ss = 0.f;
#pragma unroll
  for (int j = 0; j < 8; j++) ss += x[j] * x[j];
#pragma unroll
  for (int o = 16; o > 0; o >>= 1) ss += __shfl_xor_sync(0xffffffffu, ss, o);
  const float inv = rsqrtf(ss * (1.0f / D) + EPS);

  float4 w0 = *(const float4*)&wv[p0];
  float4 w1 = *(const float4*)&wv[p0 + 4];
  float xn[8];
  xn[0] = x[0] * inv * (1.0f + w0.x);
  xn[1] = x[1] * inv * (1.0f + w0.y);
  xn[2] = x[2] * inv * (1.0f + w0.z);
  xn[3] = x[3] * inv * (1.0f + w0.w);
  xn[4] = x[4] * inv * (1.0f + w1.x);
  xn[5] = x[5] * inv * (1.0f + w1.y);
  xn[6] = x[6] * inv * (1.0f + w1.z);
  xn[7] = x[7] * inv * (1.0f + w1.w);

  const float* cb = &cosb[(size_t)row * D + p0];
  const float* sb = &sinb[(size_t)row * D + p0];
  float4 c0 = *(const float4*)cb;
  float4 c1 = *(const float4*)(cb + 4);
  float4 s0 = *(const float4*)sb;
  float4 s1 = *(const float4*)(sb + 4);
  const float cs[8] = {c0.x, c0.y, c0.z, c0.w, c1.x, c1.y, c1.z, c1.w};
  const float sn[8] = {s0.x, s0.y, s0.z, s0.w, s1.x, s1.y, s1.z, s1.w};

  const float rsgn = (lane < 16) ? -1.0f : 1.0f;
  float o[8];
#pragma unroll
  for (int j = 0; j < 8; j++) {
    float other = __shfl_xor_sync(0xffffffffu, xn[j], 16);
    o[j] = (xn[j] * cs[j] + rsgn * other * sn[j]) * osc;
  }
  uint4 out;
  __half2 t;
  t = __floats2half2_rn(o[0], o[1]); out.x = *(uint32_t*)&t;
  t = __floats2half2_rn(o[2], o[3]); out.y = *(uint32_t*)&t;
  t = __floats2half2_rn(o[4], o[5]); out.z = *(uint32_t*)&t;
  t = __floats2half2_rn(o[6], o[7]); out.w = *(uint32_t*)&t;
  *(uint4*)&dst[p0] = out;
}

// == persistent fp16 mma flash attention: bulk-copy staging ==============
#define QHLD 264
#define PHLD 72
#define ATTH_SMEM 112640
#define NEGF (-1e30f)
#define TILE_BYTES (64 * QHLD * 2)  // 33792

__global__ __launch_bounds__(256, 2) void attn_f16(const int* __restrict__ am) {
  extern __shared__ char smc[];
  __half* Qs = (__half*)smc;            // [64][QHLD]
  __half* Ks = Qs + 64 * QHLD;
  __half* Vs = Ks + 64 * QHLD;
  __half* Ps = Vs + 64 * QHLD;          // [64][PHLD]
  float* row_a = (float*)(smc + 110592);  // [64]
  float* pm = row_a + 64;                 // [2][64]
  float* pl = pm + 128;                   // [2][64]
  int* ams = (int*)(pl + 128);            // [64]
  int* nxt = ams + 64;                    // [1]
  // mbarriers at 8-aligned offset past nxt
  uint64_t* mb = (uint64_t*)(smc + 112136);  // [2]

  const uint32_t uQ = smem_u32(Qs);
  const uint32_t uK = smem_u32(Ks);
  const uint32_t uV = smem_u32(Vs);
  const uint32_t uP = smem_u32(Ps);
  const uint32_t mbKQ = smem_u32(&mb[0]);
  const uint32_t mbV = smem_u32(&mb[1]);

  const int tid = threadIdx.x;
  const int lane = tid & 31;
  const int w = tid >> 5;
  const int mt = w & 3;
  const int half_ = w >> 2;
  const int lr = lane >> 2;
  const int lc = lane & 3;
  const int lrow = lane & 15;
  const int lcol8 = (lane >> 4) * 8;

  const int r0 = mt * 16 + lr;
  const int r1 = r0 + 8;

  if (tid == 0) {
    MBAR_INIT(mbKQ);
    MBAR_INIT(mbV);
  }
  __syncthreads();
  uint32_t kq_ph = 0, v_ph = 0;

  int tile = blockIdx.x;
  while (tile < NTILES) {
    const int qi = 31 - (tile >> 4);
    const int h = (tile >> 1) & 7;
    const int b = tile & 1;
    const int q0 = qi * 64;
    const int hk = h / (H / KV);

    int kb0 = q0 - (WIN - 1);
    if (kb0 < 0) kb0 = 0;
    kb0 &= ~63;
    const int kb_end = q0 + 63;

    const __half* qbase = g_qpad + (size_t)(b * H + h) * S * PADW;
    const __half* kbase = g_kpad + (size_t)(b * KV + hk) * S * PADW;
    const __half* vbase = g_vpad + (size_t)(b * KV + hk) * S * PADW;

    // prologue: Q + K(kb0) into one mbKQ phase
    if (tid == 0) {
      MBAR_EXPECT(mbKQ, 2 * TILE_BYTES);
      bulkg2s(uQ, qbase + (size_t)q0 * PADW, TILE_BYTES, mbKQ);
      bulkg2s(uK, kbase + (size_t)kb0 * PADW, TILE_BYTES, mbKQ);
    }

    float m0 = NEGF, m1 = NEGF;
    float l0 = 0.f, l1 = 0.f;
    float oacc[2][8][4] = {};

    for (int kb = kb0; kb <= kb_end; kb += 64) {
      __syncthreads();  // (a) prev PV readers done -> Vs/Ps reusable
      if (tid == 0) {
        MBAR_EXPECT(mbV, TILE_BYTES);
        bulkg2s(uV, vbase + (size_t)kb * PADW, TILE_BYTES, mbV);
      }
      int padok = 1;
      if (tid < 64) {
        int v = am[b * S + kb + tid];
        ams[tid] = v;
        padok = (v != 0);
      }
      MBAR_WAIT(mbKQ, kq_ph);  // Q + K(kb) ready
      kq_ph ^= 1;
      const int allpad = __syncthreads_and(padok);  // (b)
      const bool interior =
          allpad && (kb + 63 <= q0) && (kb >= q0 + 64 - WIN);

      // ---- QK^T ----
      float sacc[4][4] = {};
      const uint32_t qa = uQ + ((mt * 16 + lrow) * QHLD + lcol8) * 2;
      const uint32_t ka0 = uK + ((half_ * 32 + lrow) * QHLD + lcol8) * 2;
      const uint32_t ka1 = ka0 + 16 * QHLD * 2;
#pragma unroll
      for (int ks = 0; ks < 16; ks++) {
        uint32_t a[4], t0, t1, t2, t3;
        LDMX4(a[0], a[1], a[2], a[3], qa + ks * 32);
        LDMX4(t0, t1, t2, t3, ka0 + ks * 32);
        {
          uint32_t b0[2] = {t0, t2}, b1[2] = {t1, t3};
          mma_f16(sacc[0], a, b0);
          mma_f16(sacc[1], a, b1);
        }
        LDMX4(t0, t1, t2, t3, ka1 + ks * 32);
        {
          uint32_t b0[2] = {t0, t2}, b1[2] = {t1, t3};
          mma_f16(sacc[2], a, b0);
          mma_f16(sacc[3], a, b1);
        }
      }

      // ---- mask (boundary only) + partial row max ----
      float mx0 = NEGF, mx1 = NEGF;
      if (interior) {
#pragma unroll
        for (int nt = 0; nt < 4; nt++) {
          mx0 = fmaxf(mx0, fmaxf(sacc[nt][0], sacc[nt][1]));
          mx1 = fmaxf(mx1, fmaxf(sacc[nt][2], sacc[nt][3]));
        }
      } else {
        const int qg0 = q0 + r0;
        const int qg1 = q0 + r1;
#pragma unroll
        for (int nt = 0; nt < 4; nt++) {
          const int colb = half_ * 32 + nt * 8 + 2 * lc;
#pragma unroll
          for (int j = 0; j < 4; j++) {
            const int col = colb + (j & 1);
            const int kg = kb + col;
            const int qg = (j < 2) ? qg0 : qg1;
            bool ok = (kg <= qg) && (qg - kg < WIN) && (ams[col] != 0);
            float v = ok ? sacc[nt][j] : NEGF;
            sacc[nt][j] = v;
            if (j < 2) mx0 = fmaxf(mx0, v);
            else       mx1 = fmaxf(mx1, v);
          }
        }
      }
      mx0 = fmaxf(mx0, __shfl_xor_sync(0xffffffffu, mx0, 1));
      mx0 = fmaxf(mx0, __shfl_xor_sync(0xffffffffu, mx0, 2));
      mx1 = fmaxf(mx1, __shfl_xor_sync(0xffffffffu, mx1, 1));
      mx1 = fmaxf(mx1, __shfl_xor_sync(0xffffffffu, mx1, 2));
      if (lc == 0) {
        pm[half_ * 64 + r0] = mx0;
        pm[half_ * 64 + r1] = mx1;
      }
      __syncthreads();  // (c) pm visible; all warps past QK -> Ks reusable

      const bool hasnext = (kb + 64 <= kb_end);
      if (hasnext && tid == 0) {
        MBAR_EXPECT(mbKQ, TILE_BYTES);
        bulkg2s(uK, kbase + (size_t)(kb + 64) * PADW, TILE_BYTES, mbKQ);
      }

      // ---- per-thread m/a update ----
      const float mn0 = fmaxf(m0, fmaxf(pm[r0], pm[64 + r0]));
      const float mn1 = fmaxf(m1, fmaxf(pm[r1], pm[64 + r1]));
      const float a0 = __expf(m0 - mn0);
      const float a1 = __expf(m1 - mn1);
      m0 = mn0;
      m1 = mn1;
      if (half_ == 0 && lc == 0) {
        row_a[r0] = a0;
        row_a[r1] = a1;
      }

      // ---- P = exp2 via f16x2 MUFU; sums in fp32 ----
      const float mnl0 = fmaxf(mn0, -1e4f) * LOG2E;
      const float mnl1 = fmaxf(mn1, -1e4f) * LOG2E;
      float s0 = 0.f, s1 = 0.f;
#pragma unroll
      for (int nt = 0; nt < 4; nt++) {
        const int colb = half_ * 32 + nt * 8 + 2 * lc;
        float x00 = fmaf(sacc[nt][0], LOG2E, -mnl0);
        float x01 = fmaf(sacc[nt][1], LOG2E, -mnl0);
        float x10 = fmaf(sacc[nt][2], LOG2E, -mnl1);
        float x11 = fmaf(sacc[nt][3], LOG2E, -mnl1);
        __half2 hx0 = __floats2half2_rn(x00, x01);
        __half2 hx1 = __floats2half2_rn(x10, x11);
        uint32_t e0 = h2ex2(*(uint32_t*)&hx0);
        uint32_t e1 = h2ex2(*(uint32_t*)&hx1);
        *(uint32_t*)&Ps[r0 * PHLD + colb] = e0;
        *(uint32_t*)&Ps[r1 * PHLD + colb] = e1;
        float2 f0 = __half22float2(*(__half2*)&e0);
        float2 f1 = __half22float2(*(__half2*)&e1);
        s0 += f0.x + f0.y;
        s1 += f1.x + f1.y;
      }
      s0 += __shfl_xor_sync(0xffffffffu, s0, 1);
      s0 += __shfl_xor_sync(0xffffffffu, s0, 2);
      s1 += __shfl_xor_sync(0xffffffffu, s1, 1);
      s1 += __shfl_xor_sync(0xffffffffu, s1, 2);
      l0 = l0 * a0 + s0;
      l1 = l1 * a1 + s1;

      MBAR_WAIT(mbV, v_ph);  // V(kb) ready
      v_ph ^= 1;
      __syncthreads();  // (d) row_a + Ps + Vs visible

#pragma unroll
      for (int nq = 0; nq < 8; nq++) {
        const int qc = nq * 8 + 2 * lc;
        const float ra0 = row_a[qc];
        const float ra1 = row_a[qc + 1];
#pragma unroll
        for (int mt2 = 0; mt2 < 2; mt2++) {
          oacc[mt2][nq][0] *= ra0;
          oacc[mt2][nq][1] *= ra1;
          oacc[mt2][nq][2] *= ra0;
          oacc[mt2][nq][3] *= ra1;
        }
      }

#pragma unroll
      for (int kk = 0; kk < 4; kk++) {
        uint32_t av[2][4];
#pragma unroll
        for (int mt2 = 0; mt2 < 2; mt2++) {
          uint32_t t0, t1, t2, t3;
          LDMX4T(t0, t1, t2, t3,
                 uV + ((kk * 16 + lrow) * QHLD + w * 32 + mt2 * 16 + lcol8) * 2);
          av[mt2][0] = t0; av[mt2][1] = t2;
          av[mt2][2] = t1; av[mt2][3] = t3;
        }
#pragma unroll
        for (int nq = 0; nq < 4; nq++) {
          uint32_t t0, t1, t2, t3;
          LDMX4(t0, t1, t2, t3,
                uP + ((nq * 16 + lrow) * PHLD + kk * 16 + lcol8) * 2);
          uint32_t b0[2] = {t0, t2}, b1[2] = {t1, t3};
          mma_f16(oacc[0][2 * nq], av[0], b0);
          mma_f16(oacc[0][2 * nq + 1], av[0], b1);
          mma_f16(oacc[1][2 * nq], av[1], b0);
          mma_f16(oacc[1][2 * nq + 1], av[1], b1);
        }
      }
    }

    // ---- epilogue ----
    if (lc == 0) {
      pl[half_ * 64 + r0] = l0;
      pl[half_ * 64 + r1] = l1;
    }
    __syncthreads();
#pragma unroll
    for (int nq = 0; nq < 8; nq++) {
      const int qc = nq * 8 + 2 * lc;
      const float il0 = 1.0f / (pl[qc] + pl[64 + qc]);
      const float il1 = 1.0f / (pl[qc + 1] + pl[64 + qc + 1]);
#pragma unroll
      for (int mt2 = 0; mt2 < 2; mt2++) {
        const int d0 = w * 32 + mt2 * 16 + lr;
        Qs[qc * QHLD + d0] = __float2half(oacc[mt2][nq][0] * il0);
        Qs[(qc + 1) * QHLD + d0] = __float2half(oacc[mt2][nq][1] * il1);
        Qs[qc * QHLD + d0 + 8] = __float2half(oacc[mt2][nq][2] * il0);
        Qs[(qc + 1) * QHLD + d0 + 8] = __float2half(oacc[mt2][nq][3] * il1);
      }
    }
    __syncthreads();
    {
      __half* odst = &g_oh[(((size_t)(b * S + q0) * H + h) * D)];
      uint32_t sOff = (uint32_t)(w * QHLD + lane * 8);
      size_t gOff = (size_t)w * (H * D) + lane * 8;
#pragma unroll
      for (int j = 0; j < 8; j++) {
        uint4 u = *(uint4*)&Qs[sOff];
        *(uint4*)&odst[gOff] = u;
        sOff += 8 * QHLD;
        gOff += (size_t)8 * H * D;
      }
    }

    __syncthreads();
    if (tid == 0) *nxt = atomicAdd(&g_ctr, 1);
    __syncthreads();
    tile = *nxt;
  }
}

// ---------------- launch ----------------
extern "C" void kernel_launch(void* const* d_in, const int* in_sizes, int n_in,
                              void* d_out, int out_size) {
  const float* hs   = (const float*)d_in[0];
  const float* cosb = (const float*)d_in[1];
  const float* sinb = (const float*)d_in[2];
  const int*   am   = (const int*)d_in[3];
  const float* Wq   = (const float*)d_in[4];
  const float* Wk   = (const float*)d_in[5];
  const float* Wv   = (const float*)d_in[6];
  const float* Wo   = (const float*)d_in[7];
  const float* qw   = (const float*)d_in[8];
  const float* kw   = (const float*)d_in[9];
  float* out = (float*)d_out;

  __half *hsh, *wqkvh, *woh, *qkvh, *oh;
  cudaGetSymbolAddress((void**)&hsh, g_hsh);
  cudaGetSymbolAddress((void**)&wqkvh, g_wqkvh);
  cudaGetSymbolAddress((void**)&woh, g_woh);
  cudaGetSymbolAddress((void**)&qkvh, g_qkvh);
  cudaGetSymbolAddress((void**)&oh, g_oh);

  const int M = B * S;  // 4096

  cudaFuncSetAttribute(gemm_f16<__half>,
                       cudaFuncAttributeMaxDynamicSharedMemorySize, GEMMH_SMEM);
  cudaFuncSetAttribute(gemm_f16<float>,
                       cudaFuncAttributeMaxDynamicSharedMemorySize, GEMMH_SMEM);
  cudaFuncSetAttribute(attn_f16, cudaFuncAttributeMaxDynamicSharedMemorySize,
                       ATTH_SMEM);

  // single fused conversion/packing pass (also resets tile counter)
  cvt_all<<<4096, 256>>>((const float4*)hs, (const float4*)Wo,
                         (const float4*)Wq, (const float4*)Wk,
                         (const float4*)Wv);

  // fused QKV projection (N = 4096), fp16 out
  gemm_f16<__half><<<dim3(4096 / 128, M / 128), 256, GEMMH_SMEM>>>(
      hsh, wqkvh, qkvh, M, 4096, E);

  // norm+rope+scatter: 16 warps per token (Q norm, K norm, V copy)
  norm_rope4<<<(M * 16) / 8, 256>>>(cosb, sinb, qw, kw);

  attn_f16<<<NPERS, 256, ATTH_SMEM>>>(am);

  gemm_f16<float><<<dim3(E / 128, M / 128), 256, GEMMH_SMEM>>>(
      oh, woh, out, M, E, E);
}